// round 10
// baseline (speedup 1.0000x reference)
#include <cuda_runtime.h>
#include <math.h>
#include <stdint.h>

#define NB    128
#define NTOKN 64
#define CDIM  784
#define NHD   8
#define HD    98
#define HID   3136
#define NROW  (NB*NTOKN)
#define M2    (NB*784)
#define OUT1  (NROW*CDIM)

// ---------------- scratch (device globals; no allocation allowed) ----------
__device__ float  g_h_hi  [NROW*CDIM];     // aperm
__device__ float  g_h_lo  [NROW*CDIM];     // aperm
__device__ float  g_qkv   [NROW*3*CDIM];
__device__ float  g_ao_hi [NROW*CDIM];     // aperm
__device__ float  g_ao_lo [NROW*CDIM];     // aperm
__device__ float  g_o     [NROW*CDIM];
__device__ float  g_xr    [NROW*CDIM];
__device__ float  g_h2    [NROW*CDIM];     // aperm
__device__ float  g_mid   [NROW*HID];      // aperm
__device__ float  g_xT_hi [M2*64];         // aperm
__device__ float  g_xT_lo [M2*64];         // aperm
__device__ float  g_bfqkv [M2*192];
__device__ float  g_bfao  [M2*64];
__device__ float  g_bfao_hi[M2*64];        // aperm
__device__ float  g_bfao_lo[M2*64];        // aperm
__device__ float  g_bf2   [M2*64];
__device__ float4 g_qwp   [(CDIM/8)*(3*CDIM)*4];
__device__ float4 g_pwp   [(CDIM/8)*CDIM*4];
__device__ float4 g_bfqwp [(64/8)*192*4];
__device__ float4 g_bfowp [(64/8)*64*4];
__device__ float4 g_fc1wp [(CDIM/16)*HID*4];
__device__ float4 g_fc2wp [(HID/16)*CDIM*4];
__device__ float  g_qr    [NB*49*64];
__device__ float  g_kr    [NB*49*64];
__device__ float  g_ar    [NB*49*49];
__device__ int    g_topk  [NB*49*4];

// ---------------- helpers ----------------------------------------------------
__device__ __forceinline__ float f2tf32f(float x) {
    unsigned r;
    asm("cvt.rna.tf32.f32 %0, %1;" : "=r"(r) : "f"(x));
    return __uint_as_float(r);
}

// fragment-order A permutation: 16-row x 8-k blocks of 128 floats.
// Within block: lane = (row%8)*4 + (k%4), elem = 2*((k%8)/4) + ((row%16)/8).
__device__ __forceinline__ size_t aperm(int row, int k, int K) {
    return ((size_t)((row >> 4) * (K >> 3) + (k >> 3)) << 7)
         + (size_t)((((row & 7) << 2) | (k & 3)) << 2)
         + (size_t)(((k & 4) >> 1) | ((row & 8) >> 3));
}

__device__ __forceinline__ void mma_tf32(float& d0, float& d1, float& d2, float& d3,
                                         unsigned a0, unsigned a1, unsigned a2, unsigned a3,
                                         unsigned b0, unsigned b1) {
    asm volatile(
        "mma.sync.aligned.m16n8k8.row.col.f32.tf32.tf32.f32 "
        "{%0,%1,%2,%3}, {%4,%5,%6,%7}, {%8,%9}, {%0,%1,%2,%3};\n"
        : "+f"(d0), "+f"(d1), "+f"(d2), "+f"(d3)
        : "r"(a0), "r"(a1), "r"(a2), "r"(a3), "r"(b0), "r"(b1));
}

__device__ __forceinline__ void cp16(void* dst, const void* src, bool pred) {
    unsigned daddr = (unsigned)__cvta_generic_to_shared(dst);
    int sz = pred ? 16 : 0;
    asm volatile("cp.async.cg.shared.global [%0], [%1], 16, %2;\n"
                 :: "r"(daddr), "l"(src), "r"(sz));
}
#define CP_COMMIT() asm volatile("cp.async.commit_group;\n" ::: "memory")
#define CP_WAIT2()  asm volatile("cp.async.wait_group 2;\n" ::: "memory")

// ---------------- weight packs -----------------------------------------------
// 3x pack from w[K][N]: quad q = (k8*N + n)*4 + c
//   -> {hi(k8*8+c, n), lo(same), hi(k8*8+c+4, n), lo(same)}
__global__ void bpack3(const float* __restrict__ w, float4* __restrict__ out,
                       int K, int N) {
    int q = blockIdx.x * blockDim.x + threadIdx.x;
    int total = (K >> 3) * N * 4;
    if (q >= total) return;
    int c = q & 3, n = (q >> 2) % N, k8 = q / (4 * N);
    float v0 = w[(size_t)(k8 * 8 + c) * N + n];
    float v1 = w[(size_t)(k8 * 8 + c + 4) * N + n];
    float h0 = f2tf32f(v0), h1 = f2tf32f(v1);
    out[q] = make_float4(h0, f2tf32f(v0 - h0), h1, f2tf32f(v1 - h1));
}
// 3x pack from w[N][K] (transpose during pack)
__global__ void bpack3t(const float* __restrict__ w, float4* __restrict__ out,
                        int K, int N) {
    int q = blockIdx.x * blockDim.x + threadIdx.x;
    int total = (K >> 3) * N * 4;
    if (q >= total) return;
    int c = q & 3, n = (q >> 2) % N, k8 = q / (4 * N);
    float v0 = w[(size_t)n * K + k8 * 8 + c];
    float v1 = w[(size_t)n * K + k8 * 8 + c + 4];
    float h0 = f2tf32f(v0), h1 = f2tf32f(v1);
    out[q] = make_float4(h0, f2tf32f(v0 - h0), h1, f2tf32f(v1 - h1));
}
// 1x pack from w[K][N]: quad q = (k16*N + n)*4 + c
//   -> {rna(w[16k16+c][n]), rna(w[+4+c]), rna(w[+8+c]), rna(w[+12+c])}
__global__ void bpack1(const float* __restrict__ w, float4* __restrict__ out,
                       int K, int N) {
    int q = blockIdx.x * blockDim.x + threadIdx.x;
    int total = (K >> 4) * N * 4;
    if (q >= total) return;
    int c = q & 3, n = (q >> 2) % N, k16 = q / (4 * N);
    const float* p = w + (size_t)(k16 * 16 + c) * N + n;
    out[q] = make_float4(f2tf32f(p[0]),
                         f2tf32f(p[(size_t)4 * N]),
                         f2tf32f(p[(size_t)8 * N]),
                         f2tf32f(p[(size_t)12 * N]));
}

// ---------------- LayerNorm, aperm rounded output (feeds 1x GEMM) -----------
__global__ void ln_kernel(const float* __restrict__ x, const float* __restrict__ g,
                          const float* __restrict__ b, float* __restrict__ y) {
    int row = blockIdx.x;
    const float* xr = x + (size_t)row * CDIM;
    float s = 0.f, s2 = 0.f;
    for (int i = threadIdx.x; i < CDIM; i += blockDim.x) {
        float v = xr[i]; s += v; s2 += v * v;
    }
    for (int o = 16; o; o >>= 1) {
        s  += __shfl_xor_sync(0xffffffffu, s,  o);
        s2 += __shfl_xor_sync(0xffffffffu, s2, o);
    }
    __shared__ float sh[16], sh2[16];
    int warp = threadIdx.x >> 5, lane = threadIdx.x & 31;
    if (lane == 0) { sh[warp] = s; sh2[warp] = s2; }
    __syncthreads();
    if (threadIdx.x == 0) {
        float t = 0.f, t2 = 0.f;
        int nw = blockDim.x >> 5;
        for (int i = 0; i < nw; i++) { t += sh[i]; t2 += sh2[i]; }
        sh[0] = t; sh2[0] = t2;
    }
    __syncthreads();
    float mean = sh[0] * (1.0f / CDIM);
    float var  = sh2[0] * (1.0f / CDIM) - mean * mean;
    float rinv = rsqrtf(var + 1e-5f);
    for (int i = threadIdx.x; i < CDIM; i += blockDim.x)
        y[aperm(row, i, CDIM)] = f2tf32f((xr[i] - mean) * rinv * g[i] + b[i]);
}

// ---------------- LayerNorm, aperm split output ------------------------------
__global__ void ln_split_kernel(const float* __restrict__ x, const float* __restrict__ g,
                                const float* __restrict__ b,
                                float* __restrict__ yh, float* __restrict__ yl) {
    int row = blockIdx.x;
    const float* xr = x + (size_t)row * CDIM;
    float s = 0.f, s2 = 0.f;
    for (int i = threadIdx.x; i < CDIM; i += blockDim.x) {
        float v = xr[i]; s += v; s2 += v * v;
    }
    for (int o = 16; o; o >>= 1) {
        s  += __shfl_xor_sync(0xffffffffu, s,  o);
        s2 += __shfl_xor_sync(0xffffffffu, s2, o);
    }
    __shared__ float sh[16], sh2[16];
    int warp = threadIdx.x >> 5, lane = threadIdx.x & 31;
    if (lane == 0) { sh[warp] = s; sh2[warp] = s2; }
    __syncthreads();
    if (threadIdx.x == 0) {
        float t = 0.f, t2 = 0.f;
        int nw = blockDim.x >> 5;
        for (int i = 0; i < nw; i++) { t += sh[i]; t2 += sh2[i]; }
        sh[0] = t; sh2[0] = t2;
    }
    __syncthreads();
    float mean = sh[0] * (1.0f / CDIM);
    float var  = sh2[0] * (1.0f / CDIM) - mean * mean;
    float rinv = rsqrtf(var + 1e-5f);
    for (int i = threadIdx.x; i < CDIM; i += blockDim.x) {
        float v = (xr[i] - mean) * rinv * g[i] + b[i];
        float h = f2tf32f(v);
        size_t idx = aperm(row, i, CDIM);
        yh[idx] = h;
        yl[idx] = f2tf32f(v - h);
    }
}

// ---------------- 3xTF32 GEMM, fragment-permuted operands, 3-stage ----------
#define S3STG 8192
#define GS3V  (3*S3STG*4)
__global__ void __launch_bounds__(256, 2)
gemm3v(const float* __restrict__ Ah, const float* __restrict__ Al,
       const float4* __restrict__ Bq,
       const float* __restrict__ bias, const float* __restrict__ res,
       float* __restrict__ C, float* __restrict__ C2, const float* __restrict__ res2,
       int M, int N, int K) {
    extern __shared__ float sm[];
    int tid = threadIdx.x, warp = tid >> 5, lane = tid & 31;
    int wm = warp & 1, wn = warp >> 1;
    int row0 = blockIdx.y * 128, col0 = blockIdx.x * 128;
    int r = lane >> 2, c = lane & 3;
    int nk = K >> 4, K8 = K >> 3;

    float acc[4][4][4];
#pragma unroll
    for (int i = 0; i < 4; i++)
#pragma unroll
        for (int j = 0; j < 4; j++)
#pragma unroll
            for (int q = 0; q < 4; q++) acc[i][j][q] = 0.f;

#define P3(SIDX, KT) do { \
        float* sa = sm + (SIDX) * S3STG; \
        for (int q = tid; q < 512; q += 256) { \
            int b_ = q >> 6, ks_ = (q >> 5) & 1, ln_ = q & 31; \
            size_t g_ = ((size_t)((row0 >> 4) + b_) * K8 + (KT) * 2 + ks_) * 128 + ln_ * 4; \
            cp16(sa + (b_ * 2 + ks_) * 128 + ln_ * 4, Ah + g_, true); \
            cp16(sa + 2048 + (b_ * 2 + ks_) * 128 + ln_ * 4, Al + g_, true); \
        } \
        for (int q = tid; q < 1024; q += 256) { \
            int ks_ = q >> 9, rem_ = q & 511, nl_ = rem_ >> 2, cc_ = rem_ & 3; \
            int n_ = col0 + nl_; \
            size_t g_ = ((size_t)((KT) * 2 + ks_) * N + n_) * 4 + cc_; \
            cp16(sa + 4096 + q * 4, Bq + g_, n_ < N); \
        } \
    } while (0)

    P3(0, 0); CP_COMMIT();
    if (nk > 1) P3(1, 1);
    CP_COMMIT();
    if (nk > 2) P3(2, 2);
    CP_COMMIT();

    for (int kt = 0; kt < nk; kt++) {
        CP_WAIT2();
        __syncthreads();
        int s = kt % 3;
        float* sa = sm + s * S3STG;
#pragma unroll
        for (int ks = 0; ks < 2; ks++) {
            float4 ah4[4], al4[4], bq4[4];
#pragma unroll
            for (int mt = 0; mt < 4; mt++) {
                int off = ((wm * 4 + mt) * 2 + ks) * 128 + lane * 4;
                ah4[mt] = *(const float4*)(sa + off);
                al4[mt] = *(const float4*)(sa + 2048 + off);
            }
#pragma unroll
            for (int nt = 0; nt < 4; nt++) {
                int nl = wn * 32 + nt * 8 + r;
                bq4[nt] = *(const float4*)(sa + 4096 + ((ks * 128 + nl) * 4 + c) * 4);
            }
#pragma unroll
            for (int mt = 0; mt < 4; mt++) {
                unsigned a0 = __float_as_uint(ah4[mt].x), a1 = __float_as_uint(ah4[mt].y);
                unsigned a2 = __float_as_uint(ah4[mt].z), a3 = __float_as_uint(ah4[mt].w);
                unsigned l0 = __float_as_uint(al4[mt].x), l1 = __float_as_uint(al4[mt].y);
                unsigned l2 = __float_as_uint(al4[mt].z), l3 = __float_as_uint(al4[mt].w);
#pragma unroll
                for (int nt = 0; nt < 4; nt++) {
                    unsigned bh0 = __float_as_uint(bq4[nt].x), bl0 = __float_as_uint(bq4[nt].y);
                    unsigned bh1 = __float_as_uint(bq4[nt].z), bl1 = __float_as_uint(bq4[nt].w);
                    mma_tf32(acc[mt][nt][0], acc[mt][nt][1], acc[mt][nt][2], acc[mt][nt][3],
                             a0, a1, a2, a3, bl0, bl1);
                    mma_tf32(acc[mt][nt][0], acc[mt][nt][1], acc[mt][nt][2], acc[mt][nt][3],
                             l0, l1, l2, l3, bh0, bh1);
                    mma_tf32(acc[mt][nt][0], acc[mt][nt][1], acc[mt][nt][2], acc[mt][nt][3],
                             a0, a1, a2, a3, bh0, bh1);
                }
            }
        }
        __syncthreads();
        if (kt + 3 < nk) P3(s, kt + 3);
        CP_COMMIT();
    }
#undef P3

#pragma unroll
    for (int mt = 0; mt < 4; mt++) {
        int rr0 = row0 + wm * 64 + mt * 16 + r;
#pragma unroll
        for (int nt = 0; nt < 4; nt++) {
            int cb = col0 + wn * 32 + nt * 8 + 2 * c;
#pragma unroll
            for (int half = 0; half < 2; half++) {
                int rr = rr0 + half * 8;
                float v0 = acc[mt][nt][half * 2 + 0];
                float v1 = acc[mt][nt][half * 2 + 1];
                if (bias) { if (cb < N) v0 += bias[cb]; if (cb + 1 < N) v1 += bias[cb + 1]; }
                size_t base = (size_t)rr * N + cb;
                float w0 = v0, w1 = v1;
                if (res) { if (cb < N) w0 += res[base]; if (cb + 1 < N) w1 += res[base + 1]; }
                if (cb < N)     C[base]     = w0;
                if (cb + 1 < N) C[base + 1] = w1;
                if (C2) {
                    float u0 = v0, u1 = v1;
                    if (res2) { if (cb < N) u0 += res2[base]; if (cb + 1 < N) u1 += res2[base + 1]; }
                    if (cb < N)     C2[base]     = u0;
                    if (cb + 1 < N) C2[base + 1] = u1;
                }
            }
        }
    }
}

// ---------------- 1xTF32 GEMM, fragment-permuted operands, 3-stage ----------
#define S1STG 4096
#define GS1V  (3*S1STG*4)
__global__ void __launch_bounds__(256, 2)
gemm1v(const float* __restrict__ A, const float4* __restrict__ Bq,
       const float* __restrict__ bias, const float* __restrict__ res,
       float* __restrict__ C, int M, int N, int K, int act, int permC) {
    extern __shared__ float sm[];
    int tid = threadIdx.x, warp = tid >> 5, lane = tid & 31;
    int wm = warp & 1, wn = warp >> 1;
    int row0 = blockIdx.y * 128, col0 = blockIdx.x * 128;
    int r = lane >> 2, c = lane & 3;
    int nk = K >> 4, K8 = K >> 3;

    float acc[4][4][4];
#pragma unroll
    for (int i = 0; i < 4; i++)
#pragma unroll
        for (int j = 0; j < 4; j++)
#pragma unroll
            for (int q = 0; q < 4; q++) acc[i][j][q] = 0.f;

#define P1(SIDX, KT) do { \
        float* sa = sm + (SIDX) * S1STG; \
        for (int q = tid; q < 512; q += 256) { \
            int b_ = q >> 6, ks_ = (q >> 5) & 1, ln_ = q & 31; \
            size_t g_ = ((size_t)((row0 >> 4) + b_) * K8 + (KT) * 2 + ks_) * 128 + ln_ * 4; \
            cp16(sa + (b_ * 2 + ks_) * 128 + ln_ * 4, A + g_, true); \
        } \
        for (int q = tid; q < 512; q += 256) { \
            int nl_ = q >> 2, cc_ = q & 3; \
            int n_ = col0 + nl_; \
            size_t g_ = ((size_t)(KT) * N + n_) * 4 + cc_; \
            cp16(sa + 2048 + q * 4, Bq + g_, n_ < N); \
        } \
    } while (0)

    P1(0, 0); CP_COMMIT();
    if (nk > 1) P1(1, 1);
    CP_COMMIT();
    if (nk > 2) P1(2, 2);
    CP_COMMIT();

    for (int kt = 0; kt < nk; kt++) {
        CP_WAIT2();
        __syncthreads();
        int s = kt % 3;
        float* sa = sm + s * S1STG;
        float4 bq4[4];
#pragma unroll
        for (int nt = 0; nt < 4; nt++) {
            int nl = wn * 32 + nt * 8 + r;
            bq4[nt] = *(const float4*)(sa + 2048 + (nl * 4 + c) * 4);
        }
#pragma unroll
        for (int ks = 0; ks < 2; ks++) {
            float4 a4[4];
#pragma unroll
            for (int mt = 0; mt < 4; mt++) {
                int off = ((wm * 4 + mt) * 2 + ks) * 128 + lane * 4;
                a4[mt] = *(const float4*)(sa + off);
            }
#pragma unroll
            for (int mt = 0; mt < 4; mt++) {
                unsigned a0 = __float_as_uint(a4[mt].x), a1 = __float_as_uint(a4[mt].y);
                unsigned a2 = __float_as_uint(a4[mt].z), a3 = __float_as_uint(a4[mt].w);
#pragma unroll
                for (int nt = 0; nt < 4; nt++) {
                    unsigned b0 = __float_as_uint(ks == 0 ? bq4[nt].x : bq4[nt].z);
                    unsigned b1 = __float_as_uint(ks == 0 ? bq4[nt].y : bq4[nt].w);
                    mma_tf32(acc[mt][nt][0], acc[mt][nt][1], acc[mt][nt][2], acc[mt][nt][3],
                             a0, a1, a2, a3, b0, b1);
                }
            }
        }
        __syncthreads();
        if (kt + 3 < nk) P1(s, kt + 3);
        CP_COMMIT();
    }
#undef P1

#pragma unroll
    for (int mt = 0; mt < 4; mt++) {
        int rr0 = row0 + wm * 64 + mt * 16 + r;
#pragma unroll
        for (int nt = 0; nt < 4; nt++) {
            int cb = col0 + wn * 32 + nt * 8 + 2 * c;
#pragma unroll
            for (int half = 0; half < 2; half++) {
                int rr = rr0 + half * 8;
                float v0 = acc[mt][nt][half * 2 + 0];
                float v1 = acc[mt][nt][half * 2 + 1];
                if (bias) { if (cb < N) v0 += bias[cb]; if (cb + 1 < N) v1 += bias[cb + 1]; }
                if (act == 1) {
                    v0 = f2tf32f(0.5f * v0 * (1.f + erff(v0 * 0.70710678118654752f)));
                    v1 = f2tf32f(0.5f * v1 * (1.f + erff(v1 * 0.70710678118654752f)));
                }
                size_t base = (size_t)rr * N + cb;
                if (res) { if (cb < N) v0 += res[base]; if (cb + 1 < N) v1 += res[base + 1]; }
                if (permC) {
                    if (cb < N)     C[aperm(rr, cb, N)]     = v0;
                    if (cb + 1 < N) C[aperm(rr, cb + 1, N)] = v1;
                } else {
                    if (cb < N)     C[base]     = v0;
                    if (cb + 1 < N) C[base + 1] = v1;
                }
            }
        }
    }
}

// ---------------- fused main MHA: aperm split output ------------------------
#define ATTN_SMEM ((3*64*99 + 64*64) * 4)
__global__ void attn_kernel(const float* __restrict__ qkv,
                            float* __restrict__ oh, float* __restrict__ ol) {
    extern __shared__ float smf[];
    float* Qs = smf;
    float* Ks = Qs + 64 * 99;
    float* Vs = Ks + 64 * 99;
    float* Ss = Vs + 64 * 99;
    int b = blockIdx.x >> 3;
    int h = blockIdx.x & 7;
    const float* base = qkv + (size_t)b * 64 * (3 * CDIM) + h * HD;

    for (int e = threadIdx.x; e < 64 * HD; e += blockDim.x) {
        int r = e / HD, d = e % HD;
        const float* rp = base + (size_t)r * (3 * CDIM) + d;
        Qs[r * 99 + d] = rp[0];
        Ks[r * 99 + d] = rp[CDIM];
        Vs[r * 99 + d] = rp[2 * CDIM];
    }
    __syncthreads();

    const float scale = 1.0f / sqrtf(98.0f);
    for (int e = threadIdx.x; e < 4096; e += blockDim.x) {
        int i = e >> 6, j = e & 63;
        const float* qi = Qs + i * 99;
        const float* kj = Ks + j * 99;
        float a = 0.f;
#pragma unroll
        for (int d = 0; d < HD; d++) a = fmaf(qi[d], kj[d], a);
        Ss[e] = a * scale;
    }
    __syncthreads();

    int warp = threadIdx.x >> 5, lane = threadIdx.x & 31;
    for (int i = warp; i < 64; i += 8) {
        float v0 = Ss[i * 64 + lane], v1 = Ss[i * 64 + lane + 32];
        float mx = fmaxf(v0, v1);
        for (int o = 16; o; o >>= 1) mx = fmaxf(mx, __shfl_xor_sync(0xffffffffu, mx, o));
        float e0 = __expf(v0 - mx), e1 = __expf(v1 - mx);
        float s = e0 + e1;
        for (int o = 16; o; o >>= 1) s += __shfl_xor_sync(0xffffffffu, s, o);
        float inv = 1.f / s;
        Ss[i * 64 + lane]      = e0 * inv;
        Ss[i * 64 + lane + 32] = e1 * inv;
    }
    __syncthreads();

    for (int e = threadIdx.x; e < 64 * HD; e += blockDim.x) {
        int i = e / HD, d = e % HD;
        const float* p = Ss + i * 64;
        float a = 0.f;
#pragma unroll
        for (int j = 0; j < 64; j++) a = fmaf(p[j], Vs[j * 99 + d], a);
        size_t idx = aperm(b * 64 + i, h * HD + d, CDIM);
        float hh = f2tf32f(a);
        oh[idx] = hh;
        ol[idx] = f2tf32f(a - hh);
    }
}

// ---------------- transpose with aperm split output -------------------------
__global__ void transpose_split_kernel(const float* __restrict__ in,
                                       float* __restrict__ oh, float* __restrict__ ol) {
    __shared__ float tile[32][33];
    int b = blockIdx.z;
    int r0 = blockIdx.y * 32, c0 = blockIdx.x * 32;
    const float* ib = in + (size_t)b * 64 * 784;
    int r = r0 + threadIdx.y, c = c0 + threadIdx.x;
    if (r < 64 && c < 784) tile[threadIdx.y][threadIdx.x] = ib[(size_t)r * 784 + c];
    __syncthreads();
    int rr = r0 + threadIdx.x, cc = c0 + threadIdx.y;
    if (rr < 64 && cc < 784) {
        float v = tile[threadIdx.x][threadIdx.y];
        float h = f2tf32f(v);
        size_t o = aperm(b * 784 + cc, rr, 64);
        oh[o] = h;
        ol[o] = f2tf32f(v - h);
    }
}

// ---------------- plain transpose: [bt][R][Cc] -> [bt][Cc][R] ----------------
__global__ void transpose_kernel(const float* __restrict__ in, float* __restrict__ out,
                                 int R, int Cc) {
    __shared__ float tile[32][33];
    int b = blockIdx.z;
    int r0 = blockIdx.y * 32, c0 = blockIdx.x * 32;
    const float* ib = in + (size_t)b * R * Cc;
    float* ob = out + (size_t)b * R * Cc;
    int r = r0 + threadIdx.y, c = c0 + threadIdx.x;
    if (r < R && c < Cc) tile[threadIdx.y][threadIdx.x] = ib[(size_t)r * Cc + c];
    __syncthreads();
    int rr = r0 + threadIdx.x, cc = c0 + threadIdx.y;
    if (rr < R && cc < Cc) ob[(size_t)cc * R + rr] = tile[threadIdx.x][threadIdx.y];
}

// ---------------- BiFormer: region mean-pool of q/k -------------------------
__global__ void bf_pool_kernel(const float* __restrict__ qkvt,
                               float* __restrict__ qr, float* __restrict__ kr) {
    int br = blockIdx.x;
    int b = br / 49, r = br % 49;
    int rh = r / 7, rw = r % 7;
    int tid = threadIdx.x;
    int c = tid & 63;
    int off = (tid >= 64) ? 64 : 0;
    int hw0 = (rh * 4) * 28 + rw * 4;
    float s = 0.f;
#pragma unroll
    for (int p = 0; p < 4; p++)
#pragma unroll
        for (int q = 0; q < 4; q++) {
            int hw = hw0 + p * 28 + q;
            s += qkvt[((size_t)b * 784 + hw) * 192 + off + c];
        }
    float* dst = (tid >= 64) ? kr : qr;
    dst[((size_t)b * 49 + r) * 64 + c] = s * (1.0f / 16.0f);
}

// ---------------- region affinity ---------------------------------------------
__global__ void bf_ar_kernel(const float* __restrict__ qr, const float* __restrict__ kr,
                             float* __restrict__ ar) {
    int idx = blockIdx.x * blockDim.x + threadIdx.x;
    if (idx >= NB * 49 * 49) return;
    int s = idx % 49, r = (idx / 49) % 49, b = idx / (49 * 49);
    const float* qp = qr + ((size_t)b * 49 + r) * 64;
    const float* kp = kr + ((size_t)b * 49 + s) * 64;
    float a = 0.f;
#pragma unroll
    for (int c = 0; c < 64; c++) a = fmaf(qp[c], kp[c], a);
    ar[idx] = a;
}

// ---------------- top-4 per (b, r) -------------------------------------------
__global__ void bf_topk_kernel(const float* __restrict__ ar, int* __restrict__ idx) {
    int t = blockIdx.x * blockDim.x + threadIdx.x;
    if (t >= NB * 49) return;
    float v[49];
    const float* row = ar + (size_t)t * 49;
#pragma unroll
    for (int s = 0; s < 49; s++) v[s] = row[s];
    for (int k = 0; k < 4; k++) {
        float best = -3.4e38f; int bi = 0;
        for (int s = 0; s < 49; s++)
            if (v[s] > best) { best = v[s]; bi = s; }
        idx[t * 4 + k] = bi;
        v[bi] = -3.4e38f;
    }
}

// ---------------- BiFormer region attention ----------------------------------
__global__ void bf_attn_kernel(const float* __restrict__ qkvt, const int* __restrict__ idx,
                               float* __restrict__ ao) {
    __shared__ float Qs[16][8], Ks[64][9], Vs[64][9], S[16][64];
    __shared__ int sreg[4];
    int r = blockIdx.x % 49;
    int m = (blockIdx.x / 49) & 7;
    int b = blockIdx.x / (49 * 8);
    int tid = threadIdx.x;
    int rh = r / 7, rw = r % 7;

    if (tid < 4) sreg[tid] = idx[((size_t)b * 49 + r) * 4 + tid];
    {
        int p = tid >> 3, d = tid & 7;
        int hw = (rh * 4 + (p >> 2)) * 28 + rw * 4 + (p & 3);
        Qs[p][d] = qkvt[((size_t)b * 784 + hw) * 192 + m * 8 + d];
    }
    __syncthreads();

    for (int e = tid; e < 512; e += 128) {
        int slot = e >> 3, d = e & 7;
        int t = slot >> 4, s = slot & 15;
        int sr = sreg[t];
        int hw = ((sr / 7) * 4 + (s >> 2)) * 28 + (sr % 7) * 4 + (s & 3);
        const float* p = qkvt + ((size_t)b * 784 + hw) * 192 + m * 8 + d;
        Ks[slot][d] = p[64];
        Vs[slot][d] = p[128];
    }
    __syncthreads();

    for (int e = tid; e < 1024; e += 128) {
        int i = e >> 6, j = e & 63;
        float a = 0.f;
#pragma unroll
        for (int d = 0; d < 8; d++) a = fmaf(Qs[i][d], Ks[j][d], a);
        S[i][j] = a * 0.125f;
    }
    __syncthreads();

    int warp = tid >> 5, lane = tid & 31;
    for (int i = warp; i < 16; i += 4) {
        float v0 = S[i][lane], v1 = S[i][lane + 32];
        float mx = fmaxf(v0, v1);
        for (int o = 16; o; o >>= 1) mx = fmaxf(mx, __shfl_xor_sync(0xffffffffu, mx, o));
        float e0 = __expf(v0 - mx), e1 = __expf(v1 - mx);
        float s = e0 + e1;
        for (int o = 16; o; o >>= 1) s += __shfl_xor_sync(0xffffffffu, s, o);
        float inv = 1.f / s;
        S[i][lane] = e0 * inv;
        S[i][lane + 32] = e1 * inv;
    }
    __syncthreads();

    {
        int i = tid >> 3, d = tid & 7;
        float a = 0.f;
#pragma unroll
        for (int j = 0; j < 64; j++) a = fmaf(S[i][j], Vs[j][d], a);
        int hw = (rh * 4 + (i >> 2)) * 28 + rw * 4 + (i & 3);
        ao[((size_t)b * 784 + hw) * 64 + m * 8 + d] = a;
    }
}

// ---------------- LePE: adds 3x3 dw conv to ao, writes aperm split ----------
__global__ void bf_lepe_split_kernel(const float* __restrict__ qkvt,
                                     const float* __restrict__ w,
                                     const float* __restrict__ bias,
                                     const float* __restrict__ ao,
                                     float* __restrict__ aoh, float* __restrict__ aol) {
    int e = blockIdx.x * blockDim.x + threadIdx.x;
    if (e >= NB * 784 * 64) return;
    int c  = e & 63;
    int hw = (e >> 6) % 784;
    int b  = e / (784 * 64);
    int h = hw / 28, wq = hw % 28;
    float acc = bias[c];
#pragma unroll
    for (int i = 0; i < 3; i++) {
        int hh = h + i - 1;
        if (hh < 0 || hh >= 28) continue;
#pragma unroll
        for (int j = 0; j < 3; j++) {
            int ww = wq + j - 1;
            if (ww < 0 || ww >= 28) continue;
            acc = fmaf(qkvt[((size_t)b * 784 + hh * 28 + ww) * 192 + 128 + c],
                       w[c * 9 + i * 3 + j], acc);
        }
    }
    float v = ao[e] + acc;
    float hh2 = f2tf32f(v);
    size_t idx = aperm(b * 784 + hw, c, 64);
    aoh[idx] = hh2;
    aol[idx] = f2tf32f(v - hh2);
}

// ============================================================================
extern "C" void kernel_launch(void* const* d_in, const int* in_sizes, int n_in,
                              void* d_out, int out_size) {
    const float* x        = (const float*)d_in[0];
    const float* n1g      = (const float*)d_in[1];
    const float* n1b      = (const float*)d_in[2];
    const float* qkv_w    = (const float*)d_in[3];
    const float* proj_w   = (const float*)d_in[4];
    const float* proj_b   = (const float*)d_in[5];
    const float* n2g      = (const float*)d_in[6];
    const float* n2b      = (const float*)d_in[7];
    const float* fc1_w    = (const float*)d_in[8];
    const float* fc1_b    = (const float*)d_in[9];
    const float* fc2_w    = (const float*)d_in[10];
    const float* fc2_b    = (const float*)d_in[11];
    const float* bfqkv_w  = (const float*)d_in[12];
    const float* bfqkv_b  = (const float*)d_in[13];
    const float* bflepe_w = (const float*)d_in[14];
    const float* bflepe_b = (const float*)d_in[15];
    const float* bfout_w  = (const float*)d_in[16];
    const float* bfout_b  = (const float*)d_in[17];
    float* out = (float*)d_out;

    float *p_hh, *p_hl, *p_qkv, *p_aoh, *p_aol, *p_o, *p_xr, *p_h2, *p_mid;
    float *p_xTh, *p_xTl, *p_bfqkv, *p_bfao, *p_bfaoh, *p_bfaol, *p_bf2;
    float4 *p_qwp, *p_pwp, *p_bfqwp, *p_bfowp, *p_fc1wp, *p_fc2wp;
    float *p_qr, *p_kr, *p_ar;
    int* p_idx;
    cudaGetSymbolAddress((void**)&p_hh,    g_h_hi);
    cudaGetSymbolAddress((void**)&p_hl,    g_h_lo);
    cudaGetSymbolAddress((void**)&p_qkv,   g_qkv);
    cudaGetSymbolAddress((void**)&p_aoh,   g_ao_hi);
    cudaGetSymbolAddress((void**)&p_aol,   g_ao_lo);
    cudaGetSymbolAddress((void**)&p_o,     g_o);
    cudaGetSymbolAddress((void**)&p_xr,    g_xr);
    cudaGetSymbolAddress((void**)&p_h2,    g_h2);
    cudaGetSymbolAddress((void**)&p_mid,   g_mid);
    cudaGetSymbolAddress((void**)&p_xTh,   g_xT_hi);
    cudaGetSymbolAddress((void**)&p_xTl,   g_xT_lo);
    cudaGetSymbolAddress((void**)&p_bfqkv, g_bfqkv);
    cudaGetSymbolAddress((void**)&p_bfao,  g_bfao);
    cudaGetSymbolAddress((void**)&p_bfaoh, g_bfao_hi);
    cudaGetSymbolAddress((void**)&p_bfaol, g_bfao_lo);
    cudaGetSymbolAddress((void**)&p_bf2,   g_bf2);
    cudaGetSymbolAddress((void**)&p_qwp,   g_qwp);
    cudaGetSymbolAddress((void**)&p_pwp,   g_pwp);
    cudaGetSymbolAddress((void**)&p_bfqwp, g_bfqwp);
    cudaGetSymbolAddress((void**)&p_bfowp, g_bfowp);
    cudaGetSymbolAddress((void**)&p_fc1wp, g_fc1wp);
    cudaGetSymbolAddress((void**)&p_fc2wp, g_fc2wp);
    cudaGetSymbolAddress((void**)&p_qr,    g_qr);
    cudaGetSymbolAddress((void**)&p_kr,    g_kr);
    cudaGetSymbolAddress((void**)&p_ar,    g_ar);
    cudaGetSymbolAddress((void**)&p_idx,   g_topk);

    cudaFuncSetAttribute(attn_kernel, cudaFuncAttributeMaxDynamicSharedMemorySize, ATTN_SMEM);
    cudaFuncSetAttribute(gemm3v, cudaFuncAttributeMaxDynamicSharedMemorySize, GS3V);
    cudaFuncSetAttribute(gemm1v, cudaFuncAttributeMaxDynamicSharedMemorySize, GS1V);

    // ---- weight packs ----
    bpack3 <<<(98 * 2352 * 4 + 255) / 256, 256>>>(qkv_w,  p_qwp,   CDIM, 3 * CDIM);
    bpack3 <<<(98 * 784 * 4 + 255) / 256, 256>>>(proj_w, p_pwp,   CDIM, CDIM);
    bpack3t<<<(8 * 192 * 4 + 255) / 256, 256>>>(bfqkv_w, p_bfqwp, 64, 192);
    bpack3t<<<(8 * 64 * 4 + 255) / 256, 256>>>(bfout_w,  p_bfowp, 64, 64);
    bpack1 <<<(49 * 3136 * 4 + 255) / 256, 256>>>(fc1_w, p_fc1wp, CDIM, HID);
    bpack1 <<<(196 * 784 * 4 + 255) / 256, 256>>>(fc2_w, p_fc2wp, HID, CDIM);

    // ---- main path up through proj (3xTF32) ----
    ln_split_kernel<<<NROW, 256>>>(x, n1g, n1b, p_hh, p_hl);
    gemm3v<<<dim3(19, 64), 256, GS3V>>>(p_hh, p_hl, p_qwp, nullptr, nullptr,
                                        p_qkv, nullptr, nullptr, NROW, 3 * CDIM, CDIM);
    attn_kernel<<<NB * NHD, 256, ATTN_SMEM>>>(p_qkv, p_aoh, p_aol);
    gemm3v<<<dim3(7, 64), 256, GS3V>>>(p_aoh, p_aol, p_pwp, proj_b, nullptr,
                                       p_o, p_xr, x, NROW, CDIM, CDIM);

    // ---- BiFormer branch ----
    transpose_split_kernel<<<dim3(25, 2, NB), dim3(32, 32)>>>(p_o, p_xTh, p_xTl);
    gemm3v<<<dim3(2, M2 / 128), 256, GS3V>>>(p_xTh, p_xTl, p_bfqwp, bfqkv_b, nullptr,
                                             p_bfqkv, nullptr, nullptr, M2, 192, 64);
    bf_pool_kernel<<<NB * 49, 128>>>(p_bfqkv, p_qr, p_kr);
    bf_ar_kernel<<<(NB * 49 * 49 + 255) / 256, 256>>>(p_qr, p_kr, p_ar);
    bf_topk_kernel<<<(NB * 49 + 255) / 256, 256>>>(p_ar, p_idx);
    bf_attn_kernel<<<NB * 8 * 49, 128>>>(p_bfqkv, p_idx, p_bfao);
    bf_lepe_split_kernel<<<(NB * 784 * 64 + 255) / 256, 256>>>(p_bfqkv, bflepe_w, bflepe_b,
                                                               p_bfao, p_bfaoh, p_bfaol);
    gemm3v<<<dim3(1, M2 / 128), 256, GS3V>>>(p_bfaoh, p_bfaol, p_bfowp, bfout_b, nullptr,
                                             p_bf2, nullptr, nullptr, M2, 64, 64);
    transpose_kernel<<<dim3(2, 25, NB), dim3(32, 32)>>>(p_bf2, out + OUT1, 784, 64);

    // ---- main path: LN2 + MLP (1xTF32) ----
    ln_kernel<<<NROW, 256>>>(p_xr, n2g, n2b, p_h2);
    gemm1v<<<dim3(25, 64), 256, GS1V>>>(p_h2, p_fc1wp, fc1_b, nullptr, p_mid,
                                        NROW, HID, CDIM, 1, 1);
    gemm1v<<<dim3(7, 64), 256, GS1V>>>(p_mid, p_fc2wp, fc2_b, p_xr, out,
                                       NROW, CDIM, HID, 0, 0);
}

// round 11
// speedup vs baseline: 1.0637x; 1.0637x over previous
#include <cuda_runtime.h>
#include <math.h>
#include <stdint.h>

#define NB    128
#define NTOKN 64
#define CDIM  784
#define NHD   8
#define HD    98
#define HID   3136
#define NROW  (NB*NTOKN)
#define M2    (NB*784)
#define OUT1  (NROW*CDIM)

// ---------------- scratch (device globals; no allocation allowed) ----------
__device__ float  g_h_hi  [NROW*CDIM];     // aperm
__device__ float  g_h_lo  [NROW*CDIM];     // aperm
__device__ float  g_qkv   [NROW*3*CDIM];
__device__ float  g_ao_hi [NROW*CDIM];     // aperm
__device__ float  g_ao_lo [NROW*CDIM];     // aperm
__device__ float  g_o     [NROW*CDIM];
__device__ float  g_xr    [NROW*CDIM];
__device__ float  g_h2    [NROW*CDIM];     // aperm
__device__ float  g_mid   [NROW*HID];      // aperm
__device__ float  g_xT_hi [M2*64];         // aperm
__device__ float  g_xT_lo [M2*64];         // aperm
__device__ float  g_bfqkv [M2*192];
__device__ float  g_bfao  [M2*64];
__device__ float  g_bfao_hi[M2*64];        // aperm
__device__ float  g_bfao_lo[M2*64];        // aperm
__device__ float  g_bf2   [M2*64];
__device__ float4 g_qwp   [(CDIM/8)*(3*CDIM)*4];
__device__ float4 g_pwp   [(CDIM/8)*CDIM*4];
__device__ float4 g_bfqwp [(64/8)*192*4];
__device__ float4 g_bfowp [(64/8)*64*4];
__device__ float4 g_fc1wp [(CDIM/16)*HID*4];
__device__ float4 g_fc2wp [(HID/16)*CDIM*4];
__device__ float  g_qr    [NB*49*64];
__device__ float  g_kr    [NB*49*64];
__device__ float  g_ar    [NB*49*49];
__device__ int    g_topk  [NB*49*4];

// ---------------- helpers ----------------------------------------------------
__device__ __forceinline__ float f2tf32f(float x) {
    unsigned r;
    asm("cvt.rna.tf32.f32 %0, %1;" : "=r"(r) : "f"(x));
    return __uint_as_float(r);
}

// fragment-order A permutation: 16-row x 8-k blocks of 128 floats.
__device__ __forceinline__ size_t aperm(int row, int k, int K) {
    return ((size_t)((row >> 4) * (K >> 3) + (k >> 3)) << 7)
         + (size_t)((((row & 7) << 2) | (k & 3)) << 2)
         + (size_t)(((k & 4) >> 1) | ((row & 8) >> 3));
}

__device__ __forceinline__ void mma_tf32(float& d0, float& d1, float& d2, float& d3,
                                         unsigned a0, unsigned a1, unsigned a2, unsigned a3,
                                         unsigned b0, unsigned b1) {
    asm volatile(
        "mma.sync.aligned.m16n8k8.row.col.f32.tf32.tf32.f32 "
        "{%0,%1,%2,%3}, {%4,%5,%6,%7}, {%8,%9}, {%0,%1,%2,%3};\n"
        : "+f"(d0), "+f"(d1), "+f"(d2), "+f"(d3)
        : "r"(a0), "r"(a1), "r"(a2), "r"(a3), "r"(b0), "r"(b1));
}

__device__ __forceinline__ void cp16(void* dst, const void* src, bool pred) {
    unsigned daddr = (unsigned)__cvta_generic_to_shared(dst);
    int sz = pred ? 16 : 0;
    asm volatile("cp.async.cg.shared.global [%0], [%1], 16, %2;\n"
                 :: "r"(daddr), "l"(src), "r"(sz));
}
#define CP_COMMIT() asm volatile("cp.async.commit_group;\n" ::: "memory")
#define CP_WAIT2()  asm volatile("cp.async.wait_group 2;\n" ::: "memory")

// ---------------- weight packs -----------------------------------------------
__global__ void bpack3(const float* __restrict__ w, float4* __restrict__ out,
                       int K, int N) {
    int q = blockIdx.x * blockDim.x + threadIdx.x;
    int total = (K >> 3) * N * 4;
    if (q >= total) return;
    int c = q & 3, n = (q >> 2) % N, k8 = q / (4 * N);
    float v0 = w[(size_t)(k8 * 8 + c) * N + n];
    float v1 = w[(size_t)(k8 * 8 + c + 4) * N + n];
    float h0 = f2tf32f(v0), h1 = f2tf32f(v1);
    out[q] = make_float4(h0, f2tf32f(v0 - h0), h1, f2tf32f(v1 - h1));
}
__global__ void bpack3t(const float* __restrict__ w, float4* __restrict__ out,
                        int K, int N) {
    int q = blockIdx.x * blockDim.x + threadIdx.x;
    int total = (K >> 3) * N * 4;
    if (q >= total) return;
    int c = q & 3, n = (q >> 2) % N, k8 = q / (4 * N);
    float v0 = w[(size_t)n * K + k8 * 8 + c];
    float v1 = w[(size_t)n * K + k8 * 8 + c + 4];
    float h0 = f2tf32f(v0), h1 = f2tf32f(v1);
    out[q] = make_float4(h0, f2tf32f(v0 - h0), h1, f2tf32f(v1 - h1));
}
__global__ void bpack1(const float* __restrict__ w, float4* __restrict__ out,
                       int K, int N) {
    int q = blockIdx.x * blockDim.x + threadIdx.x;
    int total = (K >> 4) * N * 4;
    if (q >= total) return;
    int c = q & 3, n = (q >> 2) % N, k16 = q / (4 * N);
    const float* p = w + (size_t)(k16 * 16 + c) * N + n;
    out[q] = make_float4(f2tf32f(p[0]),
                         f2tf32f(p[(size_t)4 * N]),
                         f2tf32f(p[(size_t)8 * N]),
                         f2tf32f(p[(size_t)12 * N]));
}

// ---------------- LayerNorm, aperm rounded output ----------------------------
__global__ void ln_kernel(const float* __restrict__ x, const float* __restrict__ g,
                          const float* __restrict__ b, float* __restrict__ y) {
    int row = blockIdx.x;
    const float* xr = x + (size_t)row * CDIM;
    float s = 0.f, s2 = 0.f;
    for (int i = threadIdx.x; i < CDIM; i += blockDim.x) {
        float v = xr[i]; s += v; s2 += v * v;
    }
    for (int o = 16; o; o >>= 1) {
        s  += __shfl_xor_sync(0xffffffffu, s,  o);
        s2 += __shfl_xor_sync(0xffffffffu, s2, o);
    }
    __shared__ float sh[16], sh2[16];
    int warp = threadIdx.x >> 5, lane = threadIdx.x & 31;
    if (lane == 0) { sh[warp] = s; sh2[warp] = s2; }
    __syncthreads();
    if (threadIdx.x == 0) {
        float t = 0.f, t2 = 0.f;
        int nw = blockDim.x >> 5;
        for (int i = 0; i < nw; i++) { t += sh[i]; t2 += sh2[i]; }
        sh[0] = t; sh2[0] = t2;
    }
    __syncthreads();
    float mean = sh[0] * (1.0f / CDIM);
    float var  = sh2[0] * (1.0f / CDIM) - mean * mean;
    float rinv = rsqrtf(var + 1e-5f);
    for (int i = threadIdx.x; i < CDIM; i += blockDim.x)
        y[aperm(row, i, CDIM)] = f2tf32f((xr[i] - mean) * rinv * g[i] + b[i]);
}

// ---------------- LayerNorm, aperm split output ------------------------------
__global__ void ln_split_kernel(const float* __restrict__ x, const float* __restrict__ g,
                                const float* __restrict__ b,
                                float* __restrict__ yh, float* __restrict__ yl) {
    int row = blockIdx.x;
    const float* xr = x + (size_t)row * CDIM;
    float s = 0.f, s2 = 0.f;
    for (int i = threadIdx.x; i < CDIM; i += blockDim.x) {
        float v = xr[i]; s += v; s2 += v * v;
    }
    for (int o = 16; o; o >>= 1) {
        s  += __shfl_xor_sync(0xffffffffu, s,  o);
        s2 += __shfl_xor_sync(0xffffffffu, s2, o);
    }
    __shared__ float sh[16], sh2[16];
    int warp = threadIdx.x >> 5, lane = threadIdx.x & 31;
    if (lane == 0) { sh[warp] = s; sh2[warp] = s2; }
    __syncthreads();
    if (threadIdx.x == 0) {
        float t = 0.f, t2 = 0.f;
        int nw = blockDim.x >> 5;
        for (int i = 0; i < nw; i++) { t += sh[i]; t2 += sh2[i]; }
        sh[0] = t; sh2[0] = t2;
    }
    __syncthreads();
    float mean = sh[0] * (1.0f / CDIM);
    float var  = sh2[0] * (1.0f / CDIM) - mean * mean;
    float rinv = rsqrtf(var + 1e-5f);
    for (int i = threadIdx.x; i < CDIM; i += blockDim.x) {
        float v = (xr[i] - mean) * rinv * g[i] + b[i];
        float h = f2tf32f(v);
        size_t idx = aperm(row, i, CDIM);
        yh[idx] = h;
        yl[idx] = f2tf32f(v - h);
    }
}

// ---------------- 3xTF32 GEMM, fragment-permuted operands, 3-stage ----------
#define S3STG 8192
#define GS3V  (3*S3STG*4)
__global__ void __launch_bounds__(256, 2)
gemm3v(const float* __restrict__ Ah, const float* __restrict__ Al,
       const float4* __restrict__ Bq,
       const float* __restrict__ bias, const float* __restrict__ res,
       float* __restrict__ C, float* __restrict__ C2, const float* __restrict__ res2,
       int M, int N, int K) {
    extern __shared__ float sm[];
    int tid = threadIdx.x, warp = tid >> 5, lane = tid & 31;
    int wm = warp & 1, wn = warp >> 1;
    int row0 = blockIdx.y * 128, col0 = blockIdx.x * 128;
    int r = lane >> 2, c = lane & 3;
    int nk = K >> 4, K8 = K >> 3;

    float acc[4][4][4];
#pragma unroll
    for (int i = 0; i < 4; i++)
#pragma unroll
        for (int j = 0; j < 4; j++)
#pragma unroll
            for (int q = 0; q < 4; q++) acc[i][j][q] = 0.f;

#define P3(SIDX, KT) do { \
        float* sa = sm + (SIDX) * S3STG; \
        for (int q = tid; q < 512; q += 256) { \
            int b_ = q >> 6, ks_ = (q >> 5) & 1, ln_ = q & 31; \
            size_t g_ = ((size_t)((row0 >> 4) + b_) * K8 + (KT) * 2 + ks_) * 128 + ln_ * 4; \
            cp16(sa + (b_ * 2 + ks_) * 128 + ln_ * 4, Ah + g_, true); \
            cp16(sa + 2048 + (b_ * 2 + ks_) * 128 + ln_ * 4, Al + g_, true); \
        } \
        for (int q = tid; q < 1024; q += 256) { \
            int ks_ = q >> 9, rem_ = q & 511, nl_ = rem_ >> 2, cc_ = rem_ & 3; \
            int n_ = col0 + nl_; \
            size_t g_ = ((size_t)((KT) * 2 + ks_) * N + n_) * 4 + cc_; \
            cp16(sa + 4096 + q * 4, Bq + g_, n_ < N); \
        } \
    } while (0)

    P3(0, 0); CP_COMMIT();
    if (nk > 1) P3(1, 1);
    CP_COMMIT();
    if (nk > 2) P3(2, 2);
    CP_COMMIT();

    for (int kt = 0; kt < nk; kt++) {
        CP_WAIT2();
        __syncthreads();
        int s = kt % 3;
        float* sa = sm + s * S3STG;
#pragma unroll
        for (int ks = 0; ks < 2; ks++) {
            float4 ah4[4], al4[4], bq4[4];
#pragma unroll
            for (int mt = 0; mt < 4; mt++) {
                int off = ((wm * 4 + mt) * 2 + ks) * 128 + lane * 4;
                ah4[mt] = *(const float4*)(sa + off);
                al4[mt] = *(const float4*)(sa + 2048 + off);
            }
#pragma unroll
            for (int nt = 0; nt < 4; nt++) {
                int nl = wn * 32 + nt * 8 + r;
                bq4[nt] = *(const float4*)(sa + 4096 + ((ks * 128 + nl) * 4 + c) * 4);
            }
#pragma unroll
            for (int mt = 0; mt < 4; mt++) {
                unsigned a0 = __float_as_uint(ah4[mt].x), a1 = __float_as_uint(ah4[mt].y);
                unsigned a2 = __float_as_uint(ah4[mt].z), a3 = __float_as_uint(ah4[mt].w);
                unsigned l0 = __float_as_uint(al4[mt].x), l1 = __float_as_uint(al4[mt].y);
                unsigned l2 = __float_as_uint(al4[mt].z), l3 = __float_as_uint(al4[mt].w);
#pragma unroll
                for (int nt = 0; nt < 4; nt++) {
                    unsigned bh0 = __float_as_uint(bq4[nt].x), bl0 = __float_as_uint(bq4[nt].y);
                    unsigned bh1 = __float_as_uint(bq4[nt].z), bl1 = __float_as_uint(bq4[nt].w);
                    mma_tf32(acc[mt][nt][0], acc[mt][nt][1], acc[mt][nt][2], acc[mt][nt][3],
                             a0, a1, a2, a3, bl0, bl1);
                    mma_tf32(acc[mt][nt][0], acc[mt][nt][1], acc[mt][nt][2], acc[mt][nt][3],
                             l0, l1, l2, l3, bh0, bh1);
                    mma_tf32(acc[mt][nt][0], acc[mt][nt][1], acc[mt][nt][2], acc[mt][nt][3],
                             a0, a1, a2, a3, bh0, bh1);
                }
            }
        }
        __syncthreads();
        if (kt + 3 < nk) P3(s, kt + 3);
        CP_COMMIT();
    }
#undef P3

#pragma unroll
    for (int mt = 0; mt < 4; mt++) {
        int rr0 = row0 + wm * 64 + mt * 16 + r;
#pragma unroll
        for (int nt = 0; nt < 4; nt++) {
            int cb = col0 + wn * 32 + nt * 8 + 2 * c;
#pragma unroll
            for (int half = 0; half < 2; half++) {
                int rr = rr0 + half * 8;
                float v0 = acc[mt][nt][half * 2 + 0];
                float v1 = acc[mt][nt][half * 2 + 1];
                if (bias) { if (cb < N) v0 += bias[cb]; if (cb + 1 < N) v1 += bias[cb + 1]; }
                size_t base = (size_t)rr * N + cb;
                float w0 = v0, w1 = v1;
                if (res) { if (cb < N) w0 += res[base]; if (cb + 1 < N) w1 += res[base + 1]; }
                if (cb < N)     C[base]     = w0;
                if (cb + 1 < N) C[base + 1] = w1;
                if (C2) {
                    float u0 = v0, u1 = v1;
                    if (res2) { if (cb < N) u0 += res2[base]; if (cb + 1 < N) u1 += res2[base + 1]; }
                    if (cb < N)     C2[base]     = u0;
                    if (cb + 1 < N) C2[base + 1] = u1;
                }
            }
        }
    }
}

// ---------------- 1xTF32 GEMM, fragment-permuted operands, 3-stage ----------
#define S1STG 4096
#define GS1V  (3*S1STG*4)
__global__ void __launch_bounds__(256, 2)
gemm1v(const float* __restrict__ A, const float4* __restrict__ Bq,
       const float* __restrict__ bias, const float* __restrict__ res,
       float* __restrict__ C, int M, int N, int K, int act, int permC) {
    extern __shared__ float sm[];
    int tid = threadIdx.x, warp = tid >> 5, lane = tid & 31;
    int wm = warp & 1, wn = warp >> 1;
    int row0 = blockIdx.y * 128, col0 = blockIdx.x * 128;
    int r = lane >> 2, c = lane & 3;
    int nk = K >> 4, K8 = K >> 3;

    float acc[4][4][4];
#pragma unroll
    for (int i = 0; i < 4; i++)
#pragma unroll
        for (int j = 0; j < 4; j++)
#pragma unroll
            for (int q = 0; q < 4; q++) acc[i][j][q] = 0.f;

#define P1(SIDX, KT) do { \
        float* sa = sm + (SIDX) * S1STG; \
        for (int q = tid; q < 512; q += 256) { \
            int b_ = q >> 6, ks_ = (q >> 5) & 1, ln_ = q & 31; \
            size_t g_ = ((size_t)((row0 >> 4) + b_) * K8 + (KT) * 2 + ks_) * 128 + ln_ * 4; \
            cp16(sa + (b_ * 2 + ks_) * 128 + ln_ * 4, A + g_, true); \
        } \
        for (int q = tid; q < 512; q += 256) { \
            int nl_ = q >> 2, cc_ = q & 3; \
            int n_ = col0 + nl_; \
            size_t g_ = ((size_t)(KT) * N + n_) * 4 + cc_; \
            cp16(sa + 2048 + q * 4, Bq + g_, n_ < N); \
        } \
    } while (0)

    P1(0, 0); CP_COMMIT();
    if (nk > 1) P1(1, 1);
    CP_COMMIT();
    if (nk > 2) P1(2, 2);
    CP_COMMIT();

    for (int kt = 0; kt < nk; kt++) {
        CP_WAIT2();
        __syncthreads();
        int s = kt % 3;
        float* sa = sm + s * S1STG;
        float4 bq4[4];
#pragma unroll
        for (int nt = 0; nt < 4; nt++) {
            int nl = wn * 32 + nt * 8 + r;
            bq4[nt] = *(const float4*)(sa + 2048 + (nl * 4 + c) * 4);
        }
#pragma unroll
        for (int ks = 0; ks < 2; ks++) {
            float4 a4[4];
#pragma unroll
            for (int mt = 0; mt < 4; mt++) {
                int off = ((wm * 4 + mt) * 2 + ks) * 128 + lane * 4;
                a4[mt] = *(const float4*)(sa + off);
            }
#pragma unroll
            for (int mt = 0; mt < 4; mt++) {
                unsigned a0 = __float_as_uint(a4[mt].x), a1 = __float_as_uint(a4[mt].y);
                unsigned a2 = __float_as_uint(a4[mt].z), a3 = __float_as_uint(a4[mt].w);
#pragma unroll
                for (int nt = 0; nt < 4; nt++) {
                    unsigned b0 = __float_as_uint(ks == 0 ? bq4[nt].x : bq4[nt].z);
                    unsigned b1 = __float_as_uint(ks == 0 ? bq4[nt].y : bq4[nt].w);
                    mma_tf32(acc[mt][nt][0], acc[mt][nt][1], acc[mt][nt][2], acc[mt][nt][3],
                             a0, a1, a2, a3, b0, b1);
                }
            }
        }
        __syncthreads();
        if (kt + 3 < nk) P1(s, kt + 3);
        CP_COMMIT();
    }
#undef P1

#pragma unroll
    for (int mt = 0; mt < 4; mt++) {
        int rr0 = row0 + wm * 64 + mt * 16 + r;
#pragma unroll
        for (int nt = 0; nt < 4; nt++) {
            int cb = col0 + wn * 32 + nt * 8 + 2 * c;
#pragma unroll
            for (int half = 0; half < 2; half++) {
                int rr = rr0 + half * 8;
                float v0 = acc[mt][nt][half * 2 + 0];
                float v1 = acc[mt][nt][half * 2 + 1];
                if (bias) { if (cb < N) v0 += bias[cb]; if (cb + 1 < N) v1 += bias[cb + 1]; }
                if (act == 1) {
                    v0 = f2tf32f(0.5f * v0 * (1.f + erff(v0 * 0.70710678118654752f)));
                    v1 = f2tf32f(0.5f * v1 * (1.f + erff(v1 * 0.70710678118654752f)));
                }
                size_t base = (size_t)rr * N + cb;
                if (res) { if (cb < N) v0 += res[base]; if (cb + 1 < N) v1 += res[base + 1]; }
                if (permC) {
                    if (cb < N)     C[aperm(rr, cb, N)]     = v0;
                    if (cb + 1 < N) C[aperm(rr, cb + 1, N)] = v1;
                } else {
                    if (cb < N)     C[base]     = v0;
                    if (cb + 1 < N) C[base + 1] = v1;
                }
            }
        }
    }
}

// ---------------- fused main MHA: aperm split output ------------------------
#define ATTN_SMEM ((3*64*99 + 64*64) * 4)
__global__ void attn_kernel(const float* __restrict__ qkv,
                            float* __restrict__ oh, float* __restrict__ ol) {
    extern __shared__ float smf[];
    float* Qs = smf;
    float* Ks = Qs + 64 * 99;
    float* Vs = Ks + 64 * 99;
    float* Ss = Vs + 64 * 99;
    int b = blockIdx.x >> 3;
    int h = blockIdx.x & 7;
    const float* base = qkv + (size_t)b * 64 * (3 * CDIM) + h * HD;

    for (int e = threadIdx.x; e < 64 * HD; e += blockDim.x) {
        int r = e / HD, d = e % HD;
        const float* rp = base + (size_t)r * (3 * CDIM) + d;
        Qs[r * 99 + d] = rp[0];
        Ks[r * 99 + d] = rp[CDIM];
        Vs[r * 99 + d] = rp[2 * CDIM];
    }
    __syncthreads();

    const float scale = 1.0f / sqrtf(98.0f);
    for (int e = threadIdx.x; e < 4096; e += blockDim.x) {
        int i = e >> 6, j = e & 63;
        const float* qi = Qs + i * 99;
        const float* kj = Ks + j * 99;
        float a = 0.f;
#pragma unroll
        for (int d = 0; d < HD; d++) a = fmaf(qi[d], kj[d], a);
        Ss[e] = a * scale;
    }
    __syncthreads();

    int warp = threadIdx.x >> 5, lane = threadIdx.x & 31;
    for (int i = warp; i < 64; i += 8) {
        float v0 = Ss[i * 64 + lane], v1 = Ss[i * 64 + lane + 32];
        float mx = fmaxf(v0, v1);
        for (int o = 16; o; o >>= 1) mx = fmaxf(mx, __shfl_xor_sync(0xffffffffu, mx, o));
        float e0 = __expf(v0 - mx), e1 = __expf(v1 - mx);
        float s = e0 + e1;
        for (int o = 16; o; o >>= 1) s += __shfl_xor_sync(0xffffffffu, s, o);
        float inv = 1.f / s;
        Ss[i * 64 + lane]      = e0 * inv;
        Ss[i * 64 + lane + 32] = e1 * inv;
    }
    __syncthreads();

    for (int e = threadIdx.x; e < 64 * HD; e += blockDim.x) {
        int i = e / HD, d = e % HD;
        const float* p = Ss + i * 64;
        float a = 0.f;
#pragma unroll
        for (int j = 0; j < 64; j++) a = fmaf(p[j], Vs[j * 99 + d], a);
        size_t idx = aperm(b * 64 + i, h * HD + d, CDIM);
        float hh = f2tf32f(a);
        oh[idx] = hh;
        ol[idx] = f2tf32f(a - hh);
    }
}

// ---------------- transpose with aperm split output -------------------------
__global__ void transpose_split_kernel(const float* __restrict__ in,
                                       float* __restrict__ oh, float* __restrict__ ol) {
    __shared__ float tile[32][33];
    int b = blockIdx.z;
    int r0 = blockIdx.y * 32, c0 = blockIdx.x * 32;
    const float* ib = in + (size_t)b * 64 * 784;
    int r = r0 + threadIdx.y, c = c0 + threadIdx.x;
    if (r < 64 && c < 784) tile[threadIdx.y][threadIdx.x] = ib[(size_t)r * 784 + c];
    __syncthreads();
    int rr = r0 + threadIdx.x, cc = c0 + threadIdx.y;
    if (rr < 64 && cc < 784) {
        float v = tile[threadIdx.x][threadIdx.y];
        float h = f2tf32f(v);
        size_t o = aperm(b * 784 + cc, rr, 64);
        oh[o] = h;
        ol[o] = f2tf32f(v - h);
    }
}

// ---------------- plain transpose: [bt][R][Cc] -> [bt][Cc][R] ----------------
__global__ void transpose_kernel(const float* __restrict__ in, float* __restrict__ out,
                                 int R, int Cc) {
    __shared__ float tile[32][33];
    int b = blockIdx.z;
    int r0 = blockIdx.y * 32, c0 = blockIdx.x * 32;
    const float* ib = in + (size_t)b * R * Cc;
    float* ob = out + (size_t)b * R * Cc;
    int r = r0 + threadIdx.y, c = c0 + threadIdx.x;
    if (r < R && c < Cc) tile[threadIdx.y][threadIdx.x] = ib[(size_t)r * Cc + c];
    __syncthreads();
    int rr = r0 + threadIdx.x, cc = c0 + threadIdx.y;
    if (rr < R && cc < Cc) ob[(size_t)cc * R + rr] = tile[threadIdx.x][threadIdx.y];
}

// ---------------- BiFormer: region mean-pool of q/k -------------------------
__global__ void bf_pool_kernel(const float* __restrict__ qkvt,
                               float* __restrict__ qr, float* __restrict__ kr) {
    int br = blockIdx.x;
    int b = br / 49, r = br % 49;
    int rh = r / 7, rw = r % 7;
    int tid = threadIdx.x;
    int c = tid & 63;
    int off = (tid >= 64) ? 64 : 0;
    int hw0 = (rh * 4) * 28 + rw * 4;
    float s = 0.f;
#pragma unroll
    for (int p = 0; p < 4; p++)
#pragma unroll
        for (int q = 0; q < 4; q++) {
            int hw = hw0 + p * 28 + q;
            s += qkvt[((size_t)b * 784 + hw) * 192 + off + c];
        }
    float* dst = (tid >= 64) ? kr : qr;
    dst[((size_t)b * 49 + r) * 64 + c] = s * (1.0f / 16.0f);
}

// ---------------- region affinity ---------------------------------------------
__global__ void bf_ar_kernel(const float* __restrict__ qr, const float* __restrict__ kr,
                             float* __restrict__ ar) {
    int idx = blockIdx.x * blockDim.x + threadIdx.x;
    if (idx >= NB * 49 * 49) return;
    int s = idx % 49, r = (idx / 49) % 49, b = idx / (49 * 49);
    const float* qp = qr + ((size_t)b * 49 + r) * 64;
    const float* kp = kr + ((size_t)b * 49 + s) * 64;
    float a = 0.f;
#pragma unroll
    for (int c = 0; c < 64; c++) a = fmaf(qp[c], kp[c], a);
    ar[idx] = a;
}

// ---------------- top-4 per (b, r) -------------------------------------------
__global__ void bf_topk_kernel(const float* __restrict__ ar, int* __restrict__ idx) {
    int t = blockIdx.x * blockDim.x + threadIdx.x;
    if (t >= NB * 49) return;
    float v[49];
    const float* row = ar + (size_t)t * 49;
#pragma unroll
    for (int s = 0; s < 49; s++) v[s] = row[s];
    for (int k = 0; k < 4; k++) {
        float best = -3.4e38f; int bi = 0;
        for (int s = 0; s < 49; s++)
            if (v[s] > best) { best = v[s]; bi = s; }
        idx[t * 4 + k] = bi;
        v[bi] = -3.4e38f;
    }
}

// ---------------- BiFormer region attention ----------------------------------
__global__ void bf_attn_kernel(const float* __restrict__ qkvt, const int* __restrict__ idx,
                               float* __restrict__ ao) {
    __shared__ float Qs[16][8], Ks[64][9], Vs[64][9], S[16][64];
    __shared__ int sreg[4];
    int r = blockIdx.x % 49;
    int m = (blockIdx.x / 49) & 7;
    int b = blockIdx.x / (49 * 8);
    int tid = threadIdx.x;
    int rh = r / 7, rw = r % 7;

    if (tid < 4) sreg[tid] = idx[((size_t)b * 49 + r) * 4 + tid];
    {
        int p = tid >> 3, d = tid & 7;
        int hw = (rh * 4 + (p >> 2)) * 28 + rw * 4 + (p & 3);
        Qs[p][d] = qkvt[((size_t)b * 784 + hw) * 192 + m * 8 + d];
    }
    __syncthreads();

    for (int e = tid; e < 512; e += 128) {
        int slot = e >> 3, d = e & 7;
        int t = slot >> 4, s = slot & 15;
        int sr = sreg[t];
        int hw = ((sr / 7) * 4 + (s >> 2)) * 28 + (sr % 7) * 4 + (s & 3);
        const float* p = qkvt + ((size_t)b * 784 + hw) * 192 + m * 8 + d;
        Ks[slot][d] = p[64];
        Vs[slot][d] = p[128];
    }
    __syncthreads();

    for (int e = tid; e < 1024; e += 128) {
        int i = e >> 6, j = e & 63;
        float a = 0.f;
#pragma unroll
        for (int d = 0; d < 8; d++) a = fmaf(Qs[i][d], Ks[j][d], a);
        S[i][j] = a * 0.125f;
    }
    __syncthreads();

    int warp = tid >> 5, lane = tid & 31;
    for (int i = warp; i < 16; i += 4) {
        float v0 = S[i][lane], v1 = S[i][lane + 32];
        float mx = fmaxf(v0, v1);
        for (int o = 16; o; o >>= 1) mx = fmaxf(mx, __shfl_xor_sync(0xffffffffu, mx, o));
        float e0 = __expf(v0 - mx), e1 = __expf(v1 - mx);
        float s = e0 + e1;
        for (int o = 16; o; o >>= 1) s += __shfl_xor_sync(0xffffffffu, s, o);
        float inv = 1.f / s;
        S[i][lane] = e0 * inv;
        S[i][lane + 32] = e1 * inv;
    }
    __syncthreads();

    {
        int i = tid >> 3, d = tid & 7;
        float a = 0.f;
#pragma unroll
        for (int j = 0; j < 64; j++) a = fmaf(S[i][j], Vs[j][d], a);
        int hw = (rh * 4 + (i >> 2)) * 28 + rw * 4 + (i & 3);
        ao[((size_t)b * 784 + hw) * 64 + m * 8 + d] = a;
    }
}

// ---------------- LePE: adds 3x3 dw conv to ao, writes aperm split ----------
__global__ void bf_lepe_split_kernel(const float* __restrict__ qkvt,
                                     const float* __restrict__ w,
                                     const float* __restrict__ bias,
                                     const float* __restrict__ ao,
                                     float* __restrict__ aoh, float* __restrict__ aol) {
    int e = blockIdx.x * blockDim.x + threadIdx.x;
    if (e >= NB * 784 * 64) return;
    int c  = e & 63;
    int hw = (e >> 6) % 784;
    int b  = e / (784 * 64);
    int h = hw / 28, wq = hw % 28;
    float acc = bias[c];
#pragma unroll
    for (int i = 0; i < 3; i++) {
        int hh = h + i - 1;
        if (hh < 0 || hh >= 28) continue;
#pragma unroll
        for (int j = 0; j < 3; j++) {
            int ww = wq + j - 1;
            if (ww < 0 || ww >= 28) continue;
            acc = fmaf(qkvt[((size_t)b * 784 + hh * 28 + ww) * 192 + 128 + c],
                       w[c * 9 + i * 3 + j], acc);
        }
    }
    float v = ao[e] + acc;
    float hh2 = f2tf32f(v);
    size_t idx = aperm(b * 784 + hw, c, 64);
    aoh[idx] = hh2;
    aol[idx] = f2tf32f(v - hh2);
}

// ============================================================================
extern "C" void kernel_launch(void* const* d_in, const int* in_sizes, int n_in,
                              void* d_out, int out_size) {
    const float* x        = (const float*)d_in[0];
    const float* n1g      = (const float*)d_in[1];
    const float* n1b      = (const float*)d_in[2];
    const float* qkv_w    = (const float*)d_in[3];
    const float* proj_w   = (const float*)d_in[4];
    const float* proj_b   = (const float*)d_in[5];
    const float* n2g      = (const float*)d_in[6];
    const float* n2b      = (const float*)d_in[7];
    const float* fc1_w    = (const float*)d_in[8];
    const float* fc1_b    = (const float*)d_in[9];
    const float* fc2_w    = (const float*)d_in[10];
    const float* fc2_b    = (const float*)d_in[11];
    const float* bfqkv_w  = (const float*)d_in[12];
    const float* bfqkv_b  = (const float*)d_in[13];
    const float* bflepe_w = (const float*)d_in[14];
    const float* bflepe_b = (const float*)d_in[15];
    const float* bfout_w  = (const float*)d_in[16];
    const float* bfout_b  = (const float*)d_in[17];
    float* out = (float*)d_out;

    float *p_hh, *p_hl, *p_qkv, *p_aoh, *p_aol, *p_o, *p_xr, *p_h2, *p_mid;
    float *p_xTh, *p_xTl, *p_bfqkv, *p_bfao, *p_bfaoh, *p_bfaol, *p_bf2;
    float4 *p_qwp, *p_pwp, *p_bfqwp, *p_bfowp, *p_fc1wp, *p_fc2wp;
    float *p_qr, *p_kr, *p_ar;
    int* p_idx;
    cudaGetSymbolAddress((void**)&p_hh,    g_h_hi);
    cudaGetSymbolAddress((void**)&p_hl,    g_h_lo);
    cudaGetSymbolAddress((void**)&p_qkv,   g_qkv);
    cudaGetSymbolAddress((void**)&p_aoh,   g_ao_hi);
    cudaGetSymbolAddress((void**)&p_aol,   g_ao_lo);
    cudaGetSymbolAddress((void**)&p_o,     g_o);
    cudaGetSymbolAddress((void**)&p_xr,    g_xr);
    cudaGetSymbolAddress((void**)&p_h2,    g_h2);
    cudaGetSymbolAddress((void**)&p_mid,   g_mid);
    cudaGetSymbolAddress((void**)&p_xTh,   g_xT_hi);
    cudaGetSymbolAddress((void**)&p_xTl,   g_xT_lo);
    cudaGetSymbolAddress((void**)&p_bfqkv, g_bfqkv);
    cudaGetSymbolAddress((void**)&p_bfao,  g_bfao);
    cudaGetSymbolAddress((void**)&p_bfaoh, g_bfao_hi);
    cudaGetSymbolAddress((void**)&p_bfaol, g_bfao_lo);
    cudaGetSymbolAddress((void**)&p_bf2,   g_bf2);
    cudaGetSymbolAddress((void**)&p_qwp,   g_qwp);
    cudaGetSymbolAddress((void**)&p_pwp,   g_pwp);
    cudaGetSymbolAddress((void**)&p_bfqwp, g_bfqwp);
    cudaGetSymbolAddress((void**)&p_bfowp, g_bfowp);
    cudaGetSymbolAddress((void**)&p_fc1wp, g_fc1wp);
    cudaGetSymbolAddress((void**)&p_fc2wp, g_fc2wp);
    cudaGetSymbolAddress((void**)&p_qr,    g_qr);
    cudaGetSymbolAddress((void**)&p_kr,    g_kr);
    cudaGetSymbolAddress((void**)&p_ar,    g_ar);
    cudaGetSymbolAddress((void**)&p_idx,   g_topk);

    cudaFuncSetAttribute(attn_kernel, cudaFuncAttributeMaxDynamicSharedMemorySize, ATTN_SMEM);
    cudaFuncSetAttribute(gemm3v, cudaFuncAttributeMaxDynamicSharedMemorySize, GS3V);
    cudaFuncSetAttribute(gemm1v, cudaFuncAttributeMaxDynamicSharedMemorySize, GS1V);

    // Second stream + fork/join events. Created once on the first call (the
    // correctness run, which is NOT captured); reused identically every call
    // so the enqueued work is deterministic and graph-capturable.
    static cudaStream_t s2 = nullptr;
    static cudaEvent_t evA = nullptr, evB = nullptr, evC = nullptr, evD = nullptr;
    if (s2 == nullptr) {
        cudaStreamCreateWithFlags(&s2, cudaStreamNonBlocking);
        cudaEventCreateWithFlags(&evA, cudaEventDisableTiming);
        cudaEventCreateWithFlags(&evB, cudaEventDisableTiming);
        cudaEventCreateWithFlags(&evC, cudaEventDisableTiming);
        cudaEventCreateWithFlags(&evD, cudaEventDisableTiming);
    }

    // ---- fork #1: non-qkv weight packs overlap ln+qkv gemm ----
    cudaEventRecord(evA, 0);
    cudaStreamWaitEvent(s2, evA, 0);

    bpack3 <<<(98 * 2352 * 4 + 255) / 256, 256>>>(qkv_w, p_qwp, CDIM, 3 * CDIM);
    ln_split_kernel<<<NROW, 256>>>(x, n1g, n1b, p_hh, p_hl);

    bpack3 <<<(98 * 784 * 4 + 255) / 256, 256, 0, s2>>>(proj_w, p_pwp, CDIM, CDIM);
    bpack3t<<<(8 * 192 * 4 + 255) / 256, 256, 0, s2>>>(bfqkv_w, p_bfqwp, 64, 192);
    bpack3t<<<(8 * 64 * 4 + 255) / 256, 256, 0, s2>>>(bfout_w, p_bfowp, 64, 64);
    bpack1 <<<(49 * 3136 * 4 + 255) / 256, 256, 0, s2>>>(fc1_w, p_fc1wp, CDIM, HID);
    bpack1 <<<(196 * 784 * 4 + 255) / 256, 256, 0, s2>>>(fc2_w, p_fc2wp, HID, CDIM);
    cudaEventRecord(evB, s2);

    gemm3v<<<dim3(19, 64), 256, GS3V>>>(p_hh, p_hl, p_qwp, nullptr, nullptr,
                                        p_qkv, nullptr, nullptr, NROW, 3 * CDIM, CDIM);
    attn_kernel<<<NB * NHD, 256, ATTN_SMEM>>>(p_qkv, p_aoh, p_aol);

    // join #1: proj gemm needs p_pwp from s2
    cudaStreamWaitEvent(0, evB, 0);
    gemm3v<<<dim3(7, 64), 256, GS3V>>>(p_aoh, p_aol, p_pwp, proj_b, nullptr,
                                       p_o, p_xr, x, NROW, CDIM, CDIM);

    // ---- fork #2: BiFormer branch on s2, MLP on main stream ----
    cudaEventRecord(evC, 0);
    cudaStreamWaitEvent(s2, evC, 0);

    transpose_split_kernel<<<dim3(25, 2, NB), dim3(32, 32), 0, s2>>>(p_o, p_xTh, p_xTl);
    gemm3v<<<dim3(2, M2 / 128), 256, GS3V, s2>>>(p_xTh, p_xTl, p_bfqwp, bfqkv_b, nullptr,
                                                 p_bfqkv, nullptr, nullptr, M2, 192, 64);
    bf_pool_kernel<<<NB * 49, 128, 0, s2>>>(p_bfqkv, p_qr, p_kr);
    bf_ar_kernel<<<(NB * 49 * 49 + 255) / 256, 256, 0, s2>>>(p_qr, p_kr, p_ar);
    bf_topk_kernel<<<(NB * 49 + 255) / 256, 256, 0, s2>>>(p_ar, p_idx);
    bf_attn_kernel<<<NB * 8 * 49, 128, 0, s2>>>(p_bfqkv, p_idx, p_bfao);
    bf_lepe_split_kernel<<<(NB * 784 * 64 + 255) / 256, 256, 0, s2>>>(p_bfqkv, bflepe_w,
                                                                      bflepe_b, p_bfao,
                                                                      p_bfaoh, p_bfaol);
    gemm3v<<<dim3(1, M2 / 128), 256, GS3V, s2>>>(p_bfaoh, p_bfaol, p_bfowp, bfout_b, nullptr,
                                                 p_bf2, nullptr, nullptr, M2, 64, 64);
    transpose_kernel<<<dim3(2, 25, NB), dim3(32, 32), 0, s2>>>(p_bf2, out + OUT1, 784, 64);
    cudaEventRecord(evD, s2);

    ln_kernel<<<NROW, 256>>>(p_xr, n2g, n2b, p_h2);
    gemm1v<<<dim3(25, 64), 256, GS1V>>>(p_h2, p_fc1wp, fc1_b, nullptr, p_mid,
                                        NROW, HID, CDIM, 1, 1);
    gemm1v<<<dim3(7, 64), 256, GS1V>>>(p_mid, p_fc2wp, fc2_b, p_xr, out,
                                       NROW, CDIM, HID, 0, 0);

    // join #2: graph leaf depends on both branches
    cudaStreamWaitEvent(0, evD, 0);
}

// round 12
// speedup vs baseline: 1.1396x; 1.0714x over previous
#include <cuda_runtime.h>
#include <math.h>
#include <stdint.h>

#define NB    128
#define NTOKN 64
#define CDIM  784
#define NHD   8
#define HD    98
#define HID   3136
#define NROW  (NB*NTOKN)
#define M2    (NB*784)
#define OUT1  (NROW*CDIM)

// ---------------- scratch (device globals; no allocation allowed) ----------
__device__ float  g_h_hi  [NROW*CDIM];     // aperm
__device__ float  g_h_lo  [NROW*CDIM];     // aperm
__device__ float  g_qkv   [NROW*3*CDIM];
__device__ float  g_ao_hi [NROW*CDIM];     // aperm
__device__ float  g_ao_lo [NROW*CDIM];     // aperm
__device__ float  g_o     [NROW*CDIM];
__device__ float  g_xr    [NROW*CDIM];
__device__ float  g_h2    [NROW*CDIM];     // aperm
__device__ float  g_mid   [NROW*HID];      // aperm
__device__ float  g_xT_hi [M2*64];         // aperm
__device__ float  g_xT_lo [M2*64];         // aperm
__device__ float  g_bfqkv [M2*192];
__device__ float  g_bfao  [M2*64];
__device__ float  g_bfao_hi[M2*64];        // aperm
__device__ float  g_bfao_lo[M2*64];        // aperm
__device__ float  g_bf2   [M2*64];
__device__ float4 g_qwp   [(CDIM/8)*(3*CDIM)*4];
__device__ float4 g_pwp   [(CDIM/8)*CDIM*4];
__device__ float4 g_bfqwp [(64/8)*192*4];
__device__ float4 g_bfowp [(64/8)*64*4];
__device__ float4 g_fc1wp [(CDIM/16)*HID*4];
__device__ float4 g_fc2wp [(HID/16)*CDIM*4];
__device__ float  g_qr    [NB*49*64];
__device__ float  g_kr    [NB*49*64];
__device__ float  g_ar    [NB*49*49];
__device__ int    g_topk  [NB*49*4];

// ---------------- helpers ----------------------------------------------------
__device__ __forceinline__ float f2tf32f(float x) {
    unsigned r;
    asm("cvt.rna.tf32.f32 %0, %1;" : "=r"(r) : "f"(x));
    return __uint_as_float(r);
}

// pack two f32 into bf16x2. Convention is uniform across A and B fragments,
// so the within-register half ordering cancels (k-slot relabeling).
__device__ __forceinline__ unsigned packbf(float p, float q) {
    unsigned r;
    asm("cvt.rn.bf16x2.f32 %0, %1, %2;" : "=r"(r) : "f"(q), "f"(p));
    return r;
}

// fragment-order A permutation: 16-row x 8-k blocks of 128 floats.
__device__ __forceinline__ size_t aperm(int row, int k, int K) {
    return ((size_t)((row >> 4) * (K >> 3) + (k >> 3)) << 7)
         + (size_t)((((row & 7) << 2) | (k & 3)) << 2)
         + (size_t)(((k & 4) >> 1) | ((row & 8) >> 3));
}

__device__ __forceinline__ void mma_tf32(float& d0, float& d1, float& d2, float& d3,
                                         unsigned a0, unsigned a1, unsigned a2, unsigned a3,
                                         unsigned b0, unsigned b1) {
    asm volatile(
        "mma.sync.aligned.m16n8k8.row.col.f32.tf32.tf32.f32 "
        "{%0,%1,%2,%3}, {%4,%5,%6,%7}, {%8,%9}, {%0,%1,%2,%3};\n"
        : "+f"(d0), "+f"(d1), "+f"(d2), "+f"(d3)
        : "r"(a0), "r"(a1), "r"(a2), "r"(a3), "r"(b0), "r"(b1));
}

__device__ __forceinline__ void mma_bf16(float& d0, float& d1, float& d2, float& d3,
                                         unsigned a0, unsigned a1, unsigned a2, unsigned a3,
                                         unsigned b0, unsigned b1) {
    asm volatile(
        "mma.sync.aligned.m16n8k16.row.col.f32.bf16.bf16.f32 "
        "{%0,%1,%2,%3}, {%4,%5,%6,%7}, {%8,%9}, {%0,%1,%2,%3};\n"
        : "+f"(d0), "+f"(d1), "+f"(d2), "+f"(d3)
        : "r"(a0), "r"(a1), "r"(a2), "r"(a3), "r"(b0), "r"(b1));
}

__device__ __forceinline__ void cp16(void* dst, const void* src, bool pred) {
    unsigned daddr = (unsigned)__cvta_generic_to_shared(dst);
    int sz = pred ? 16 : 0;
    asm volatile("cp.async.cg.shared.global [%0], [%1], 16, %2;\n"
                 :: "r"(daddr), "l"(src), "r"(sz));
}
#define CP_COMMIT() asm volatile("cp.async.commit_group;\n" ::: "memory")
#define CP_WAIT2()  asm volatile("cp.async.wait_group 2;\n" ::: "memory")

// ---------------- weight packs -----------------------------------------------
__global__ void bpack3(const float* __restrict__ w, float4* __restrict__ out,
                       int K, int N) {
    int q = blockIdx.x * blockDim.x + threadIdx.x;
    int total = (K >> 3) * N * 4;
    if (q >= total) return;
    int c = q & 3, n = (q >> 2) % N, k8 = q / (4 * N);
    float v0 = w[(size_t)(k8 * 8 + c) * N + n];
    float v1 = w[(size_t)(k8 * 8 + c + 4) * N + n];
    float h0 = f2tf32f(v0), h1 = f2tf32f(v1);
    out[q] = make_float4(h0, f2tf32f(v0 - h0), h1, f2tf32f(v1 - h1));
}
__global__ void bpack3t(const float* __restrict__ w, float4* __restrict__ out,
                        int K, int N) {
    int q = blockIdx.x * blockDim.x + threadIdx.x;
    int total = (K >> 3) * N * 4;
    if (q >= total) return;
    int c = q & 3, n = (q >> 2) % N, k8 = q / (4 * N);
    float v0 = w[(size_t)n * K + k8 * 8 + c];
    float v1 = w[(size_t)n * K + k8 * 8 + c + 4];
    float h0 = f2tf32f(v0), h1 = f2tf32f(v1);
    out[q] = make_float4(h0, f2tf32f(v0 - h0), h1, f2tf32f(v1 - h1));
}
__global__ void bpack1(const float* __restrict__ w, float4* __restrict__ out,
                       int K, int N) {
    int q = blockIdx.x * blockDim.x + threadIdx.x;
    int total = (K >> 4) * N * 4;
    if (q >= total) return;
    int c = q & 3, n = (q >> 2) % N, k16 = q / (4 * N);
    const float* p = w + (size_t)(k16 * 16 + c) * N + n;
    out[q] = make_float4(f2tf32f(p[0]),
                         f2tf32f(p[(size_t)4 * N]),
                         f2tf32f(p[(size_t)8 * N]),
                         f2tf32f(p[(size_t)12 * N]));
}

// ---------------- LayerNorm, aperm rounded output ----------------------------
__global__ void ln_kernel(const float* __restrict__ x, const float* __restrict__ g,
                          const float* __restrict__ b, float* __restrict__ y) {
    int row = blockIdx.x;
    const float* xr = x + (size_t)row * CDIM;
    float s = 0.f, s2 = 0.f;
    for (int i = threadIdx.x; i < CDIM; i += blockDim.x) {
        float v = xr[i]; s += v; s2 += v * v;
    }
    for (int o = 16; o; o >>= 1) {
        s  += __shfl_xor_sync(0xffffffffu, s,  o);
        s2 += __shfl_xor_sync(0xffffffffu, s2, o);
    }
    __shared__ float sh[16], sh2[16];
    int warp = threadIdx.x >> 5, lane = threadIdx.x & 31;
    if (lane == 0) { sh[warp] = s; sh2[warp] = s2; }
    __syncthreads();
    if (threadIdx.x == 0) {
        float t = 0.f, t2 = 0.f;
        int nw = blockDim.x >> 5;
        for (int i = 0; i < nw; i++) { t += sh[i]; t2 += sh2[i]; }
        sh[0] = t; sh2[0] = t2;
    }
    __syncthreads();
    float mean = sh[0] * (1.0f / CDIM);
    float var  = sh2[0] * (1.0f / CDIM) - mean * mean;
    float rinv = rsqrtf(var + 1e-5f);
    for (int i = threadIdx.x; i < CDIM; i += blockDim.x)
        y[aperm(row, i, CDIM)] = f2tf32f((xr[i] - mean) * rinv * g[i] + b[i]);
}

// ---------------- LayerNorm, aperm split output ------------------------------
__global__ void ln_split_kernel(const float* __restrict__ x, const float* __restrict__ g,
                                const float* __restrict__ b,
                                float* __restrict__ yh, float* __restrict__ yl) {
    int row = blockIdx.x;
    const float* xr = x + (size_t)row * CDIM;
    float s = 0.f, s2 = 0.f;
    for (int i = threadIdx.x; i < CDIM; i += blockDim.x) {
        float v = xr[i]; s += v; s2 += v * v;
    }
    for (int o = 16; o; o >>= 1) {
        s  += __shfl_xor_sync(0xffffffffu, s,  o);
        s2 += __shfl_xor_sync(0xffffffffu, s2, o);
    }
    __shared__ float sh[16], sh2[16];
    int warp = threadIdx.x >> 5, lane = threadIdx.x & 31;
    if (lane == 0) { sh[warp] = s; sh2[warp] = s2; }
    __syncthreads();
    if (threadIdx.x == 0) {
        float t = 0.f, t2 = 0.f;
        int nw = blockDim.x >> 5;
        for (int i = 0; i < nw; i++) { t += sh[i]; t2 += sh2[i]; }
        sh[0] = t; sh2[0] = t2;
    }
    __syncthreads();
    float mean = sh[0] * (1.0f / CDIM);
    float var  = sh2[0] * (1.0f / CDIM) - mean * mean;
    float rinv = rsqrtf(var + 1e-5f);
    for (int i = threadIdx.x; i < CDIM; i += blockDim.x) {
        float v = (xr[i] - mean) * rinv * g[i] + b[i];
        float h = f2tf32f(v);
        size_t idx = aperm(row, i, CDIM);
        yh[idx] = h;
        yl[idx] = f2tf32f(v - h);
    }
}

// ---- 3-term GEMM: tf32 main + bf16 corrections, fragment-permuted, 3-stage --
#define S3STG 8192
#define GS3V  (3*S3STG*4)
__global__ void __launch_bounds__(256, 2)
gemm3v(const float* __restrict__ Ah, const float* __restrict__ Al,
       const float4* __restrict__ Bq,
       const float* __restrict__ bias, const float* __restrict__ res,
       float* __restrict__ C, float* __restrict__ C2, const float* __restrict__ res2,
       int M, int N, int K) {
    extern __shared__ float sm[];
    int tid = threadIdx.x, warp = tid >> 5, lane = tid & 31;
    int wm = warp & 1, wn = warp >> 1;
    int row0 = blockIdx.y * 128, col0 = blockIdx.x * 128;
    int r = lane >> 2, c = lane & 3;
    int nk = K >> 4, K8 = K >> 3;

    float acc[4][4][4];
#pragma unroll
    for (int i = 0; i < 4; i++)
#pragma unroll
        for (int j = 0; j < 4; j++)
#pragma unroll
            for (int q = 0; q < 4; q++) acc[i][j][q] = 0.f;

#define P3(SIDX, KT) do { \
        float* sa = sm + (SIDX) * S3STG; \
        for (int q = tid; q < 512; q += 256) { \
            int b_ = q >> 6, ks_ = (q >> 5) & 1, ln_ = q & 31; \
            size_t g_ = ((size_t)((row0 >> 4) + b_) * K8 + (KT) * 2 + ks_) * 128 + ln_ * 4; \
            cp16(sa + (b_ * 2 + ks_) * 128 + ln_ * 4, Ah + g_, true); \
            cp16(sa + 2048 + (b_ * 2 + ks_) * 128 + ln_ * 4, Al + g_, true); \
        } \
        for (int q = tid; q < 1024; q += 256) { \
            int ks_ = q >> 9, rem_ = q & 511, nl_ = rem_ >> 2, cc_ = rem_ & 3; \
            int n_ = col0 + nl_; \
            size_t g_ = ((size_t)((KT) * 2 + ks_) * N + n_) * 4 + cc_; \
            cp16(sa + 4096 + q * 4, Bq + g_, n_ < N); \
        } \
    } while (0)

    P3(0, 0); CP_COMMIT();
    if (nk > 1) P3(1, 1);
    CP_COMMIT();
    if (nk > 2) P3(2, 2);
    CP_COMMIT();

    for (int kt = 0; kt < nk; kt++) {
        CP_WAIT2();
        __syncthreads();
        int s = kt % 3;
        float* sa = sm + s * S3STG;

        // B fragments for both k-halves of the K=16 slab
        float4 bq0[4], bq1[4];
        unsigned bh16[4][2], bl16[4][2];
#pragma unroll
        for (int nt = 0; nt < 4; nt++) {
            int nl = wn * 32 + nt * 8 + r;
            bq0[nt] = *(const float4*)(sa + 4096 + ((0 * 128 + nl) * 4 + c) * 4);
            bq1[nt] = *(const float4*)(sa + 4096 + ((1 * 128 + nl) * 4 + c) * 4);
            bh16[nt][0] = packbf(bq0[nt].x, bq0[nt].z);
            bh16[nt][1] = packbf(bq1[nt].x, bq1[nt].z);
            bl16[nt][0] = packbf(bq0[nt].y, bq0[nt].w);
            bl16[nt][1] = packbf(bq1[nt].y, bq1[nt].w);
        }

#pragma unroll
        for (int mt = 0; mt < 4; mt++) {
            int off0 = ((wm * 4 + mt) * 2 + 0) * 128 + lane * 4;
            int off1 = ((wm * 4 + mt) * 2 + 1) * 128 + lane * 4;
            float4 ah0 = *(const float4*)(sa + off0);
            float4 ah1 = *(const float4*)(sa + off1);
            float4 al0 = *(const float4*)(sa + 2048 + off0);
            float4 al1 = *(const float4*)(sa + 2048 + off1);
            unsigned ahb0 = packbf(ah0.x, ah0.z), ahb1 = packbf(ah0.y, ah0.w);
            unsigned ahb2 = packbf(ah1.x, ah1.z), ahb3 = packbf(ah1.y, ah1.w);
            unsigned alb0 = packbf(al0.x, al0.z), alb1 = packbf(al0.y, al0.w);
            unsigned alb2 = packbf(al1.x, al1.z), alb3 = packbf(al1.y, al1.w);
            unsigned a00 = __float_as_uint(ah0.x), a01 = __float_as_uint(ah0.y);
            unsigned a02 = __float_as_uint(ah0.z), a03 = __float_as_uint(ah0.w);
            unsigned a10 = __float_as_uint(ah1.x), a11 = __float_as_uint(ah1.y);
            unsigned a12 = __float_as_uint(ah1.z), a13 = __float_as_uint(ah1.w);
#pragma unroll
            for (int nt = 0; nt < 4; nt++) {
                // tf32 main term (ah x bh), two K=8 steps
                mma_tf32(acc[mt][nt][0], acc[mt][nt][1], acc[mt][nt][2], acc[mt][nt][3],
                         a00, a01, a02, a03,
                         __float_as_uint(bq0[nt].x), __float_as_uint(bq0[nt].z));
                mma_tf32(acc[mt][nt][0], acc[mt][nt][1], acc[mt][nt][2], acc[mt][nt][3],
                         a10, a11, a12, a13,
                         __float_as_uint(bq1[nt].x), __float_as_uint(bq1[nt].z));
                // bf16 corrections: ah x bl  and  al x bh, K=16 each
                mma_bf16(acc[mt][nt][0], acc[mt][nt][1], acc[mt][nt][2], acc[mt][nt][3],
                         ahb0, ahb1, ahb2, ahb3, bl16[nt][0], bl16[nt][1]);
                mma_bf16(acc[mt][nt][0], acc[mt][nt][1], acc[mt][nt][2], acc[mt][nt][3],
                         alb0, alb1, alb2, alb3, bh16[nt][0], bh16[nt][1]);
            }
        }
        __syncthreads();
        if (kt + 3 < nk) P3(s, kt + 3);
        CP_COMMIT();
    }
#undef P3

#pragma unroll
    for (int mt = 0; mt < 4; mt++) {
        int rr0 = row0 + wm * 64 + mt * 16 + r;
#pragma unroll
        for (int nt = 0; nt < 4; nt++) {
            int cb = col0 + wn * 32 + nt * 8 + 2 * c;
#pragma unroll
            for (int half = 0; half < 2; half++) {
                int rr = rr0 + half * 8;
                float v0 = acc[mt][nt][half * 2 + 0];
                float v1 = acc[mt][nt][half * 2 + 1];
                if (bias) { if (cb < N) v0 += bias[cb]; if (cb + 1 < N) v1 += bias[cb + 1]; }
                size_t base = (size_t)rr * N + cb;
                float w0 = v0, w1 = v1;
                if (res) { if (cb < N) w0 += res[base]; if (cb + 1 < N) w1 += res[base + 1]; }
                if (cb < N)     C[base]     = w0;
                if (cb + 1 < N) C[base + 1] = w1;
                if (C2) {
                    float u0 = v0, u1 = v1;
                    if (res2) { if (cb < N) u0 += res2[base]; if (cb + 1 < N) u1 += res2[base + 1]; }
                    if (cb < N)     C2[base]     = u0;
                    if (cb + 1 < N) C2[base + 1] = u1;
                }
            }
        }
    }
}

// ---------------- 1xTF32 GEMM, fragment-permuted operands, 3-stage ----------
#define S1STG 4096
#define GS1V  (3*S1STG*4)
__global__ void __launch_bounds__(256, 2)
gemm1v(const float* __restrict__ A, const float4* __restrict__ Bq,
       const float* __restrict__ bias, const float* __restrict__ res,
       float* __restrict__ C, int M, int N, int K, int act, int permC) {
    extern __shared__ float sm[];
    int tid = threadIdx.x, warp = tid >> 5, lane = tid & 31;
    int wm = warp & 1, wn = warp >> 1;
    int row0 = blockIdx.y * 128, col0 = blockIdx.x * 128;
    int r = lane >> 2, c = lane & 3;
    int nk = K >> 4, K8 = K >> 3;

    float acc[4][4][4];
#pragma unroll
    for (int i = 0; i < 4; i++)
#pragma unroll
        for (int j = 0; j < 4; j++)
#pragma unroll
            for (int q = 0; q < 4; q++) acc[i][j][q] = 0.f;

#define P1(SIDX, KT) do { \
        float* sa = sm + (SIDX) * S1STG; \
        for (int q = tid; q < 512; q += 256) { \
            int b_ = q >> 6, ks_ = (q >> 5) & 1, ln_ = q & 31; \
            size_t g_ = ((size_t)((row0 >> 4) + b_) * K8 + (KT) * 2 + ks_) * 128 + ln_ * 4; \
            cp16(sa + (b_ * 2 + ks_) * 128 + ln_ * 4, A + g_, true); \
        } \
        for (int q = tid; q < 512; q += 256) { \
            int nl_ = q >> 2, cc_ = q & 3; \
            int n_ = col0 + nl_; \
            size_t g_ = ((size_t)(KT) * N + n_) * 4 + cc_; \
            cp16(sa + 2048 + q * 4, Bq + g_, n_ < N); \
        } \
    } while (0)

    P1(0, 0); CP_COMMIT();
    if (nk > 1) P1(1, 1);
    CP_COMMIT();
    if (nk > 2) P1(2, 2);
    CP_COMMIT();

    for (int kt = 0; kt < nk; kt++) {
        CP_WAIT2();
        __syncthreads();
        int s = kt % 3;
        float* sa = sm + s * S1STG;
        float4 bq4[4];
#pragma unroll
        for (int nt = 0; nt < 4; nt++) {
            int nl = wn * 32 + nt * 8 + r;
            bq4[nt] = *(const float4*)(sa + 2048 + (nl * 4 + c) * 4);
        }
#pragma unroll
        for (int ks = 0; ks < 2; ks++) {
            float4 a4[4];
#pragma unroll
            for (int mt = 0; mt < 4; mt++) {
                int off = ((wm * 4 + mt) * 2 + ks) * 128 + lane * 4;
                a4[mt] = *(const float4*)(sa + off);
            }
#pragma unroll
            for (int mt = 0; mt < 4; mt++) {
                unsigned a0 = __float_as_uint(a4[mt].x), a1 = __float_as_uint(a4[mt].y);
                unsigned a2 = __float_as_uint(a4[mt].z), a3 = __float_as_uint(a4[mt].w);
#pragma unroll
                for (int nt = 0; nt < 4; nt++) {
                    unsigned b0 = __float_as_uint(ks == 0 ? bq4[nt].x : bq4[nt].z);
                    unsigned b1 = __float_as_uint(ks == 0 ? bq4[nt].y : bq4[nt].w);
                    mma_tf32(acc[mt][nt][0], acc[mt][nt][1], acc[mt][nt][2], acc[mt][nt][3],
                             a0, a1, a2, a3, b0, b1);
                }
            }
        }
        __syncthreads();
        if (kt + 3 < nk) P1(s, kt + 3);
        CP_COMMIT();
    }
#undef P1

#pragma unroll
    for (int mt = 0; mt < 4; mt++) {
        int rr0 = row0 + wm * 64 + mt * 16 + r;
#pragma unroll
        for (int nt = 0; nt < 4; nt++) {
            int cb = col0 + wn * 32 + nt * 8 + 2 * c;
#pragma unroll
            for (int half = 0; half < 2; half++) {
                int rr = rr0 + half * 8;
                float v0 = acc[mt][nt][half * 2 + 0];
                float v1 = acc[mt][nt][half * 2 + 1];
                if (bias) { if (cb < N) v0 += bias[cb]; if (cb + 1 < N) v1 += bias[cb + 1]; }
                if (act == 1) {
                    v0 = f2tf32f(0.5f * v0 * (1.f + erff(v0 * 0.70710678118654752f)));
                    v1 = f2tf32f(0.5f * v1 * (1.f + erff(v1 * 0.70710678118654752f)));
                }
                size_t base = (size_t)rr * N + cb;
                if (res) { if (cb < N) v0 += res[base]; if (cb + 1 < N) v1 += res[base + 1]; }
                if (permC) {
                    if (cb < N)     C[aperm(rr, cb, N)]     = v0;
                    if (cb + 1 < N) C[aperm(rr, cb + 1, N)] = v1;
                } else {
                    if (cb < N)     C[base]     = v0;
                    if (cb + 1 < N) C[base + 1] = v1;
                }
            }
        }
    }
}

// ---------------- fused main MHA: aperm split output ------------------------
#define ATTN_SMEM ((3*64*99 + 64*64) * 4)
__global__ void attn_kernel(const float* __restrict__ qkv,
                            float* __restrict__ oh, float* __restrict__ ol) {
    extern __shared__ float smf[];
    float* Qs = smf;
    float* Ks = Qs + 64 * 99;
    float* Vs = Ks + 64 * 99;
    float* Ss = Vs + 64 * 99;
    int b = blockIdx.x >> 3;
    int h = blockIdx.x & 7;
    const float* base = qkv + (size_t)b * 64 * (3 * CDIM) + h * HD;

    for (int e = threadIdx.x; e < 64 * HD; e += blockDim.x) {
        int r = e / HD, d = e % HD;
        const float* rp = base + (size_t)r * (3 * CDIM) + d;
        Qs[r * 99 + d] = rp[0];
        Ks[r * 99 + d] = rp[CDIM];
        Vs[r * 99 + d] = rp[2 * CDIM];
    }
    __syncthreads();

    const float scale = 1.0f / sqrtf(98.0f);
    for (int e = threadIdx.x; e < 4096; e += blockDim.x) {
        int i = e >> 6, j = e & 63;
        const float* qi = Qs + i * 99;
        const float* kj = Ks + j * 99;
        float a = 0.f;
#pragma unroll
        for (int d = 0; d < HD; d++) a = fmaf(qi[d], kj[d], a);
        Ss[e] = a * scale;
    }
    __syncthreads();

    int warp = threadIdx.x >> 5, lane = threadIdx.x & 31;
    for (int i = warp; i < 64; i += 8) {
        float v0 = Ss[i * 64 + lane], v1 = Ss[i * 64 + lane + 32];
        float mx = fmaxf(v0, v1);
        for (int o = 16; o; o >>= 1) mx = fmaxf(mx, __shfl_xor_sync(0xffffffffu, mx, o));
        float e0 = __expf(v0 - mx), e1 = __expf(v1 - mx);
        float s = e0 + e1;
        for (int o = 16; o; o >>= 1) s += __shfl_xor_sync(0xffffffffu, s, o);
        float inv = 1.f / s;
        Ss[i * 64 + lane]      = e0 * inv;
        Ss[i * 64 + lane + 32] = e1 * inv;
    }
    __syncthreads();

    for (int e = threadIdx.x; e < 64 * HD; e += blockDim.x) {
        int i = e / HD, d = e % HD;
        const float* p = Ss + i * 64;
        float a = 0.f;
#pragma unroll
        for (int j = 0; j < 64; j++) a = fmaf(p[j], Vs[j * 99 + d], a);
        size_t idx = aperm(b * 64 + i, h * HD + d, CDIM);
        float hh = f2tf32f(a);
        oh[idx] = hh;
        ol[idx] = f2tf32f(a - hh);
    }
}

// ---------------- transpose with aperm split output -------------------------
__global__ void transpose_split_kernel(const float* __restrict__ in,
                                       float* __restrict__ oh, float* __restrict__ ol) {
    __shared__ float tile[32][33];
    int b = blockIdx.z;
    int r0 = blockIdx.y * 32, c0 = blockIdx.x * 32;
    const float* ib = in + (size_t)b * 64 * 784;
    int r = r0 + threadIdx.y, c = c0 + threadIdx.x;
    if (r < 64 && c < 784) tile[threadIdx.y][threadIdx.x] = ib[(size_t)r * 784 + c];
    __syncthreads();
    int rr = r0 + threadIdx.x, cc = c0 + threadIdx.y;
    if (rr < 64 && cc < 784) {
        float v = tile[threadIdx.x][threadIdx.y];
        float h = f2tf32f(v);
        size_t o = aperm(b * 784 + cc, rr, 64);
        oh[o] = h;
        ol[o] = f2tf32f(v - h);
    }
}

// ---------------- plain transpose: [bt][R][Cc] -> [bt][Cc][R] ----------------
__global__ void transpose_kernel(const float* __restrict__ in, float* __restrict__ out,
                                 int R, int Cc) {
    __shared__ float tile[32][33];
    int b = blockIdx.z;
    int r0 = blockIdx.y * 32, c0 = blockIdx.x * 32;
    const float* ib = in + (size_t)b * R * Cc;
    float* ob = out + (size_t)b * R * Cc;
    int r = r0 + threadIdx.y, c = c0 + threadIdx.x;
    if (r < R && c < Cc) tile[threadIdx.y][threadIdx.x] = ib[(size_t)r * Cc + c];
    __syncthreads();
    int rr = r0 + threadIdx.x, cc = c0 + threadIdx.y;
    if (rr < R && cc < Cc) ob[(size_t)cc * R + rr] = tile[threadIdx.x][threadIdx.y];
}

// ---------------- BiFormer: region mean-pool of q/k -------------------------
__global__ void bf_pool_kernel(const float* __restrict__ qkvt,
                               float* __restrict__ qr, float* __restrict__ kr) {
    int br = blockIdx.x;
    int b = br / 49, r = br % 49;
    int rh = r / 7, rw = r % 7;
    int tid = threadIdx.x;
    int c = tid & 63;
    int off = (tid >= 64) ? 64 : 0;
    int hw0 = (rh * 4) * 28 + rw * 4;
    float s = 0.f;
#pragma unroll
    for (int p = 0; p < 4; p++)
#pragma unroll
        for (int q = 0; q < 4; q++) {
            int hw = hw0 + p * 28 + q;
            s += qkvt[((size_t)b * 784 + hw) * 192 + off + c];
        }
    float* dst = (tid >= 64) ? kr : qr;
    dst[((size_t)b * 49 + r) * 64 + c] = s * (1.0f / 16.0f);
}

// ---------------- region affinity ---------------------------------------------
__global__ void bf_ar_kernel(const float* __restrict__ qr, const float* __restrict__ kr,
                             float* __restrict__ ar) {
    int idx = blockIdx.x * blockDim.x + threadIdx.x;
    if (idx >= NB * 49 * 49) return;
    int s = idx % 49, r = (idx / 49) % 49, b = idx / (49 * 49);
    const float* qp = qr + ((size_t)b * 49 + r) * 64;
    const float* kp = kr + ((size_t)b * 49 + s) * 64;
    float a = 0.f;
#pragma unroll
    for (int c = 0; c < 64; c++) a = fmaf(qp[c], kp[c], a);
    ar[idx] = a;
}

// ---------------- top-4 per (b, r) -------------------------------------------
__global__ void bf_topk_kernel(const float* __restrict__ ar, int* __restrict__ idx) {
    int t = blockIdx.x * blockDim.x + threadIdx.x;
    if (t >= NB * 49) return;
    float v[49];
    const float* row = ar + (size_t)t * 49;
#pragma unroll
    for (int s = 0; s < 49; s++) v[s] = row[s];
    for (int k = 0; k < 4; k++) {
        float best = -3.4e38f; int bi = 0;
        for (int s = 0; s < 49; s++)
            if (v[s] > best) { best = v[s]; bi = s; }
        idx[t * 4 + k] = bi;
        v[bi] = -3.4e38f;
    }
}

// ---------------- BiFormer region attention ----------------------------------
__global__ void bf_attn_kernel(const float* __restrict__ qkvt, const int* __restrict__ idx,
                               float* __restrict__ ao) {
    __shared__ float Qs[16][8], Ks[64][9], Vs[64][9], S[16][64];
    __shared__ int sreg[4];
    int r = blockIdx.x % 49;
    int m = (blockIdx.x / 49) & 7;
    int b = blockIdx.x / (49 * 8);
    int tid = threadIdx.x;
    int rh = r / 7, rw = r % 7;

    if (tid < 4) sreg[tid] = idx[((size_t)b * 49 + r) * 4 + tid];
    {
        int p = tid >> 3, d = tid & 7;
        int hw = (rh * 4 + (p >> 2)) * 28 + rw * 4 + (p & 3);
        Qs[p][d] = qkvt[((size_t)b * 784 + hw) * 192 + m * 8 + d];
    }
    __syncthreads();

    for (int e = tid; e < 512; e += 128) {
        int slot = e >> 3, d = e & 7;
        int t = slot >> 4, s = slot & 15;
        int sr = sreg[t];
        int hw = ((sr / 7) * 4 + (s >> 2)) * 28 + (sr % 7) * 4 + (s & 3);
        const float* p = qkvt + ((size_t)b * 784 + hw) * 192 + m * 8 + d;
        Ks[slot][d] = p[64];
        Vs[slot][d] = p[128];
    }
    __syncthreads();

    for (int e = tid; e < 1024; e += 128) {
        int i = e >> 6, j = e & 63;
        float a = 0.f;
#pragma unroll
        for (int d = 0; d < 8; d++) a = fmaf(Qs[i][d], Ks[j][d], a);
        S[i][j] = a * 0.125f;
    }
    __syncthreads();

    int warp = tid >> 5, lane = tid & 31;
    for (int i = warp; i < 16; i += 4) {
        float v0 = S[i][lane], v1 = S[i][lane + 32];
        float mx = fmaxf(v0, v1);
        for (int o = 16; o; o >>= 1) mx = fmaxf(mx, __shfl_xor_sync(0xffffffffu, mx, o));
        float e0 = __expf(v0 - mx), e1 = __expf(v1 - mx);
        float s = e0 + e1;
        for (int o = 16; o; o >>= 1) s += __shfl_xor_sync(0xffffffffu, s, o);
        float inv = 1.f / s;
        S[i][lane] = e0 * inv;
        S[i][lane + 32] = e1 * inv;
    }
    __syncthreads();

    {
        int i = tid >> 3, d = tid & 7;
        float a = 0.f;
#pragma unroll
        for (int j = 0; j < 64; j++) a = fmaf(S[i][j], Vs[j][d], a);
        int hw = (rh * 4 + (i >> 2)) * 28 + rw * 4 + (i & 3);
        ao[((size_t)b * 784 + hw) * 64 + m * 8 + d] = a;
    }
}

// ---------------- LePE: adds 3x3 dw conv to ao, writes aperm split ----------
__global__ void bf_lepe_split_kernel(const float* __restrict__ qkvt,
                                     const float* __restrict__ w,
                                     const float* __restrict__ bias,
                                     const float* __restrict__ ao,
                                     float* __restrict__ aoh, float* __restrict__ aol) {
    int e = blockIdx.x * blockDim.x + threadIdx.x;
    if (e >= NB * 784 * 64) return;
    int c  = e & 63;
    int hw = (e >> 6) % 784;
    int b  = e / (784 * 64);
    int h = hw / 28, wq = hw % 28;
    float acc = bias[c];
#pragma unroll
    for (int i = 0; i < 3; i++) {
        int hh = h + i - 1;
        if (hh < 0 || hh >= 28) continue;
#pragma unroll
        for (int j = 0; j < 3; j++) {
            int ww = wq + j - 1;
            if (ww < 0 || ww >= 28) continue;
            acc = fmaf(qkvt[((size_t)b * 784 + hh * 28 + ww) * 192 + 128 + c],
                       w[c * 9 + i * 3 + j], acc);
        }
    }
    float v = ao[e] + acc;
    float hh2 = f2tf32f(v);
    size_t idx = aperm(b * 784 + hw, c, 64);
    aoh[idx] = hh2;
    aol[idx] = f2tf32f(v - hh2);
}

// ============================================================================
extern "C" void kernel_launch(void* const* d_in, const int* in_sizes, int n_in,
                              void* d_out, int out_size) {
    const float* x        = (const float*)d_in[0];
    const float* n1g      = (const float*)d_in[1];
    const float* n1b      = (const float*)d_in[2];
    const float* qkv_w    = (const float*)d_in[3];
    const float* proj_w   = (const float*)d_in[4];
    const float* proj_b   = (const float*)d_in[5];
    const float* n2g      = (const float*)d_in[6];
    const float* n2b      = (const float*)d_in[7];
    const float* fc1_w    = (const float*)d_in[8];
    const float* fc1_b    = (const float*)d_in[9];
    const float* fc2_w    = (const float*)d_in[10];
    const float* fc2_b    = (const float*)d_in[11];
    const float* bfqkv_w  = (const float*)d_in[12];
    const float* bfqkv_b  = (const float*)d_in[13];
    const float* bflepe_w = (const float*)d_in[14];
    const float* bflepe_b = (const float*)d_in[15];
    const float* bfout_w  = (const float*)d_in[16];
    const float* bfout_b  = (const float*)d_in[17];
    float* out = (float*)d_out;

    float *p_hh, *p_hl, *p_qkv, *p_aoh, *p_aol, *p_o, *p_xr, *p_h2, *p_mid;
    float *p_xTh, *p_xTl, *p_bfqkv, *p_bfao, *p_bfaoh, *p_bfaol, *p_bf2;
    float4 *p_qwp, *p_pwp, *p_bfqwp, *p_bfowp, *p_fc1wp, *p_fc2wp;
    float *p_qr, *p_kr, *p_ar;
    int* p_idx;
    cudaGetSymbolAddress((void**)&p_hh,    g_h_hi);
    cudaGetSymbolAddress((void**)&p_hl,    g_h_lo);
    cudaGetSymbolAddress((void**)&p_qkv,   g_qkv);
    cudaGetSymbolAddress((void**)&p_aoh,   g_ao_hi);
    cudaGetSymbolAddress((void**)&p_aol,   g_ao_lo);
    cudaGetSymbolAddress((void**)&p_o,     g_o);
    cudaGetSymbolAddress((void**)&p_xr,    g_xr);
    cudaGetSymbolAddress((void**)&p_h2,    g_h2);
    cudaGetSymbolAddress((void**)&p_mid,   g_mid);
    cudaGetSymbolAddress((void**)&p_xTh,   g_xT_hi);
    cudaGetSymbolAddress((void**)&p_xTl,   g_xT_lo);
    cudaGetSymbolAddress((void**)&p_bfqkv, g_bfqkv);
    cudaGetSymbolAddress((void**)&p_bfao,  g_bfao);
    cudaGetSymbolAddress((void**)&p_bfaoh, g_bfao_hi);
    cudaGetSymbolAddress((void**)&p_bfaol, g_bfao_lo);
    cudaGetSymbolAddress((void**)&p_bf2,   g_bf2);
    cudaGetSymbolAddress((void**)&p_qwp,   g_qwp);
    cudaGetSymbolAddress((void**)&p_pwp,   g_pwp);
    cudaGetSymbolAddress((void**)&p_bfqwp, g_bfqwp);
    cudaGetSymbolAddress((void**)&p_bfowp, g_bfowp);
    cudaGetSymbolAddress((void**)&p_fc1wp, g_fc1wp);
    cudaGetSymbolAddress((void**)&p_fc2wp, g_fc2wp);
    cudaGetSymbolAddress((void**)&p_qr,    g_qr);
    cudaGetSymbolAddress((void**)&p_kr,    g_kr);
    cudaGetSymbolAddress((void**)&p_ar,    g_ar);
    cudaGetSymbolAddress((void**)&p_idx,   g_topk);

    cudaFuncSetAttribute(attn_kernel, cudaFuncAttributeMaxDynamicSharedMemorySize, ATTN_SMEM);
    cudaFuncSetAttribute(gemm3v, cudaFuncAttributeMaxDynamicSharedMemorySize, GS3V);
    cudaFuncSetAttribute(gemm1v, cudaFuncAttributeMaxDynamicSharedMemorySize, GS1V);

    static cudaStream_t s2 = nullptr;
    static cudaEvent_t evA = nullptr, evB = nullptr, evC = nullptr, evD = nullptr;
    if (s2 == nullptr) {
        cudaStreamCreateWithFlags(&s2, cudaStreamNonBlocking);
        cudaEventCreateWithFlags(&evA, cudaEventDisableTiming);
        cudaEventCreateWithFlags(&evB, cudaEventDisableTiming);
        cudaEventCreateWithFlags(&evC, cudaEventDisableTiming);
        cudaEventCreateWithFlags(&evD, cudaEventDisableTiming);
    }

    // ---- fork #1: non-qkv weight packs overlap ln+qkv gemm ----
    cudaEventRecord(evA, 0);
    cudaStreamWaitEvent(s2, evA, 0);

    bpack3 <<<(98 * 2352 * 4 + 255) / 256, 256>>>(qkv_w, p_qwp, CDIM, 3 * CDIM);
    ln_split_kernel<<<NROW, 256>>>(x, n1g, n1b, p_hh, p_hl);

    bpack3 <<<(98 * 784 * 4 + 255) / 256, 256, 0, s2>>>(proj_w, p_pwp, CDIM, CDIM);
    bpack3t<<<(8 * 192 * 4 + 255) / 256, 256, 0, s2>>>(bfqkv_w, p_bfqwp, 64, 192);
    bpack3t<<<(8 * 64 * 4 + 255) / 256, 256, 0, s2>>>(bfout_w, p_bfowp, 64, 64);
    bpack1 <<<(49 * 3136 * 4 + 255) / 256, 256, 0, s2>>>(fc1_w, p_fc1wp, CDIM, HID);
    bpack1 <<<(196 * 784 * 4 + 255) / 256, 256, 0, s2>>>(fc2_w, p_fc2wp, HID, CDIM);
    cudaEventRecord(evB, s2);

    gemm3v<<<dim3(19, 64), 256, GS3V>>>(p_hh, p_hl, p_qwp, nullptr, nullptr,
                                        p_qkv, nullptr, nullptr, NROW, 3 * CDIM, CDIM);
    attn_kernel<<<NB * NHD, 256, ATTN_SMEM>>>(p_qkv, p_aoh, p_aol);

    cudaStreamWaitEvent(0, evB, 0);
    gemm3v<<<dim3(7, 64), 256, GS3V>>>(p_aoh, p_aol, p_pwp, proj_b, nullptr,
                                       p_o, p_xr, x, NROW, CDIM, CDIM);

    // ---- fork #2: BiFormer branch on s2, MLP on main stream ----
    cudaEventRecord(evC, 0);
    cudaStreamWaitEvent(s2, evC, 0);

    transpose_split_kernel<<<dim3(25, 2, NB), dim3(32, 32), 0, s2>>>(p_o, p_xTh, p_xTl);
    gemm3v<<<dim3(2, M2 / 128), 256, GS3V, s2>>>(p_xTh, p_xTl, p_bfqwp, bfqkv_b, nullptr,
                                                 p_bfqkv, nullptr, nullptr, M2, 192, 64);
    bf_pool_kernel<<<NB * 49, 128, 0, s2>>>(p_bfqkv, p_qr, p_kr);
    bf_ar_kernel<<<(NB * 49 * 49 + 255) / 256, 256, 0, s2>>>(p_qr, p_kr, p_ar);
    bf_topk_kernel<<<(NB * 49 + 255) / 256, 256, 0, s2>>>(p_ar, p_idx);
    bf_attn_kernel<<<NB * 8 * 49, 128, 0, s2>>>(p_bfqkv, p_idx, p_bfao);
    bf_lepe_split_kernel<<<(NB * 784 * 64 + 255) / 256, 256, 0, s2>>>(p_bfqkv, bflepe_w,
                                                                      bflepe_b, p_bfao,
                                                                      p_bfaoh, p_bfaol);
    gemm3v<<<dim3(1, M2 / 128), 256, GS3V, s2>>>(p_bfaoh, p_bfaol, p_bfowp, bfout_b, nullptr,
                                                 p_bf2, nullptr, nullptr, M2, 64, 64);
    transpose_kernel<<<dim3(2, 25, NB), dim3(32, 32), 0, s2>>>(p_bf2, out + OUT1, 784, 64);
    cudaEventRecord(evD, s2);

    ln_kernel<<<NROW, 256>>>(p_xr, n2g, n2b, p_h2);
    gemm1v<<<dim3(25, 64), 256, GS1V>>>(p_h2, p_fc1wp, fc1_b, nullptr, p_mid,
                                        NROW, HID, CDIM, 1, 1);
    gemm1v<<<dim3(7, 64), 256, GS1V>>>(p_mid, p_fc2wp, fc2_b, p_xr, out,
                                       NROW, CDIM, HID, 0, 0);

    cudaStreamWaitEvent(0, evD, 0);
}

// round 13
// speedup vs baseline: 1.1967x; 1.0501x over previous
#include <cuda_runtime.h>
#include <math.h>
#include <stdint.h>

#define NB    128
#define NTOKN 64
#define CDIM  784
#define NHD   8
#define HD    98
#define HID   3136
#define NROW  (NB*NTOKN)
#define M2    (NB*784)
#define OUT1  (NROW*CDIM)

// ---------------- scratch (device globals; no allocation allowed) ----------
__device__ float    g_h_hi  [NROW*CDIM];      // aperm f32
__device__ unsigned g_h_hb  [NROW*CDIM/2];    // bf16 pairs
__device__ unsigned g_h_lb  [NROW*CDIM/2];
__device__ float    g_qkv   [NROW*3*CDIM];
__device__ float    g_ao_hi [NROW*CDIM];
__device__ unsigned g_ao_hb [NROW*CDIM/2];
__device__ unsigned g_ao_lb [NROW*CDIM/2];
__device__ float    g_o     [NROW*CDIM];
__device__ float    g_xr    [NROW*CDIM];
__device__ float    g_h2    [NROW*CDIM];      // aperm
__device__ float    g_mid   [NROW*HID];       // aperm
__device__ float    g_xT_hi [M2*64];
__device__ unsigned g_xT_hb [M2*64/2];
__device__ unsigned g_xT_lb [M2*64/2];
__device__ float    g_bfqkv [M2*192];
__device__ float    g_bfao  [M2*64];
__device__ float    g_bfao_hi[M2*64];
__device__ unsigned g_bfao_hb[M2*64/2];
__device__ unsigned g_bfao_lb[M2*64/2];
__device__ float    g_bf2   [M2*64];
__device__ float4   g_qwpf  [(CDIM/16)*(3*CDIM)*4];
__device__ uint4    g_qwpu  [(CDIM/16)*(3*CDIM)*4];
__device__ float4   g_pwpf  [(CDIM/16)*CDIM*4];
__device__ uint4    g_pwpu  [(CDIM/16)*CDIM*4];
__device__ float4   g_bfqf  [4*192*4];
__device__ uint4    g_bfqu  [4*192*4];
__device__ float4   g_bfof  [4*64*4];
__device__ uint4    g_bfou  [4*64*4];
__device__ float4   g_fc1wp [(CDIM/16)*HID*4];
__device__ float4   g_fc2wp [(HID/16)*CDIM*4];
__device__ float    g_qr    [NB*49*64];
__device__ float    g_kr    [NB*49*64];
__device__ float    g_ar    [NB*49*49];
__device__ int      g_topk  [NB*49*4];

// ---------------- helpers ----------------------------------------------------
__device__ __forceinline__ float f2tf32f(float x) {
    unsigned r;
    asm("cvt.rna.tf32.f32 %0, %1;" : "=r"(r) : "f"(x));
    return __uint_as_float(r);
}
__device__ __forceinline__ unsigned short f2bfu(float x) {
    unsigned short u;
    asm("cvt.rn.bf16.f32 %0, %1;" : "=h"(u) : "f"(x));
    return u;
}
// pack two f32 to bf16x2: p -> low half, q -> high half
__device__ __forceinline__ unsigned packbf(float p, float q) {
    unsigned r;
    asm("cvt.rn.bf16x2.f32 %0, %1, %2;" : "=r"(r) : "f"(q), "f"(p));
    return r;
}

// fragment-order A permutation for f32 (16row x 8k blocks of 128)
__device__ __forceinline__ size_t aperm(int row, int k, int K) {
    return ((size_t)((row >> 4) * (K >> 3) + (k >> 3)) << 7)
         + (size_t)((((row & 7) << 2) | (k & 3)) << 2)
         + (size_t)(((k & 4) >> 1) | ((row & 8) >> 3));
}
// ushort index into bf16 pair arrays (16row x 16k slabs of 128 u32)
__device__ __forceinline__ size_t bfidx(int row, int k, int K) {
    size_t u = ((size_t)((row >> 4) * (K >> 4) + (k >> 4)) << 7)
             + (size_t)(((((row & 7) << 2) | (k & 3)) << 2)
                        + (((k >> 3) & 1) << 1) + ((row >> 3) & 1));
    return u * 2 + (size_t)((k >> 2) & 1);
}

__device__ __forceinline__ void mma_tf32(float& d0, float& d1, float& d2, float& d3,
                                         unsigned a0, unsigned a1, unsigned a2, unsigned a3,
                                         unsigned b0, unsigned b1) {
    asm volatile(
        "mma.sync.aligned.m16n8k8.row.col.f32.tf32.tf32.f32 "
        "{%0,%1,%2,%3}, {%4,%5,%6,%7}, {%8,%9}, {%0,%1,%2,%3};\n"
        : "+f"(d0), "+f"(d1), "+f"(d2), "+f"(d3)
        : "r"(a0), "r"(a1), "r"(a2), "r"(a3), "r"(b0), "r"(b1));
}
__device__ __forceinline__ void mma_bf16(float& d0, float& d1, float& d2, float& d3,
                                         unsigned a0, unsigned a1, unsigned a2, unsigned a3,
                                         unsigned b0, unsigned b1) {
    asm volatile(
        "mma.sync.aligned.m16n8k16.row.col.f32.bf16.bf16.f32 "
        "{%0,%1,%2,%3}, {%4,%5,%6,%7}, {%8,%9}, {%0,%1,%2,%3};\n"
        : "+f"(d0), "+f"(d1), "+f"(d2), "+f"(d3)
        : "r"(a0), "r"(a1), "r"(a2), "r"(a3), "r"(b0), "r"(b1));
}

__device__ __forceinline__ void cp16(void* dst, const void* src, bool pred) {
    unsigned daddr = (unsigned)__cvta_generic_to_shared(dst);
    int sz = pred ? 16 : 0;
    asm volatile("cp.async.cg.shared.global [%0], [%1], 16, %2;\n"
                 :: "r"(daddr), "l"(src), "r"(sz));
}
#define CP_COMMIT() asm volatile("cp.async.commit_group;\n" ::: "memory")
#define CP_WAIT2()  asm volatile("cp.async.wait_group 2;\n" ::: "memory")

// ---------------- weight packs -----------------------------------------------
// from w[K][N]: quad q = (s16*N + n)*4 + c, k = s16*16 + c + {0,4,8,12}
__global__ void bpack3(const float* __restrict__ w, float4* __restrict__ of,
                       uint4* __restrict__ ou, int K, int N) {
    int q = blockIdx.x * blockDim.x + threadIdx.x;
    int total = (K >> 4) * N * 4;
    if (q >= total) return;
    int c = q & 3, n = (q >> 2) % N, s16 = q / (4 * N);
    int k = s16 * 16 + c;
    float v0 = w[(size_t)k * N + n];
    float v1 = w[(size_t)(k + 4) * N + n];
    float v2 = w[(size_t)(k + 8) * N + n];
    float v3 = w[(size_t)(k + 12) * N + n];
    float h0 = f2tf32f(v0), h1 = f2tf32f(v1), h2 = f2tf32f(v2), h3 = f2tf32f(v3);
    float l0 = f2tf32f(v0 - h0), l1 = f2tf32f(v1 - h1);
    float l2 = f2tf32f(v2 - h2), l3 = f2tf32f(v3 - h3);
    of[q] = make_float4(h0, h1, h2, h3);
    ou[q] = make_uint4(packbf(h0, h1), packbf(h2, h3), packbf(l0, l1), packbf(l2, l3));
}
// from w[N][K] (transpose during pack)
__global__ void bpack3t(const float* __restrict__ w, float4* __restrict__ of,
                        uint4* __restrict__ ou, int K, int N) {
    int q = blockIdx.x * blockDim.x + threadIdx.x;
    int total = (K >> 4) * N * 4;
    if (q >= total) return;
    int c = q & 3, n = (q >> 2) % N, s16 = q / (4 * N);
    int k = s16 * 16 + c;
    float v0 = w[(size_t)n * K + k];
    float v1 = w[(size_t)n * K + k + 4];
    float v2 = w[(size_t)n * K + k + 8];
    float v3 = w[(size_t)n * K + k + 12];
    float h0 = f2tf32f(v0), h1 = f2tf32f(v1), h2 = f2tf32f(v2), h3 = f2tf32f(v3);
    float l0 = f2tf32f(v0 - h0), l1 = f2tf32f(v1 - h1);
    float l2 = f2tf32f(v2 - h2), l3 = f2tf32f(v3 - h3);
    of[q] = make_float4(h0, h1, h2, h3);
    ou[q] = make_uint4(packbf(h0, h1), packbf(h2, h3), packbf(l0, l1), packbf(l2, l3));
}
// 1x pack (unchanged layout)
__global__ void bpack1(const float* __restrict__ w, float4* __restrict__ out,
                       int K, int N) {
    int q = blockIdx.x * blockDim.x + threadIdx.x;
    int total = (K >> 4) * N * 4;
    if (q >= total) return;
    int c = q & 3, n = (q >> 2) % N, k16 = q / (4 * N);
    const float* p = w + (size_t)(k16 * 16 + c) * N + n;
    out[q] = make_float4(f2tf32f(p[0]),
                         f2tf32f(p[(size_t)4 * N]),
                         f2tf32f(p[(size_t)8 * N]),
                         f2tf32f(p[(size_t)12 * N]));
}

// ---------------- LayerNorm, aperm rounded output (1x path) -----------------
__global__ void ln_kernel(const float* __restrict__ x, const float* __restrict__ g,
                          const float* __restrict__ b, float* __restrict__ y) {
    int row = blockIdx.x;
    const float* xr = x + (size_t)row * CDIM;
    float s = 0.f, s2 = 0.f;
    for (int i = threadIdx.x; i < CDIM; i += blockDim.x) {
        float v = xr[i]; s += v; s2 += v * v;
    }
    for (int o = 16; o; o >>= 1) {
        s  += __shfl_xor_sync(0xffffffffu, s,  o);
        s2 += __shfl_xor_sync(0xffffffffu, s2, o);
    }
    __shared__ float sh[16], sh2[16];
    int warp = threadIdx.x >> 5, lane = threadIdx.x & 31;
    if (lane == 0) { sh[warp] = s; sh2[warp] = s2; }
    __syncthreads();
    if (threadIdx.x == 0) {
        float t = 0.f, t2 = 0.f;
        int nw = blockDim.x >> 5;
        for (int i = 0; i < nw; i++) { t += sh[i]; t2 += sh2[i]; }
        sh[0] = t; sh2[0] = t2;
    }
    __syncthreads();
    float mean = sh[0] * (1.0f / CDIM);
    float var  = sh2[0] * (1.0f / CDIM) - mean * mean;
    float rinv = rsqrtf(var + 1e-5f);
    for (int i = threadIdx.x; i < CDIM; i += blockDim.x)
        y[aperm(row, i, CDIM)] = f2tf32f((xr[i] - mean) * rinv * g[i] + b[i]);
}

// ---------------- LayerNorm, aperm f32 hi + bf16 hi/lo outputs ---------------
__global__ void ln_split_kernel(const float* __restrict__ x, const float* __restrict__ g,
                                const float* __restrict__ b, float* __restrict__ yh,
                                unsigned* __restrict__ hbw, unsigned* __restrict__ lbw) {
    int row = blockIdx.x;
    const float* xr = x + (size_t)row * CDIM;
    unsigned short* hb = (unsigned short*)hbw;
    unsigned short* lb = (unsigned short*)lbw;
    float s = 0.f, s2 = 0.f;
    for (int i = threadIdx.x; i < CDIM; i += blockDim.x) {
        float v = xr[i]; s += v; s2 += v * v;
    }
    for (int o = 16; o; o >>= 1) {
        s  += __shfl_xor_sync(0xffffffffu, s,  o);
        s2 += __shfl_xor_sync(0xffffffffu, s2, o);
    }
    __shared__ float sh[16], sh2[16];
    int warp = threadIdx.x >> 5, lane = threadIdx.x & 31;
    if (lane == 0) { sh[warp] = s; sh2[warp] = s2; }
    __syncthreads();
    if (threadIdx.x == 0) {
        float t = 0.f, t2 = 0.f;
        int nw = blockDim.x >> 5;
        for (int i = 0; i < nw; i++) { t += sh[i]; t2 += sh2[i]; }
        sh[0] = t; sh2[0] = t2;
    }
    __syncthreads();
    float mean = sh[0] * (1.0f / CDIM);
    float var  = sh2[0] * (1.0f / CDIM) - mean * mean;
    float rinv = rsqrtf(var + 1e-5f);
    for (int i = threadIdx.x; i < CDIM; i += blockDim.x) {
        float v = (xr[i] - mean) * rinv * g[i] + b[i];
        float h = f2tf32f(v);
        yh[aperm(row, i, CDIM)] = h;
        size_t bi = bfidx(row, i, CDIM);
        hb[bi] = f2bfu(h);
        lb[bi] = f2bfu(f2tf32f(v - h));
    }
}

// ---- 3-term GEMM: tf32 main + pre-packed bf16 corrections, 3-stage ---------
#define S3STG 8192
#define GS3V  (3*S3STG*4)
__global__ void __launch_bounds__(256, 2)
gemm3v(const float* __restrict__ Ah, const unsigned* __restrict__ HB,
       const unsigned* __restrict__ LB,
       const float4* __restrict__ Bf, const uint4* __restrict__ Bu,
       const float* __restrict__ bias, const float* __restrict__ res,
       float* __restrict__ C, float* __restrict__ C2, const float* __restrict__ res2,
       int M, int N, int K) {
    extern __shared__ float sm[];
    int tid = threadIdx.x, warp = tid >> 5, lane = tid & 31;
    int wm = warp & 1, wn = warp >> 1;
    int row0 = blockIdx.y * 128, col0 = blockIdx.x * 128;
    int r = lane >> 2, c = lane & 3;
    int nk = K >> 4, K8 = K >> 3, K16 = K >> 4;

    float acc[4][4][4];
#pragma unroll
    for (int i = 0; i < 4; i++)
#pragma unroll
        for (int j = 0; j < 4; j++)
#pragma unroll
            for (int q = 0; q < 4; q++) acc[i][j][q] = 0.f;

#define P3(SIDX, KT) do { \
        float* sa = sm + (SIDX) * S3STG; \
        for (int q = tid; q < 512; q += 256) { \
            int b_ = q >> 6, ks_ = (q >> 5) & 1, ln_ = q & 31; \
            size_t g_ = ((size_t)((row0 >> 4) + b_) * K8 + (KT) * 2 + ks_) * 128 + ln_ * 4; \
            cp16(sa + (b_ * 2 + ks_) * 128 + ln_ * 4, Ah + g_, true); \
        } \
        { \
            int b_ = tid >> 5, ln_ = tid & 31; \
            size_t g_ = ((size_t)((row0 >> 4) + b_) * K16 + (KT)) * 128 + ln_ * 4; \
            cp16(sa + 2048 + b_ * 128 + ln_ * 4, HB + g_, true); \
            cp16(sa + 3072 + b_ * 128 + ln_ * 4, LB + g_, true); \
        } \
        for (int q = tid; q < 512; q += 256) { \
            int nl_ = q >> 2, cc_ = q & 3; \
            int n_ = col0 + nl_; \
            size_t g_ = ((size_t)(KT) * N + n_) * 4 + cc_; \
            cp16(sa + 4096 + q * 4, Bf + g_, n_ < N); \
            cp16(sa + 6144 + q * 4, Bu + g_, n_ < N); \
        } \
    } while (0)

    P3(0, 0); CP_COMMIT();
    if (nk > 1) P3(1, 1);
    CP_COMMIT();
    if (nk > 2) P3(2, 2);
    CP_COMMIT();

    for (int kt = 0; kt < nk; kt++) {
        CP_WAIT2();
        __syncthreads();
        int s = kt % 3;
        float* sa = sm + s * S3STG;

        float4 bf4[4];
        uint4  bu4[4];
#pragma unroll
        for (int nt = 0; nt < 4; nt++) {
            int nl = wn * 32 + nt * 8 + r;
            int o = (nl * 4 + c) * 4;
            bf4[nt] = *(const float4*)(sa + 4096 + o);
            bu4[nt] = *(const uint4*)(sa + 6144 + o);
        }
#pragma unroll
        for (int mt = 0; mt < 4; mt++) {
            int off0 = ((wm * 4 + mt) * 2 + 0) * 128 + lane * 4;
            float4 ah0 = *(const float4*)(sa + off0);
            float4 ah1 = *(const float4*)(sa + off0 + 128);
            uint4 hb = *(const uint4*)(sa + 2048 + (wm * 4 + mt) * 128 + lane * 4);
            uint4 lb = *(const uint4*)(sa + 3072 + (wm * 4 + mt) * 128 + lane * 4);
            unsigned a00 = __float_as_uint(ah0.x), a01 = __float_as_uint(ah0.y);
            unsigned a02 = __float_as_uint(ah0.z), a03 = __float_as_uint(ah0.w);
            unsigned a10 = __float_as_uint(ah1.x), a11 = __float_as_uint(ah1.y);
            unsigned a12 = __float_as_uint(ah1.z), a13 = __float_as_uint(ah1.w);
#pragma unroll
            for (int nt = 0; nt < 4; nt++) {
                mma_tf32(acc[mt][nt][0], acc[mt][nt][1], acc[mt][nt][2], acc[mt][nt][3],
                         a00, a01, a02, a03,
                         __float_as_uint(bf4[nt].x), __float_as_uint(bf4[nt].y));
                mma_tf32(acc[mt][nt][0], acc[mt][nt][1], acc[mt][nt][2], acc[mt][nt][3],
                         a10, a11, a12, a13,
                         __float_as_uint(bf4[nt].z), __float_as_uint(bf4[nt].w));
                mma_bf16(acc[mt][nt][0], acc[mt][nt][1], acc[mt][nt][2], acc[mt][nt][3],
                         hb.x, hb.y, hb.z, hb.w, bu4[nt].z, bu4[nt].w);
                mma_bf16(acc[mt][nt][0], acc[mt][nt][1], acc[mt][nt][2], acc[mt][nt][3],
                         lb.x, lb.y, lb.z, lb.w, bu4[nt].x, bu4[nt].y);
            }
        }
        __syncthreads();
        if (kt + 3 < nk) P3(s, kt + 3);
        CP_COMMIT();
    }
#undef P3

#pragma unroll
    for (int mt = 0; mt < 4; mt++) {
        int rr0 = row0 + wm * 64 + mt * 16 + r;
#pragma unroll
        for (int nt = 0; nt < 4; nt++) {
            int cb = col0 + wn * 32 + nt * 8 + 2 * c;
#pragma unroll
            for (int half = 0; half < 2; half++) {
                int rr = rr0 + half * 8;
                float v0 = acc[mt][nt][half * 2 + 0];
                float v1 = acc[mt][nt][half * 2 + 1];
                if (bias) { if (cb < N) v0 += bias[cb]; if (cb + 1 < N) v1 += bias[cb + 1]; }
                size_t base = (size_t)rr * N + cb;
                float w0 = v0, w1 = v1;
                if (res) { if (cb < N) w0 += res[base]; if (cb + 1 < N) w1 += res[base + 1]; }
                if (cb < N)     C[base]     = w0;
                if (cb + 1 < N) C[base + 1] = w1;
                if (C2) {
                    float u0 = v0, u1 = v1;
                    if (res2) { if (cb < N) u0 += res2[base]; if (cb + 1 < N) u1 += res2[base + 1]; }
                    if (cb < N)     C2[base]     = u0;
                    if (cb + 1 < N) C2[base + 1] = u1;
                }
            }
        }
    }
}

// ---------------- 1xTF32 GEMM (unchanged) ------------------------------------
#define S1STG 4096
#define GS1V  (3*S1STG*4)
__global__ void __launch_bounds__(256, 2)
gemm1v(const float* __restrict__ A, const float4* __restrict__ Bq,
       const float* __restrict__ bias, const float* __restrict__ res,
       float* __restrict__ C, int M, int N, int K, int act, int permC) {
    extern __shared__ float sm[];
    int tid = threadIdx.x, warp = tid >> 5, lane = tid & 31;
    int wm = warp & 1, wn = warp >> 1;
    int row0 = blockIdx.y * 128, col0 = blockIdx.x * 128;
    int r = lane >> 2, c = lane & 3;
    int nk = K >> 4, K8 = K >> 3;

    float acc[4][4][4];
#pragma unroll
    for (int i = 0; i < 4; i++)
#pragma unroll
        for (int j = 0; j < 4; j++)
#pragma unroll
            for (int q = 0; q < 4; q++) acc[i][j][q] = 0.f;

#define P1(SIDX, KT) do { \
        float* sa = sm + (SIDX) * S1STG; \
        for (int q = tid; q < 512; q += 256) { \
            int b_ = q >> 6, ks_ = (q >> 5) & 1, ln_ = q & 31; \
            size_t g_ = ((size_t)((row0 >> 4) + b_) * K8 + (KT) * 2 + ks_) * 128 + ln_ * 4; \
            cp16(sa + (b_ * 2 + ks_) * 128 + ln_ * 4, A + g_, true); \
        } \
        for (int q = tid; q < 512; q += 256) { \
            int nl_ = q >> 2, cc_ = q & 3; \
            int n_ = col0 + nl_; \
            size_t g_ = ((size_t)(KT) * N + n_) * 4 + cc_; \
            cp16(sa + 2048 + q * 4, Bq + g_, n_ < N); \
        } \
    } while (0)

    P1(0, 0); CP_COMMIT();
    if (nk > 1) P1(1, 1);
    CP_COMMIT();
    if (nk > 2) P1(2, 2);
    CP_COMMIT();

    for (int kt = 0; kt < nk; kt++) {
        CP_WAIT2();
        __syncthreads();
        int s = kt % 3;
        float* sa = sm + s * S1STG;
        float4 bq4[4];
#pragma unroll
        for (int nt = 0; nt < 4; nt++) {
            int nl = wn * 32 + nt * 8 + r;
            bq4[nt] = *(const float4*)(sa + 2048 + (nl * 4 + c) * 4);
        }
#pragma unroll
        for (int ks = 0; ks < 2; ks++) {
            float4 a4[4];
#pragma unroll
            for (int mt = 0; mt < 4; mt++) {
                int off = ((wm * 4 + mt) * 2 + ks) * 128 + lane * 4;
                a4[mt] = *(const float4*)(sa + off);
            }
#pragma unroll
            for (int mt = 0; mt < 4; mt++) {
                unsigned a0 = __float_as_uint(a4[mt].x), a1 = __float_as_uint(a4[mt].y);
                unsigned a2 = __float_as_uint(a4[mt].z), a3 = __float_as_uint(a4[mt].w);
#pragma unroll
                for (int nt = 0; nt < 4; nt++) {
                    unsigned b0 = __float_as_uint(ks == 0 ? bq4[nt].x : bq4[nt].z);
                    unsigned b1 = __float_as_uint(ks == 0 ? bq4[nt].y : bq4[nt].w);
                    mma_tf32(acc[mt][nt][0], acc[mt][nt][1], acc[mt][nt][2], acc[mt][nt][3],
                             a0, a1, a2, a3, b0, b1);
                }
            }
        }
        __syncthreads();
        if (kt + 3 < nk) P1(s, kt + 3);
        CP_COMMIT();
    }
#undef P1

#pragma unroll
    for (int mt = 0; mt < 4; mt++) {
        int rr0 = row0 + wm * 64 + mt * 16 + r;
#pragma unroll
        for (int nt = 0; nt < 4; nt++) {
            int cb = col0 + wn * 32 + nt * 8 + 2 * c;
#pragma unroll
            for (int half = 0; half < 2; half++) {
                int rr = rr0 + half * 8;
                float v0 = acc[mt][nt][half * 2 + 0];
                float v1 = acc[mt][nt][half * 2 + 1];
                if (bias) { if (cb < N) v0 += bias[cb]; if (cb + 1 < N) v1 += bias[cb + 1]; }
                if (act == 1) {
                    v0 = f2tf32f(0.5f * v0 * (1.f + erff(v0 * 0.70710678118654752f)));
                    v1 = f2tf32f(0.5f * v1 * (1.f + erff(v1 * 0.70710678118654752f)));
                }
                size_t base = (size_t)rr * N + cb;
                if (res) { if (cb < N) v0 += res[base]; if (cb + 1 < N) v1 += res[base + 1]; }
                if (permC) {
                    if (cb < N)     C[aperm(rr, cb, N)]     = v0;
                    if (cb + 1 < N) C[aperm(rr, cb + 1, N)] = v1;
                } else {
                    if (cb < N)     C[base]     = v0;
                    if (cb + 1 < N) C[base + 1] = v1;
                }
            }
        }
    }
}

// ---------------- fused main MHA: aperm hi + bf16 halves ---------------------
#define ATTN_SMEM ((3*64*99 + 64*64) * 4)
__global__ void attn_kernel(const float* __restrict__ qkv, float* __restrict__ oh,
                            unsigned* __restrict__ hbw, unsigned* __restrict__ lbw) {
    extern __shared__ float smf[];
    float* Qs = smf;
    float* Ks = Qs + 64 * 99;
    float* Vs = Ks + 64 * 99;
    float* Ss = Vs + 64 * 99;
    unsigned short* hb = (unsigned short*)hbw;
    unsigned short* lb = (unsigned short*)lbw;
    int b = blockIdx.x >> 3;
    int h = blockIdx.x & 7;
    const float* base = qkv + (size_t)b * 64 * (3 * CDIM) + h * HD;

    for (int e = threadIdx.x; e < 64 * HD; e += blockDim.x) {
        int r = e / HD, d = e % HD;
        const float* rp = base + (size_t)r * (3 * CDIM) + d;
        Qs[r * 99 + d] = rp[0];
        Ks[r * 99 + d] = rp[CDIM];
        Vs[r * 99 + d] = rp[2 * CDIM];
    }
    __syncthreads();

    const float scale = 1.0f / sqrtf(98.0f);
    for (int e = threadIdx.x; e < 4096; e += blockDim.x) {
        int i = e >> 6, j = e & 63;
        const float* qi = Qs + i * 99;
        const float* kj = Ks + j * 99;
        float a = 0.f;
#pragma unroll
        for (int d = 0; d < HD; d++) a = fmaf(qi[d], kj[d], a);
        Ss[e] = a * scale;
    }
    __syncthreads();

    int warp = threadIdx.x >> 5, lane = threadIdx.x & 31;
    for (int i = warp; i < 64; i += 8) {
        float v0 = Ss[i * 64 + lane], v1 = Ss[i * 64 + lane + 32];
        float mx = fmaxf(v0, v1);
        for (int o = 16; o; o >>= 1) mx = fmaxf(mx, __shfl_xor_sync(0xffffffffu, mx, o));
        float e0 = __expf(v0 - mx), e1 = __expf(v1 - mx);
        float s = e0 + e1;
        for (int o = 16; o; o >>= 1) s += __shfl_xor_sync(0xffffffffu, s, o);
        float inv = 1.f / s;
        Ss[i * 64 + lane]      = e0 * inv;
        Ss[i * 64 + lane + 32] = e1 * inv;
    }
    __syncthreads();

    for (int e = threadIdx.x; e < 64 * HD; e += blockDim.x) {
        int i = e / HD, d = e % HD;
        const float* p = Ss + i * 64;
        float a = 0.f;
#pragma unroll
        for (int j = 0; j < 64; j++) a = fmaf(p[j], Vs[j * 99 + d], a);
        int row = b * 64 + i, k = h * HD + d;
        float hh = f2tf32f(a);
        oh[aperm(row, k, CDIM)] = hh;
        size_t bi = bfidx(row, k, CDIM);
        hb[bi] = f2bfu(hh);
        lb[bi] = f2bfu(f2tf32f(a - hh));
    }
}

// ---------------- transpose with aperm hi + bf16 halves ----------------------
__global__ void transpose_split_kernel(const float* __restrict__ in, float* __restrict__ oh,
                                       unsigned* __restrict__ hbw, unsigned* __restrict__ lbw) {
    __shared__ float tile[32][33];
    unsigned short* hb = (unsigned short*)hbw;
    unsigned short* lb = (unsigned short*)lbw;
    int b = blockIdx.z;
    int r0 = blockIdx.y * 32, c0 = blockIdx.x * 32;
    const float* ib = in + (size_t)b * 64 * 784;
    int r = r0 + threadIdx.y, c = c0 + threadIdx.x;
    if (r < 64 && c < 784) tile[threadIdx.y][threadIdx.x] = ib[(size_t)r * 784 + c];
    __syncthreads();
    int rr = r0 + threadIdx.x, cc = c0 + threadIdx.y;
    if (rr < 64 && cc < 784) {
        float v = tile[threadIdx.x][threadIdx.y];
        float h = f2tf32f(v);
        int row = b * 784 + cc;
        oh[aperm(row, rr, 64)] = h;
        size_t bi = bfidx(row, rr, 64);
        hb[bi] = f2bfu(h);
        lb[bi] = f2bfu(f2tf32f(v - h));
    }
}

// ---------------- plain transpose --------------------------------------------
__global__ void transpose_kernel(const float* __restrict__ in, float* __restrict__ out,
                                 int R, int Cc) {
    __shared__ float tile[32][33];
    int b = blockIdx.z;
    int r0 = blockIdx.y * 32, c0 = blockIdx.x * 32;
    const float* ib = in + (size_t)b * R * Cc;
    float* ob = out + (size_t)b * R * Cc;
    int r = r0 + threadIdx.y, c = c0 + threadIdx.x;
    if (r < R && c < Cc) tile[threadIdx.y][threadIdx.x] = ib[(size_t)r * Cc + c];
    __syncthreads();
    int rr = r0 + threadIdx.x, cc = c0 + threadIdx.y;
    if (rr < R && cc < Cc) ob[(size_t)cc * R + rr] = tile[threadIdx.x][threadIdx.y];
}

// ---------------- BiFormer: region mean-pool of q/k --------------------------
__global__ void bf_pool_kernel(const float* __restrict__ qkvt,
                               float* __restrict__ qr, float* __restrict__ kr) {
    int br = blockIdx.x;
    int b = br / 49, r = br % 49;
    int rh = r / 7, rw = r % 7;
    int tid = threadIdx.x;
    int c = tid & 63;
    int off = (tid >= 64) ? 64 : 0;
    int hw0 = (rh * 4) * 28 + rw * 4;
    float s = 0.f;
#pragma unroll
    for (int p = 0; p < 4; p++)
#pragma unroll
        for (int q = 0; q < 4; q++) {
            int hw = hw0 + p * 28 + q;
            s += qkvt[((size_t)b * 784 + hw) * 192 + off + c];
        }
    float* dst = (tid >= 64) ? kr : qr;
    dst[((size_t)b * 49 + r) * 64 + c] = s * (1.0f / 16.0f);
}

// ---------------- region affinity ---------------------------------------------
__global__ void bf_ar_kernel(const float* __restrict__ qr, const float* __restrict__ kr,
                             float* __restrict__ ar) {
    int idx = blockIdx.x * blockDim.x + threadIdx.x;
    if (idx >= NB * 49 * 49) return;
    int s = idx % 49, r = (idx / 49) % 49, b = idx / (49 * 49);
    const float* qp = qr + ((size_t)b * 49 + r) * 64;
    const float* kp = kr + ((size_t)b * 49 + s) * 64;
    float a = 0.f;
#pragma unroll
    for (int c = 0; c < 64; c++) a = fmaf(qp[c], kp[c], a);
    ar[idx] = a;
}

// ---------------- top-4 per (b, r) --------------------------------------------
__global__ void bf_topk_kernel(const float* __restrict__ ar, int* __restrict__ idx) {
    int t = blockIdx.x * blockDim.x + threadIdx.x;
    if (t >= NB * 49) return;
    float v[49];
    const float* row = ar + (size_t)t * 49;
#pragma unroll
    for (int s = 0; s < 49; s++) v[s] = row[s];
    for (int k = 0; k < 4; k++) {
        float best = -3.4e38f; int bi = 0;
        for (int s = 0; s < 49; s++)
            if (v[s] > best) { best = v[s]; bi = s; }
        idx[t * 4 + k] = bi;
        v[bi] = -3.4e38f;
    }
}

// ---------------- BiFormer region attention ------------------------------------
__global__ void bf_attn_kernel(const float* __restrict__ qkvt, const int* __restrict__ idx,
                               float* __restrict__ ao) {
    __shared__ float Qs[16][8], Ks[64][9], Vs[64][9], S[16][64];
    __shared__ int sreg[4];
    int r = blockIdx.x % 49;
    int m = (blockIdx.x / 49) & 7;
    int b = blockIdx.x / (49 * 8);
    int tid = threadIdx.x;
    int rh = r / 7, rw = r % 7;

    if (tid < 4) sreg[tid] = idx[((size_t)b * 49 + r) * 4 + tid];
    {
        int p = tid >> 3, d = tid & 7;
        int hw = (rh * 4 + (p >> 2)) * 28 + rw * 4 + (p & 3);
        Qs[p][d] = qkvt[((size_t)b * 784 + hw) * 192 + m * 8 + d];
    }
    __syncthreads();

    for (int e = tid; e < 512; e += 128) {
        int slot = e >> 3, d = e & 7;
        int t = slot >> 4, s = slot & 15;
        int sr = sreg[t];
        int hw = ((sr / 7) * 4 + (s >> 2)) * 28 + (sr % 7) * 4 + (s & 3);
        const float* p = qkvt + ((size_t)b * 784 + hw) * 192 + m * 8 + d;
        Ks[slot][d] = p[64];
        Vs[slot][d] = p[128];
    }
    __syncthreads();

    for (int e = tid; e < 1024; e += 128) {
        int i = e >> 6, j = e & 63;
        float a = 0.f;
#pragma unroll
        for (int d = 0; d < 8; d++) a = fmaf(Qs[i][d], Ks[j][d], a);
        S[i][j] = a * 0.125f;
    }
    __syncthreads();

    int warp = tid >> 5, lane = tid & 31;
    for (int i = warp; i < 16; i += 4) {
        float v0 = S[i][lane], v1 = S[i][lane + 32];
        float mx = fmaxf(v0, v1);
        for (int o = 16; o; o >>= 1) mx = fmaxf(mx, __shfl_xor_sync(0xffffffffu, mx, o));
        float e0 = __expf(v0 - mx), e1 = __expf(v1 - mx);
        float s = e0 + e1;
        for (int o = 16; o; o >>= 1) s += __shfl_xor_sync(0xffffffffu, s, o);
        float inv = 1.f / s;
        S[i][lane] = e0 * inv;
        S[i][lane + 32] = e1 * inv;
    }
    __syncthreads();

    {
        int i = tid >> 3, d = tid & 7;
        float a = 0.f;
#pragma unroll
        for (int j = 0; j < 64; j++) a = fmaf(S[i][j], Vs[j][d], a);
        int hw = (rh * 4 + (i >> 2)) * 28 + rw * 4 + (i & 3);
        ao[((size_t)b * 784 + hw) * 64 + m * 8 + d] = a;
    }
}

// ---------------- LePE: dw conv add, aperm hi + bf16 halves ------------------
__global__ void bf_lepe_split_kernel(const float* __restrict__ qkvt,
                                     const float* __restrict__ w,
                                     const float* __restrict__ bias,
                                     const float* __restrict__ ao, float* __restrict__ aoh,
                                     unsigned* __restrict__ hbw, unsigned* __restrict__ lbw) {
    int e = blockIdx.x * blockDim.x + threadIdx.x;
    if (e >= NB * 784 * 64) return;
    unsigned short* hb = (unsigned short*)hbw;
    unsigned short* lb = (unsigned short*)lbw;
    int c  = e & 63;
    int hw = (e >> 6) % 784;
    int b  = e / (784 * 64);
    int h = hw / 28, wq = hw % 28;
    float acc = bias[c];
#pragma unroll
    for (int i = 0; i < 3; i++) {
        int hh = h + i - 1;
        if (hh < 0 || hh >= 28) continue;
#pragma unroll
        for (int j = 0; j < 3; j++) {
            int ww = wq + j - 1;
            if (ww < 0 || ww >= 28) continue;
            acc = fmaf(qkvt[((size_t)b * 784 + hh * 28 + ww) * 192 + 128 + c],
                       w[c * 9 + i * 3 + j], acc);
        }
    }
    float v = ao[e] + acc;
    float hh2 = f2tf32f(v);
    int row = b * 784 + hw;
    aoh[aperm(row, c, 64)] = hh2;
    size_t bi = bfidx(row, c, 64);
    hb[bi] = f2bfu(hh2);
    lb[bi] = f2bfu(f2tf32f(v - hh2));
}

// ============================================================================
extern "C" void kernel_launch(void* const* d_in, const int* in_sizes, int n_in,
                              void* d_out, int out_size) {
    const float* x        = (const float*)d_in[0];
    const float* n1g      = (const float*)d_in[1];
    const float* n1b      = (const float*)d_in[2];
    const float* qkv_w    = (const float*)d_in[3];
    const float* proj_w   = (const float*)d_in[4];
    const float* proj_b   = (const float*)d_in[5];
    const float* n2g      = (const float*)d_in[6];
    const float* n2b      = (const float*)d_in[7];
    const float* fc1_w    = (const float*)d_in[8];
    const float* fc1_b    = (const float*)d_in[9];
    const float* fc2_w    = (const float*)d_in[10];
    const float* fc2_b    = (const float*)d_in[11];
    const float* bfqkv_w  = (const float*)d_in[12];
    const float* bfqkv_b  = (const float*)d_in[13];
    const float* bflepe_w = (const float*)d_in[14];
    const float* bflepe_b = (const float*)d_in[15];
    const float* bfout_w  = (const float*)d_in[16];
    const float* bfout_b  = (const float*)d_in[17];
    float* out = (float*)d_out;

    float *p_hh, *p_qkv, *p_aoh, *p_o, *p_xr, *p_h2, *p_mid;
    float *p_xTh, *p_bfqkv, *p_bfao, *p_bfaoh, *p_bf2;
    unsigned *p_hhb, *p_hlb, *p_aohb, *p_aolb, *p_xthb, *p_xtlb, *p_bfhb, *p_bflb;
    float4 *p_qwpf, *p_pwpf, *p_bfqf, *p_bfof, *p_fc1wp, *p_fc2wp;
    uint4 *p_qwpu, *p_pwpu, *p_bfqu, *p_bfou;
    float *p_qr, *p_kr, *p_ar;
    int* p_idx;
    cudaGetSymbolAddress((void**)&p_hh,    g_h_hi);
    cudaGetSymbolAddress((void**)&p_hhb,   g_h_hb);
    cudaGetSymbolAddress((void**)&p_hlb,   g_h_lb);
    cudaGetSymbolAddress((void**)&p_qkv,   g_qkv);
    cudaGetSymbolAddress((void**)&p_aoh,   g_ao_hi);
    cudaGetSymbolAddress((void**)&p_aohb,  g_ao_hb);
    cudaGetSymbolAddress((void**)&p_aolb,  g_ao_lb);
    cudaGetSymbolAddress((void**)&p_o,     g_o);
    cudaGetSymbolAddress((void**)&p_xr,    g_xr);
    cudaGetSymbolAddress((void**)&p_h2,    g_h2);
    cudaGetSymbolAddress((void**)&p_mid,   g_mid);
    cudaGetSymbolAddress((void**)&p_xTh,   g_xT_hi);
    cudaGetSymbolAddress((void**)&p_xthb,  g_xT_hb);
    cudaGetSymbolAddress((void**)&p_xtlb,  g_xT_lb);
    cudaGetSymbolAddress((void**)&p_bfqkv, g_bfqkv);
    cudaGetSymbolAddress((void**)&p_bfao,  g_bfao);
    cudaGetSymbolAddress((void**)&p_bfaoh, g_bfao_hi);
    cudaGetSymbolAddress((void**)&p_bfhb,  g_bfao_hb);
    cudaGetSymbolAddress((void**)&p_bflb,  g_bfao_lb);
    cudaGetSymbolAddress((void**)&p_bf2,   g_bf2);
    cudaGetSymbolAddress((void**)&p_qwpf,  g_qwpf);
    cudaGetSymbolAddress((void**)&p_qwpu,  g_qwpu);
    cudaGetSymbolAddress((void**)&p_pwpf,  g_pwpf);
    cudaGetSymbolAddress((void**)&p_pwpu,  g_pwpu);
    cudaGetSymbolAddress((void**)&p_bfqf,  g_bfqf);
    cudaGetSymbolAddress((void**)&p_bfqu,  g_bfqu);
    cudaGetSymbolAddress((void**)&p_bfof,  g_bfof);
    cudaGetSymbolAddress((void**)&p_bfou,  g_bfou);
    cudaGetSymbolAddress((void**)&p_fc1wp, g_fc1wp);
    cudaGetSymbolAddress((void**)&p_fc2wp, g_fc2wp);
    cudaGetSymbolAddress((void**)&p_qr,    g_qr);
    cudaGetSymbolAddress((void**)&p_kr,    g_kr);
    cudaGetSymbolAddress((void**)&p_ar,    g_ar);
    cudaGetSymbolAddress((void**)&p_idx,   g_topk);

    cudaFuncSetAttribute(attn_kernel, cudaFuncAttributeMaxDynamicSharedMemorySize, ATTN_SMEM);
    cudaFuncSetAttribute(gemm3v, cudaFuncAttributeMaxDynamicSharedMemorySize, GS3V);
    cudaFuncSetAttribute(gemm1v, cudaFuncAttributeMaxDynamicSharedMemorySize, GS1V);

    static cudaStream_t s2 = nullptr;
    static cudaEvent_t evA = nullptr, evB = nullptr, evC = nullptr, evD = nullptr;
    if (s2 == nullptr) {
        cudaStreamCreateWithFlags(&s2, cudaStreamNonBlocking);
        cudaEventCreateWithFlags(&evA, cudaEventDisableTiming);
        cudaEventCreateWithFlags(&evB, cudaEventDisableTiming);
        cudaEventCreateWithFlags(&evC, cudaEventDisableTiming);
        cudaEventCreateWithFlags(&evD, cudaEventDisableTiming);
    }

    // ---- fork #1: non-qkv weight packs overlap ln+qkv gemm ----
    cudaEventRecord(evA, 0);
    cudaStreamWaitEvent(s2, evA, 0);

    bpack3<<<(49 * 2352 * 4 + 255) / 256, 256>>>(qkv_w, p_qwpf, p_qwpu, CDIM, 3 * CDIM);
    ln_split_kernel<<<NROW, 256>>>(x, n1g, n1b, p_hh, p_hhb, p_hlb);

    bpack3 <<<(49 * 784 * 4 + 255) / 256, 256, 0, s2>>>(proj_w, p_pwpf, p_pwpu, CDIM, CDIM);
    bpack3t<<<(4 * 192 * 4 + 255) / 256, 256, 0, s2>>>(bfqkv_w, p_bfqf, p_bfqu, 64, 192);
    bpack3t<<<(4 * 64 * 4 + 255) / 256, 256, 0, s2>>>(bfout_w, p_bfof, p_bfou, 64, 64);
    bpack1 <<<(49 * 3136 * 4 + 255) / 256, 256, 0, s2>>>(fc1_w, p_fc1wp, CDIM, HID);
    bpack1 <<<(196 * 784 * 4 + 255) / 256, 256, 0, s2>>>(fc2_w, p_fc2wp, HID, CDIM);
    cudaEventRecord(evB, s2);

    gemm3v<<<dim3(19, 64), 256, GS3V>>>(p_hh, p_hhb, p_hlb, p_qwpf, p_qwpu,
                                        nullptr, nullptr, p_qkv, nullptr, nullptr,
                                        NROW, 3 * CDIM, CDIM);
    attn_kernel<<<NB * NHD, 256, ATTN_SMEM>>>(p_qkv, p_aoh, p_aohb, p_aolb);

    cudaStreamWaitEvent(0, evB, 0);
    gemm3v<<<dim3(7, 64), 256, GS3V>>>(p_aoh, p_aohb, p_aolb, p_pwpf, p_pwpu,
                                       proj_b, nullptr, p_o, p_xr, x,
                                       NROW, CDIM, CDIM);

    // ---- fork #2: BiFormer branch on s2, MLP on main stream ----
    cudaEventRecord(evC, 0);
    cudaStreamWaitEvent(s2, evC, 0);

    transpose_split_kernel<<<dim3(25, 2, NB), dim3(32, 32), 0, s2>>>(p_o, p_xTh, p_xthb, p_xtlb);
    gemm3v<<<dim3(2, M2 / 128), 256, GS3V, s2>>>(p_xTh, p_xthb, p_xtlb, p_bfqf, p_bfqu,
                                                 bfqkv_b, nullptr, p_bfqkv, nullptr, nullptr,
                                                 M2, 192, 64);
    bf_pool_kernel<<<NB * 49, 128, 0, s2>>>(p_bfqkv, p_qr, p_kr);
    bf_ar_kernel<<<(NB * 49 * 49 + 255) / 256, 256, 0, s2>>>(p_qr, p_kr, p_ar);
    bf_topk_kernel<<<(NB * 49 + 255) / 256, 256, 0, s2>>>(p_ar, p_idx);
    bf_attn_kernel<<<NB * 8 * 49, 128, 0, s2>>>(p_bfqkv, p_idx, p_bfao);
    bf_lepe_split_kernel<<<(NB * 784 * 64 + 255) / 256, 256, 0, s2>>>(p_bfqkv, bflepe_w,
                                                                      bflepe_b, p_bfao,
                                                                      p_bfaoh, p_bfhb, p_bflb);
    gemm3v<<<dim3(1, M2 / 128), 256, GS3V, s2>>>(p_bfaoh, p_bfhb, p_bflb, p_bfof, p_bfou,
                                                 bfout_b, nullptr, p_bf2, nullptr, nullptr,
                                                 M2, 64, 64);
    transpose_kernel<<<dim3(2, 25, NB), dim3(32, 32), 0, s2>>>(p_bf2, out + OUT1, 784, 64);
    cudaEventRecord(evD, s2);

    ln_kernel<<<NROW, 256>>>(p_xr, n2g, n2b, p_h2);
    gemm1v<<<dim3(25, 64), 256, GS1V>>>(p_h2, p_fc1wp, fc1_b, nullptr, p_mid,
                                        NROW, HID, CDIM, 1, 1);
    gemm1v<<<dim3(7, 64), 256, GS1V>>>(p_mid, p_fc2wp, fc2_b, p_xr, out,
                                       NROW, CDIM, HID, 0, 0);

    cudaStreamWaitEvent(0, evD, 0);
}

// round 14
// speedup vs baseline: 1.2320x; 1.0295x over previous
#include <cuda_runtime.h>
#include <math.h>
#include <stdint.h>

#define NB    128
#define NTOKN 64
#define CDIM  784
#define NHD   8
#define HD    98
#define HID   3136
#define NROW  (NB*NTOKN)
#define M2    (NB*784)
#define OUT1  (NROW*CDIM)

// ---------------- scratch (device globals; no allocation allowed) ----------
__device__ float    g_h_hi  [NROW*CDIM];      // aperm f32
__device__ unsigned g_h_hb  [NROW*CDIM/2];    // bf16 pairs (qkv 3-term)
__device__ unsigned g_h_lb  [NROW*CDIM/2];
__device__ float    g_qkv   [NROW*3*CDIM];
__device__ float    g_ao_hi [NROW*CDIM];      // aperm rounded (proj 1x)
__device__ float    g_ao_raw[NROW*CDIM];      // row-major fp32 (routing)
__device__ float    g_o     [NROW*CDIM];
__device__ float    g_xr    [NROW*CDIM];
__device__ float    g_h2    [NROW*CDIM];      // aperm
__device__ float    g_mid   [NROW*HID];       // aperm
__device__ float    g_xT    [M2*64];          // aperm rounded
__device__ float    g_bfqkv [M2*192];
__device__ float    g_bfao  [M2*64];
__device__ float    g_bfaoh [M2*64];          // aperm rounded
__device__ float    g_bf2   [M2*64];
__device__ float4   g_qwpf  [(CDIM/16)*(3*CDIM)*4];
__device__ uint4    g_qwpu  [(CDIM/16)*(3*CDIM)*4];
__device__ float4   g_pwp1  [(CDIM/16)*CDIM*4];
__device__ float4   g_bfq1  [4*192*4];
__device__ float4   g_bfo1  [4*64*4];
__device__ float4   g_fc1wp [(CDIM/16)*HID*4];
__device__ float4   g_fc2wp [(HID/16)*CDIM*4];
__device__ float    g_pwpool[CDIM*49];
__device__ float    g_pbpool[49];
__device__ float    g_pool  [NROW*49];
__device__ float    g_ar    [NB*49*49];
__device__ int      g_topk  [NB*49*4];

// ---------------- helpers ----------------------------------------------------
__device__ __forceinline__ float f2tf32f(float x) {
    unsigned r;
    asm("cvt.rna.tf32.f32 %0, %1;" : "=r"(r) : "f"(x));
    return __uint_as_float(r);
}
__device__ __forceinline__ unsigned short f2bfu(float x) {
    unsigned short u;
    asm("cvt.rn.bf16.f32 %0, %1;" : "=h"(u) : "f"(x));
    return u;
}
__device__ __forceinline__ unsigned packbf(float p, float q) {
    unsigned r;
    asm("cvt.rn.bf16x2.f32 %0, %1, %2;" : "=r"(r) : "f"(q), "f"(p));
    return r;
}

// fragment-order A permutation for f32 (16row x 8k blocks of 128)
__device__ __forceinline__ size_t aperm(int row, int k, int K) {
    return ((size_t)((row >> 4) * (K >> 3) + (k >> 3)) << 7)
         + (size_t)((((row & 7) << 2) | (k & 3)) << 2)
         + (size_t)(((k & 4) >> 1) | ((row & 8) >> 3));
}
// ushort index into bf16 pair arrays (16row x 16k slabs of 128 u32)
__device__ __forceinline__ size_t bfidx(int row, int k, int K) {
    size_t u = ((size_t)((row >> 4) * (K >> 4) + (k >> 4)) << 7)
             + (size_t)(((((row & 7) << 2) | (k & 3)) << 2)
                        + (((k >> 3) & 1) << 1) + ((row >> 3) & 1));
    return u * 2 + (size_t)((k >> 2) & 1);
}

__device__ __forceinline__ void mma_tf32(float& d0, float& d1, float& d2, float& d3,
                                         unsigned a0, unsigned a1, unsigned a2, unsigned a3,
                                         unsigned b0, unsigned b1) {
    asm volatile(
        "mma.sync.aligned.m16n8k8.row.col.f32.tf32.tf32.f32 "
        "{%0,%1,%2,%3}, {%4,%5,%6,%7}, {%8,%9}, {%0,%1,%2,%3};\n"
        : "+f"(d0), "+f"(d1), "+f"(d2), "+f"(d3)
        : "r"(a0), "r"(a1), "r"(a2), "r"(a3), "r"(b0), "r"(b1));
}
__device__ __forceinline__ void mma_bf16(float& d0, float& d1, float& d2, float& d3,
                                         unsigned a0, unsigned a1, unsigned a2, unsigned a3,
                                         unsigned b0, unsigned b1) {
    asm volatile(
        "mma.sync.aligned.m16n8k16.row.col.f32.bf16.bf16.f32 "
        "{%0,%1,%2,%3}, {%4,%5,%6,%7}, {%8,%9}, {%0,%1,%2,%3};\n"
        : "+f"(d0), "+f"(d1), "+f"(d2), "+f"(d3)
        : "r"(a0), "r"(a1), "r"(a2), "r"(a3), "r"(b0), "r"(b1));
}

__device__ __forceinline__ void cp16(void* dst, const void* src, bool pred) {
    unsigned daddr = (unsigned)__cvta_generic_to_shared(dst);
    int sz = pred ? 16 : 0;
    asm volatile("cp.async.cg.shared.global [%0], [%1], 16, %2;\n"
                 :: "r"(daddr), "l"(src), "r"(sz));
}
#define CP_COMMIT() asm volatile("cp.async.commit_group;\n" ::: "memory")
#define CP_WAIT2()  asm volatile("cp.async.wait_group 2;\n" ::: "memory")

// ---------------- weight packs -----------------------------------------------
// 3-term pack from w[K][N]
__global__ void bpack3(const float* __restrict__ w, float4* __restrict__ of,
                       uint4* __restrict__ ou, int K, int N) {
    int q = blockIdx.x * blockDim.x + threadIdx.x;
    int total = (K >> 4) * N * 4;
    if (q >= total) return;
    int c = q & 3, n = (q >> 2) % N, s16 = q / (4 * N);
    int k = s16 * 16 + c;
    float v0 = w[(size_t)k * N + n];
    float v1 = w[(size_t)(k + 4) * N + n];
    float v2 = w[(size_t)(k + 8) * N + n];
    float v3 = w[(size_t)(k + 12) * N + n];
    float h0 = f2tf32f(v0), h1 = f2tf32f(v1), h2 = f2tf32f(v2), h3 = f2tf32f(v3);
    float l0 = f2tf32f(v0 - h0), l1 = f2tf32f(v1 - h1);
    float l2 = f2tf32f(v2 - h2), l3 = f2tf32f(v3 - h3);
    of[q] = make_float4(h0, h1, h2, h3);
    ou[q] = make_uint4(packbf(h0, h1), packbf(h2, h3), packbf(l0, l1), packbf(l2, l3));
}
// 1x pack from w[K][N]
__global__ void bpack1(const float* __restrict__ w, float4* __restrict__ out,
                       int K, int N) {
    int q = blockIdx.x * blockDim.x + threadIdx.x;
    int total = (K >> 4) * N * 4;
    if (q >= total) return;
    int c = q & 3, n = (q >> 2) % N, k16 = q / (4 * N);
    const float* p = w + (size_t)(k16 * 16 + c) * N + n;
    out[q] = make_float4(f2tf32f(p[0]),
                         f2tf32f(p[(size_t)4 * N]),
                         f2tf32f(p[(size_t)8 * N]),
                         f2tf32f(p[(size_t)12 * N]));
}
// 1x pack from w[N][K] (transpose during pack)
__global__ void bpack1t(const float* __restrict__ w, float4* __restrict__ out,
                        int K, int N) {
    int q = blockIdx.x * blockDim.x + threadIdx.x;
    int total = (K >> 4) * N * 4;
    if (q >= total) return;
    int c = q & 3, n = (q >> 2) % N, k16 = q / (4 * N);
    const float* p = w + (size_t)n * K + k16 * 16 + c;
    out[q] = make_float4(f2tf32f(p[0]), f2tf32f(p[4]), f2tf32f(p[8]), f2tf32f(p[12]));
}
// pooled proj weight/bias for routing sidecar
__global__ void pwp_pack(const float* __restrict__ pw, const float* __restrict__ pb,
                         float* __restrict__ pwp, float* __restrict__ pbp) {
    int e = blockIdx.x * blockDim.x + threadIdx.x;
    if (e < 784 * 49) {
        int k = e / 49, r = e % 49;
        int rh = r / 7, rw = r % 7;
        float s = 0.f;
#pragma unroll
        for (int p = 0; p < 4; p++)
#pragma unroll
            for (int q = 0; q < 4; q++)
                s += pw[(size_t)k * 784 + (rh * 4 + p) * 28 + rw * 4 + q];
        pwp[e] = s * (1.f / 16.f);
    } else if (e < 784 * 49 + 49) {
        int r = e - 784 * 49;
        int rh = r / 7, rw = r % 7;
        float s = 0.f;
#pragma unroll
        for (int p = 0; p < 4; p++)
#pragma unroll
            for (int q = 0; q < 4; q++)
                s += pb[(rh * 4 + p) * 28 + rw * 4 + q];
        pbp[r] = s * (1.f / 16.f);
    }
}

// ---------------- routing sidecar --------------------------------------------
// pooled_o[row][r] = sum_k ao[row][k] * pwp[k][r] + pbp[r]
__global__ void route_pool(const float* __restrict__ ao, const float* __restrict__ pwp,
                           const float* __restrict__ pbp, float* __restrict__ pool) {
    int row = blockIdx.x;
    __shared__ float sr[784];
    __shared__ float part[256];
    for (int i = threadIdx.x; i < 784; i += 256) sr[i] = ao[(size_t)row * 784 + i];
    __syncthreads();
    int r = threadIdx.x & 63, chunk = threadIdx.x >> 6;
    float s = 0.f;
    if (r < 49) {
        int k0 = chunk * 196;
        for (int k = k0; k < k0 + 196; k++) s = fmaf(sr[k], pwp[(size_t)k * 49 + r], s);
    }
    part[threadIdx.x] = s;
    __syncthreads();
    if (threadIdx.x < 49)
        pool[(size_t)row * 49 + threadIdx.x] =
            part[threadIdx.x] + part[64 + threadIdx.x] + part[128 + threadIdx.x]
            + part[192 + threadIdx.x] + pbp[threadIdx.x];
}

// per-batch: q_r/k_r = W_qk @ pooled + bias; a_r = q_r^T k_r
__global__ void route_score(const float* __restrict__ pool, const float* __restrict__ w,
                            const float* __restrict__ bias, float* __restrict__ ar) {
    int b = blockIdx.x;
    __shared__ float P[64][50], QR[64][50], KR[64][50];
    int tid = threadIdx.x;
    for (int e = tid; e < 64 * 49; e += 256) {
        int t = e / 49, r = e % 49;
        P[t][r] = pool[((size_t)b * 64 + t) * 49 + r];
    }
    __syncthreads();
    for (int e = tid; e < 64 * 49 * 2; e += 256) {
        int which = (e >= 64 * 49) ? 1 : 0;
        int e2 = e - which * 64 * 49;
        int oc = e2 / 49, r = e2 % 49;
        const float* wr = w + (size_t)(which * 64 + oc) * 64;
        float s = bias[which * 64 + oc];
        for (int t = 0; t < 64; t++) s = fmaf(wr[t], P[t][r], s);
        if (which) KR[oc][r] = s; else QR[oc][r] = s;
    }
    __syncthreads();
    for (int e = tid; e < 49 * 49; e += 256) {
        int r = e / 49, sc = e % 49;
        float s = 0.f;
        for (int oc = 0; oc < 64; oc++) s = fmaf(QR[oc][r], KR[oc][sc], s);
        ar[((size_t)b * 49 + r) * 49 + sc] = s;
    }
}

// ---------------- LayerNorm, aperm rounded output ----------------------------
__global__ void ln_kernel(const float* __restrict__ x, const float* __restrict__ g,
                          const float* __restrict__ b, float* __restrict__ y) {
    int row = blockIdx.x;
    const float* xr = x + (size_t)row * CDIM;
    float s = 0.f, s2 = 0.f;
    for (int i = threadIdx.x; i < CDIM; i += blockDim.x) {
        float v = xr[i]; s += v; s2 += v * v;
    }
    for (int o = 16; o; o >>= 1) {
        s  += __shfl_xor_sync(0xffffffffu, s,  o);
        s2 += __shfl_xor_sync(0xffffffffu, s2, o);
    }
    __shared__ float sh[16], sh2[16];
    int warp = threadIdx.x >> 5, lane = threadIdx.x & 31;
    if (lane == 0) { sh[warp] = s; sh2[warp] = s2; }
    __syncthreads();
    if (threadIdx.x == 0) {
        float t = 0.f, t2 = 0.f;
        int nw = blockDim.x >> 5;
        for (int i = 0; i < nw; i++) { t += sh[i]; t2 += sh2[i]; }
        sh[0] = t; sh2[0] = t2;
    }
    __syncthreads();
    float mean = sh[0] * (1.0f / CDIM);
    float var  = sh2[0] * (1.0f / CDIM) - mean * mean;
    float rinv = rsqrtf(var + 1e-5f);
    for (int i = threadIdx.x; i < CDIM; i += blockDim.x)
        y[aperm(row, i, CDIM)] = f2tf32f((xr[i] - mean) * rinv * g[i] + b[i]);
}

// ---------------- LayerNorm, aperm hi + bf16 pairs (qkv 3-term) -------------
__global__ void ln_split_kernel(const float* __restrict__ x, const float* __restrict__ g,
                                const float* __restrict__ b, float* __restrict__ yh,
                                unsigned* __restrict__ hbw, unsigned* __restrict__ lbw) {
    int row = blockIdx.x;
    const float* xr = x + (size_t)row * CDIM;
    unsigned short* hb = (unsigned short*)hbw;
    unsigned short* lb = (unsigned short*)lbw;
    float s = 0.f, s2 = 0.f;
    for (int i = threadIdx.x; i < CDIM; i += blockDim.x) {
        float v = xr[i]; s += v; s2 += v * v;
    }
    for (int o = 16; o; o >>= 1) {
        s  += __shfl_xor_sync(0xffffffffu, s,  o);
        s2 += __shfl_xor_sync(0xffffffffu, s2, o);
    }
    __shared__ float sh[16], sh2[16];
    int warp = threadIdx.x >> 5, lane = threadIdx.x & 31;
    if (lane == 0) { sh[warp] = s; sh2[warp] = s2; }
    __syncthreads();
    if (threadIdx.x == 0) {
        float t = 0.f, t2 = 0.f;
        int nw = blockDim.x >> 5;
        for (int i = 0; i < nw; i++) { t += sh[i]; t2 += sh2[i]; }
        sh[0] = t; sh2[0] = t2;
    }
    __syncthreads();
    float mean = sh[0] * (1.0f / CDIM);
    float var  = sh2[0] * (1.0f / CDIM) - mean * mean;
    float rinv = rsqrtf(var + 1e-5f);
    for (int i = threadIdx.x; i < CDIM; i += blockDim.x) {
        float v = (xr[i] - mean) * rinv * g[i] + b[i];
        float h = f2tf32f(v);
        yh[aperm(row, i, CDIM)] = h;
        size_t bi = bfidx(row, i, CDIM);
        hb[bi] = f2bfu(h);
        lb[bi] = f2bfu(f2tf32f(v - h));
    }
}

// ---- 3-term GEMM: tf32 main + pre-packed bf16 corrections, 3-stage ---------
#define S3STG 8192
#define GS3V  (3*S3STG*4)
__global__ void __launch_bounds__(256, 2)
gemm3v(const float* __restrict__ Ah, const unsigned* __restrict__ HB,
       const unsigned* __restrict__ LB,
       const float4* __restrict__ Bf, const uint4* __restrict__ Bu,
       const float* __restrict__ bias, float* __restrict__ C, int M, int N, int K) {
    extern __shared__ float sm[];
    int tid = threadIdx.x, warp = tid >> 5, lane = tid & 31;
    int wm = warp & 1, wn = warp >> 1;
    int row0 = blockIdx.y * 128, col0 = blockIdx.x * 128;
    int r = lane >> 2, c = lane & 3;
    int nk = K >> 4, K8 = K >> 3, K16 = K >> 4;

    float acc[4][4][4];
#pragma unroll
    for (int i = 0; i < 4; i++)
#pragma unroll
        for (int j = 0; j < 4; j++)
#pragma unroll
            for (int q = 0; q < 4; q++) acc[i][j][q] = 0.f;

#define P3(SIDX, KT) do { \
        float* sa = sm + (SIDX) * S3STG; \
        for (int q = tid; q < 512; q += 256) { \
            int b_ = q >> 6, ks_ = (q >> 5) & 1, ln_ = q & 31; \
            size_t g_ = ((size_t)((row0 >> 4) + b_) * K8 + (KT) * 2 + ks_) * 128 + ln_ * 4; \
            cp16(sa + (b_ * 2 + ks_) * 128 + ln_ * 4, Ah + g_, true); \
        } \
        { \
            int b_ = tid >> 5, ln_ = tid & 31; \
            size_t g_ = ((size_t)((row0 >> 4) + b_) * K16 + (KT)) * 128 + ln_ * 4; \
            cp16(sa + 2048 + b_ * 128 + ln_ * 4, HB + g_, true); \
            cp16(sa + 3072 + b_ * 128 + ln_ * 4, LB + g_, true); \
        } \
        for (int q = tid; q < 512; q += 256) { \
            int nl_ = q >> 2, cc_ = q & 3; \
            int n_ = col0 + nl_; \
            size_t g_ = ((size_t)(KT) * N + n_) * 4 + cc_; \
            cp16(sa + 4096 + q * 4, Bf + g_, n_ < N); \
            cp16(sa + 6144 + q * 4, Bu + g_, n_ < N); \
        } \
    } while (0)

    P3(0, 0); CP_COMMIT();
    if (nk > 1) P3(1, 1);
    CP_COMMIT();
    if (nk > 2) P3(2, 2);
    CP_COMMIT();

    for (int kt = 0; kt < nk; kt++) {
        CP_WAIT2();
        __syncthreads();
        int s = kt % 3;
        float* sa = sm + s * S3STG;

        float4 bf4[4];
        uint4  bu4[4];
#pragma unroll
        for (int nt = 0; nt < 4; nt++) {
            int nl = wn * 32 + nt * 8 + r;
            int o = (nl * 4 + c) * 4;
            bf4[nt] = *(const float4*)(sa + 4096 + o);
            bu4[nt] = *(const uint4*)(sa + 6144 + o);
        }
#pragma unroll
        for (int mt = 0; mt < 4; mt++) {
            int off0 = ((wm * 4 + mt) * 2 + 0) * 128 + lane * 4;
            float4 ah0 = *(const float4*)(sa + off0);
            float4 ah1 = *(const float4*)(sa + off0 + 128);
            uint4 hb = *(const uint4*)(sa + 2048 + (wm * 4 + mt) * 128 + lane * 4);
            uint4 lb = *(const uint4*)(sa + 3072 + (wm * 4 + mt) * 128 + lane * 4);
            unsigned a00 = __float_as_uint(ah0.x), a01 = __float_as_uint(ah0.y);
            unsigned a02 = __float_as_uint(ah0.z), a03 = __float_as_uint(ah0.w);
            unsigned a10 = __float_as_uint(ah1.x), a11 = __float_as_uint(ah1.y);
            unsigned a12 = __float_as_uint(ah1.z), a13 = __float_as_uint(ah1.w);
#pragma unroll
            for (int nt = 0; nt < 4; nt++) {
                mma_tf32(acc[mt][nt][0], acc[mt][nt][1], acc[mt][nt][2], acc[mt][nt][3],
                         a00, a01, a02, a03,
                         __float_as_uint(bf4[nt].x), __float_as_uint(bf4[nt].y));
                mma_tf32(acc[mt][nt][0], acc[mt][nt][1], acc[mt][nt][2], acc[mt][nt][3],
                         a10, a11, a12, a13,
                         __float_as_uint(bf4[nt].z), __float_as_uint(bf4[nt].w));
                mma_bf16(acc[mt][nt][0], acc[mt][nt][1], acc[mt][nt][2], acc[mt][nt][3],
                         hb.x, hb.y, hb.z, hb.w, bu4[nt].z, bu4[nt].w);
                mma_bf16(acc[mt][nt][0], acc[mt][nt][1], acc[mt][nt][2], acc[mt][nt][3],
                         lb.x, lb.y, lb.z, lb.w, bu4[nt].x, bu4[nt].y);
            }
        }
        __syncthreads();
        if (kt + 3 < nk) P3(s, kt + 3);
        CP_COMMIT();
    }
#undef P3

#pragma unroll
    for (int mt = 0; mt < 4; mt++) {
        int rr0 = row0 + wm * 64 + mt * 16 + r;
#pragma unroll
        for (int nt = 0; nt < 4; nt++) {
            int cb = col0 + wn * 32 + nt * 8 + 2 * c;
#pragma unroll
            for (int half = 0; half < 2; half++) {
                int rr = rr0 + half * 8;
                float v0 = acc[mt][nt][half * 2 + 0];
                float v1 = acc[mt][nt][half * 2 + 1];
                if (bias) { if (cb < N) v0 += bias[cb]; if (cb + 1 < N) v1 += bias[cb + 1]; }
                size_t base = (size_t)rr * N + cb;
                if (cb < N)     C[base]     = v0;
                if (cb + 1 < N) C[base + 1] = v1;
            }
        }
    }
}

// ---------------- 1xTF32 GEMM, fragment-permuted, 3-stage, dual-output ------
#define S1STG 4096
#define GS1V  (3*S1STG*4)
__global__ void __launch_bounds__(256, 2)
gemm1v(const float* __restrict__ A, const float4* __restrict__ Bq,
       const float* __restrict__ bias, const float* __restrict__ res,
       float* __restrict__ C, float* __restrict__ C2, const float* __restrict__ res2,
       int M, int N, int K, int act, int permC) {
    extern __shared__ float sm[];
    int tid = threadIdx.x, warp = tid >> 5, lane = tid & 31;
    int wm = warp & 1, wn = warp >> 1;
    int row0 = blockIdx.y * 128, col0 = blockIdx.x * 128;
    int r = lane >> 2, c = lane & 3;
    int nk = K >> 4, K8 = K >> 3;

    float acc[4][4][4];
#pragma unroll
    for (int i = 0; i < 4; i++)
#pragma unroll
        for (int j = 0; j < 4; j++)
#pragma unroll
            for (int q = 0; q < 4; q++) acc[i][j][q] = 0.f;

#define P1(SIDX, KT) do { \
        float* sa = sm + (SIDX) * S1STG; \
        for (int q = tid; q < 512; q += 256) { \
            int b_ = q >> 6, ks_ = (q >> 5) & 1, ln_ = q & 31; \
            size_t g_ = ((size_t)((row0 >> 4) + b_) * K8 + (KT) * 2 + ks_) * 128 + ln_ * 4; \
            cp16(sa + (b_ * 2 + ks_) * 128 + ln_ * 4, A + g_, true); \
        } \
        for (int q = tid; q < 512; q += 256) { \
            int nl_ = q >> 2, cc_ = q & 3; \
            int n_ = col0 + nl_; \
            size_t g_ = ((size_t)(KT) * N + n_) * 4 + cc_; \
            cp16(sa + 2048 + q * 4, Bq + g_, n_ < N); \
        } \
    } while (0)

    P1(0, 0); CP_COMMIT();
    if (nk > 1) P1(1, 1);
    CP_COMMIT();
    if (nk > 2) P1(2, 2);
    CP_COMMIT();

    for (int kt = 0; kt < nk; kt++) {
        CP_WAIT2();
        __syncthreads();
        int s = kt % 3;
        float* sa = sm + s * S1STG;
        float4 bq4[4];
#pragma unroll
        for (int nt = 0; nt < 4; nt++) {
            int nl = wn * 32 + nt * 8 + r;
            bq4[nt] = *(const float4*)(sa + 2048 + (nl * 4 + c) * 4);
        }
#pragma unroll
        for (int ks = 0; ks < 2; ks++) {
            float4 a4[4];
#pragma unroll
            for (int mt = 0; mt < 4; mt++) {
                int off = ((wm * 4 + mt) * 2 + ks) * 128 + lane * 4;
                a4[mt] = *(const float4*)(sa + off);
            }
#pragma unroll
            for (int mt = 0; mt < 4; mt++) {
                unsigned a0 = __float_as_uint(a4[mt].x), a1 = __float_as_uint(a4[mt].y);
                unsigned a2 = __float_as_uint(a4[mt].z), a3 = __float_as_uint(a4[mt].w);
#pragma unroll
                for (int nt = 0; nt < 4; nt++) {
                    unsigned b0 = __float_as_uint(ks == 0 ? bq4[nt].x : bq4[nt].z);
                    unsigned b1 = __float_as_uint(ks == 0 ? bq4[nt].y : bq4[nt].w);
                    mma_tf32(acc[mt][nt][0], acc[mt][nt][1], acc[mt][nt][2], acc[mt][nt][3],
                             a0, a1, a2, a3, b0, b1);
                }
            }
        }
        __syncthreads();
        if (kt + 3 < nk) P1(s, kt + 3);
        CP_COMMIT();
    }
#undef P1

#pragma unroll
    for (int mt = 0; mt < 4; mt++) {
        int rr0 = row0 + wm * 64 + mt * 16 + r;
#pragma unroll
        for (int nt = 0; nt < 4; nt++) {
            int cb = col0 + wn * 32 + nt * 8 + 2 * c;
#pragma unroll
            for (int half = 0; half < 2; half++) {
                int rr = rr0 + half * 8;
                float v0 = acc[mt][nt][half * 2 + 0];
                float v1 = acc[mt][nt][half * 2 + 1];
                if (bias) { if (cb < N) v0 += bias[cb]; if (cb + 1 < N) v1 += bias[cb + 1]; }
                if (act == 1) {
                    v0 = f2tf32f(0.5f * v0 * (1.f + erff(v0 * 0.70710678118654752f)));
                    v1 = f2tf32f(0.5f * v1 * (1.f + erff(v1 * 0.70710678118654752f)));
                }
                size_t base = (size_t)rr * N + cb;
                float w0 = v0, w1 = v1;
                if (res) { if (cb < N) w0 += res[base]; if (cb + 1 < N) w1 += res[base + 1]; }
                if (permC) {
                    if (cb < N)     C[aperm(rr, cb, N)]     = w0;
                    if (cb + 1 < N) C[aperm(rr, cb + 1, N)] = w1;
                } else {
                    if (cb < N)     C[base]     = w0;
                    if (cb + 1 < N) C[base + 1] = w1;
                }
                if (C2) {
                    float u0 = v0, u1 = v1;
                    if (res2) { if (cb < N) u0 += res2[base]; if (cb + 1 < N) u1 += res2[base + 1]; }
                    if (cb < N)     C2[base]     = u0;
                    if (cb + 1 < N) C2[base + 1] = u1;
                }
            }
        }
    }
}

// ---------------- fused main MHA: aperm rounded + raw row-major --------------
#define ATTN_SMEM ((3*64*99 + 64*64) * 4)
__global__ void attn_kernel(const float* __restrict__ qkv, float* __restrict__ oh,
                            float* __restrict__ oraw) {
    extern __shared__ float smf[];
    float* Qs = smf;
    float* Ks = Qs + 64 * 99;
    float* Vs = Ks + 64 * 99;
    float* Ss = Vs + 64 * 99;
    int b = blockIdx.x >> 3;
    int h = blockIdx.x & 7;
    const float* base = qkv + (size_t)b * 64 * (3 * CDIM) + h * HD;

    for (int e = threadIdx.x; e < 64 * HD; e += blockDim.x) {
        int r = e / HD, d = e % HD;
        const float* rp = base + (size_t)r * (3 * CDIM) + d;
        Qs[r * 99 + d] = rp[0];
        Ks[r * 99 + d] = rp[CDIM];
        Vs[r * 99 + d] = rp[2 * CDIM];
    }
    __syncthreads();

    const float scale = 1.0f / sqrtf(98.0f);
    for (int e = threadIdx.x; e < 4096; e += blockDim.x) {
        int i = e >> 6, j = e & 63;
        const float* qi = Qs + i * 99;
        const float* kj = Ks + j * 99;
        float a = 0.f;
#pragma unroll
        for (int d = 0; d < HD; d++) a = fmaf(qi[d], kj[d], a);
        Ss[e] = a * scale;
    }
    __syncthreads();

    int warp = threadIdx.x >> 5, lane = threadIdx.x & 31;
    for (int i = warp; i < 64; i += 8) {
        float v0 = Ss[i * 64 + lane], v1 = Ss[i * 64 + lane + 32];
        float mx = fmaxf(v0, v1);
        for (int o = 16; o; o >>= 1) mx = fmaxf(mx, __shfl_xor_sync(0xffffffffu, mx, o));
        float e0 = __expf(v0 - mx), e1 = __expf(v1 - mx);
        float s = e0 + e1;
        for (int o = 16; o; o >>= 1) s += __shfl_xor_sync(0xffffffffu, s, o);
        float inv = 1.f / s;
        Ss[i * 64 + lane]      = e0 * inv;
        Ss[i * 64 + lane + 32] = e1 * inv;
    }
    __syncthreads();

    for (int e = threadIdx.x; e < 64 * HD; e += blockDim.x) {
        int i = e / HD, d = e % HD;
        const float* p = Ss + i * 64;
        float a = 0.f;
#pragma unroll
        for (int j = 0; j < 64; j++) a = fmaf(p[j], Vs[j * 99 + d], a);
        int row = b * 64 + i, k = h * HD + d;
        oraw[(size_t)row * CDIM + k] = a;
        oh[aperm(row, k, CDIM)] = f2tf32f(a);
    }
}

// ---------------- transpose to aperm rounded ---------------------------------
__global__ void transpose_round_kernel(const float* __restrict__ in, float* __restrict__ oh) {
    __shared__ float tile[32][33];
    int b = blockIdx.z;
    int r0 = blockIdx.y * 32, c0 = blockIdx.x * 32;
    const float* ib = in + (size_t)b * 64 * 784;
    int r = r0 + threadIdx.y, c = c0 + threadIdx.x;
    if (r < 64 && c < 784) tile[threadIdx.y][threadIdx.x] = ib[(size_t)r * 784 + c];
    __syncthreads();
    int rr = r0 + threadIdx.x, cc = c0 + threadIdx.y;
    if (rr < 64 && cc < 784)
        oh[aperm(b * 784 + cc, rr, 64)] = f2tf32f(tile[threadIdx.x][threadIdx.y]);
}

// ---------------- plain transpose --------------------------------------------
__global__ void transpose_kernel(const float* __restrict__ in, float* __restrict__ out,
                                 int R, int Cc) {
    __shared__ float tile[32][33];
    int b = blockIdx.z;
    int r0 = blockIdx.y * 32, c0 = blockIdx.x * 32;
    const float* ib = in + (size_t)b * R * Cc;
    float* ob = out + (size_t)b * R * Cc;
    int r = r0 + threadIdx.y, c = c0 + threadIdx.x;
    if (r < R && c < Cc) tile[threadIdx.y][threadIdx.x] = ib[(size_t)r * Cc + c];
    __syncthreads();
    int rr = r0 + threadIdx.x, cc = c0 + threadIdx.y;
    if (rr < R && cc < Cc) ob[(size_t)cc * R + rr] = tile[threadIdx.x][threadIdx.y];
}

// ---------------- top-4 per (b, r) --------------------------------------------
__global__ void bf_topk_kernel(const float* __restrict__ ar, int* __restrict__ idx) {
    int t = blockIdx.x * blockDim.x + threadIdx.x;
    if (t >= NB * 49) return;
    float v[49];
    const float* row = ar + (size_t)t * 49;
#pragma unroll
    for (int s = 0; s < 49; s++) v[s] = row[s];
    for (int k = 0; k < 4; k++) {
        float best = -3.4e38f; int bi = 0;
        for (int s = 0; s < 49; s++)
            if (v[s] > best) { best = v[s]; bi = s; }
        idx[t * 4 + k] = bi;
        v[bi] = -3.4e38f;
    }
}

// ---------------- BiFormer region attention ------------------------------------
__global__ void bf_attn_kernel(const float* __restrict__ qkvt, const int* __restrict__ idx,
                               float* __restrict__ ao) {
    __shared__ float Qs[16][8], Ks[64][9], Vs[64][9], S[16][64];
    __shared__ int sreg[4];
    int r = blockIdx.x % 49;
    int m = (blockIdx.x / 49) & 7;
    int b = blockIdx.x / (49 * 8);
    int tid = threadIdx.x;
    int rh = r / 7, rw = r % 7;

    if (tid < 4) sreg[tid] = idx[((size_t)b * 49 + r) * 4 + tid];
    {
        int p = tid >> 3, d = tid & 7;
        int hw = (rh * 4 + (p >> 2)) * 28 + rw * 4 + (p & 3);
        Qs[p][d] = qkvt[((size_t)b * 784 + hw) * 192 + m * 8 + d];
    }
    __syncthreads();

    for (int e = tid; e < 512; e += 128) {
        int slot = e >> 3, d = e & 7;
        int t = slot >> 4, s = slot & 15;
        int sr = sreg[t];
        int hw = ((sr / 7) * 4 + (s >> 2)) * 28 + (sr % 7) * 4 + (s & 3);
        const float* p = qkvt + ((size_t)b * 784 + hw) * 192 + m * 8 + d;
        Ks[slot][d] = p[64];
        Vs[slot][d] = p[128];
    }
    __syncthreads();

    for (int e = tid; e < 1024; e += 128) {
        int i = e >> 6, j = e & 63;
        float a = 0.f;
#pragma unroll
        for (int d = 0; d < 8; d++) a = fmaf(Qs[i][d], Ks[j][d], a);
        S[i][j] = a * 0.125f;
    }
    __syncthreads();

    int warp = tid >> 5, lane = tid & 31;
    for (int i = warp; i < 16; i += 4) {
        float v0 = S[i][lane], v1 = S[i][lane + 32];
        float mx = fmaxf(v0, v1);
        for (int o = 16; o; o >>= 1) mx = fmaxf(mx, __shfl_xor_sync(0xffffffffu, mx, o));
        float e0 = __expf(v0 - mx), e1 = __expf(v1 - mx);
        float s = e0 + e1;
        for (int o = 16; o; o >>= 1) s += __shfl_xor_sync(0xffffffffu, s, o);
        float inv = 1.f / s;
        S[i][lane] = e0 * inv;
        S[i][lane + 32] = e1 * inv;
    }
    __syncthreads();

    {
        int i = tid >> 3, d = tid & 7;
        float a = 0.f;
#pragma unroll
        for (int j = 0; j < 64; j++) a = fmaf(S[i][j], Vs[j][d], a);
        int hw = (rh * 4 + (i >> 2)) * 28 + rw * 4 + (i & 3);
        ao[((size_t)b * 784 + hw) * 64 + m * 8 + d] = a;
    }
}

// ---------------- LePE: dw conv add, aperm rounded output --------------------
__global__ void bf_lepe_round_kernel(const float* __restrict__ qkvt,
                                     const float* __restrict__ w,
                                     const float* __restrict__ bias,
                                     const float* __restrict__ ao, float* __restrict__ aoh) {
    int e = blockIdx.x * blockDim.x + threadIdx.x;
    if (e >= NB * 784 * 64) return;
    int c  = e & 63;
    int hw = (e >> 6) % 784;
    int b  = e / (784 * 64);
    int h = hw / 28, wq = hw % 28;
    float acc = bias[c];
#pragma unroll
    for (int i = 0; i < 3; i++) {
        int hh = h + i - 1;
        if (hh < 0 || hh >= 28) continue;
#pragma unroll
        for (int j = 0; j < 3; j++) {
            int ww = wq + j - 1;
            if (ww < 0 || ww >= 28) continue;
            acc = fmaf(qkvt[((size_t)b * 784 + hh * 28 + ww) * 192 + 128 + c],
                       w[c * 9 + i * 3 + j], acc);
        }
    }
    aoh[aperm(b * 784 + hw, c, 64)] = f2tf32f(ao[e] + acc);
}

// ============================================================================
extern "C" void kernel_launch(void* const* d_in, const int* in_sizes, int n_in,
                              void* d_out, int out_size) {
    const float* x        = (const float*)d_in[0];
    const float* n1g      = (const float*)d_in[1];
    const float* n1b      = (const float*)d_in[2];
    const float* qkv_w    = (const float*)d_in[3];
    const float* proj_w   = (const float*)d_in[4];
    const float* proj_b   = (const float*)d_in[5];
    const float* n2g      = (const float*)d_in[6];
    const float* n2b      = (const float*)d_in[7];
    const float* fc1_w    = (const float*)d_in[8];
    const float* fc1_b    = (const float*)d_in[9];
    const float* fc2_w    = (const float*)d_in[10];
    const float* fc2_b    = (const float*)d_in[11];
    const float* bfqkv_w  = (const float*)d_in[12];
    const float* bfqkv_b  = (const float*)d_in[13];
    const float* bflepe_w = (const float*)d_in[14];
    const float* bflepe_b = (const float*)d_in[15];
    const float* bfout_w  = (const float*)d_in[16];
    const float* bfout_b  = (const float*)d_in[17];
    float* out = (float*)d_out;

    float *p_hh, *p_qkv, *p_aoh, *p_aoraw, *p_o, *p_xr, *p_h2, *p_mid;
    float *p_xT, *p_bfqkv, *p_bfao, *p_bfaoh, *p_bf2;
    unsigned *p_hhb, *p_hlb;
    float4 *p_qwpf, *p_pwp1, *p_bfq1, *p_bfo1, *p_fc1wp, *p_fc2wp;
    uint4 *p_qwpu;
    float *p_pwpool, *p_pbpool, *p_pool, *p_ar;
    int* p_idx;
    cudaGetSymbolAddress((void**)&p_hh,     g_h_hi);
    cudaGetSymbolAddress((void**)&p_hhb,    g_h_hb);
    cudaGetSymbolAddress((void**)&p_hlb,    g_h_lb);
    cudaGetSymbolAddress((void**)&p_qkv,    g_qkv);
    cudaGetSymbolAddress((void**)&p_aoh,    g_ao_hi);
    cudaGetSymbolAddress((void**)&p_aoraw,  g_ao_raw);
    cudaGetSymbolAddress((void**)&p_o,      g_o);
    cudaGetSymbolAddress((void**)&p_xr,     g_xr);
    cudaGetSymbolAddress((void**)&p_h2,     g_h2);
    cudaGetSymbolAddress((void**)&p_mid,    g_mid);
    cudaGetSymbolAddress((void**)&p_xT,     g_xT);
    cudaGetSymbolAddress((void**)&p_bfqkv,  g_bfqkv);
    cudaGetSymbolAddress((void**)&p_bfao,   g_bfao);
    cudaGetSymbolAddress((void**)&p_bfaoh,  g_bfaoh);
    cudaGetSymbolAddress((void**)&p_bf2,    g_bf2);
    cudaGetSymbolAddress((void**)&p_qwpf,   g_qwpf);
    cudaGetSymbolAddress((void**)&p_qwpu,   g_qwpu);
    cudaGetSymbolAddress((void**)&p_pwp1,   g_pwp1);
    cudaGetSymbolAddress((void**)&p_bfq1,   g_bfq1);
    cudaGetSymbolAddress((void**)&p_bfo1,   g_bfo1);
    cudaGetSymbolAddress((void**)&p_fc1wp,  g_fc1wp);
    cudaGetSymbolAddress((void**)&p_fc2wp,  g_fc2wp);
    cudaGetSymbolAddress((void**)&p_pwpool, g_pwpool);
    cudaGetSymbolAddress((void**)&p_pbpool, g_pbpool);
    cudaGetSymbolAddress((void**)&p_pool,   g_pool);
    cudaGetSymbolAddress((void**)&p_ar,     g_ar);
    cudaGetSymbolAddress((void**)&p_idx,    g_topk);

    cudaFuncSetAttribute(attn_kernel, cudaFuncAttributeMaxDynamicSharedMemorySize, ATTN_SMEM);
    cudaFuncSetAttribute(gemm3v, cudaFuncAttributeMaxDynamicSharedMemorySize, GS3V);
    cudaFuncSetAttribute(gemm1v, cudaFuncAttributeMaxDynamicSharedMemorySize, GS1V);

    static cudaStream_t s2 = nullptr;
    static cudaEvent_t evA = nullptr, evB = nullptr, evC = nullptr, evD = nullptr, evE = nullptr;
    if (s2 == nullptr) {
        cudaStreamCreateWithFlags(&s2, cudaStreamNonBlocking);
        cudaEventCreateWithFlags(&evA, cudaEventDisableTiming);
        cudaEventCreateWithFlags(&evB, cudaEventDisableTiming);
        cudaEventCreateWithFlags(&evC, cudaEventDisableTiming);
        cudaEventCreateWithFlags(&evD, cudaEventDisableTiming);
        cudaEventCreateWithFlags(&evE, cudaEventDisableTiming);
    }

    // ---- fork #1: weight packs + routing-weight pool on s2 ----
    cudaEventRecord(evA, 0);
    cudaStreamWaitEvent(s2, evA, 0);

    bpack3<<<(49 * 2352 * 4 + 255) / 256, 256>>>(qkv_w, p_qwpf, p_qwpu, CDIM, 3 * CDIM);
    ln_split_kernel<<<NROW, 256>>>(x, n1g, n1b, p_hh, p_hhb, p_hlb);

    pwp_pack<<<(784 * 49 + 49 + 255) / 256, 256, 0, s2>>>(proj_w, proj_b, p_pwpool, p_pbpool);
    bpack1 <<<(49 * 784 * 4 + 255) / 256, 256, 0, s2>>>(proj_w, p_pwp1, CDIM, CDIM);
    bpack1t<<<(4 * 192 * 4 + 255) / 256, 256, 0, s2>>>(bfqkv_w, p_bfq1, 64, 192);
    bpack1t<<<(4 * 64 * 4 + 255) / 256, 256, 0, s2>>>(bfout_w, p_bfo1, 64, 64);
    bpack1 <<<(49 * 3136 * 4 + 255) / 256, 256, 0, s2>>>(fc1_w, p_fc1wp, CDIM, HID);
    bpack1 <<<(196 * 784 * 4 + 255) / 256, 256, 0, s2>>>(fc2_w, p_fc2wp, HID, CDIM);
    cudaEventRecord(evB, s2);

    gemm3v<<<dim3(19, 64), 256, GS3V>>>(p_hh, p_hhb, p_hlb, p_qwpf, p_qwpu,
                                        nullptr, p_qkv, NROW, 3 * CDIM, CDIM);
    attn_kernel<<<NB * NHD, 256, ATTN_SMEM>>>(p_qkv, p_aoh, p_aoraw);
    cudaEventRecord(evE, 0);

    // routing sidecar on s2 (needs attn output + pooled weights)
    cudaStreamWaitEvent(s2, evE, 0);
    route_pool<<<NROW, 256, 0, s2>>>(p_aoraw, p_pwpool, p_pbpool, p_pool);
    route_score<<<NB, 256, 0, s2>>>(p_pool, bfqkv_w, bfqkv_b, p_ar);
    bf_topk_kernel<<<(NB * 49 + 255) / 256, 256, 0, s2>>>(p_ar, p_idx);

    // proj (1x) on main; dual output o + xr = o + x
    cudaStreamWaitEvent(0, evB, 0);
    gemm1v<<<dim3(7, 64), 256, GS1V>>>(p_aoh, p_pwp1, proj_b, nullptr,
                                       p_o, p_xr, x, NROW, CDIM, CDIM, 0, 0);

    // ---- fork #2: BiFormer values on s2, MLP on main ----
    cudaEventRecord(evC, 0);
    cudaStreamWaitEvent(s2, evC, 0);

    transpose_round_kernel<<<dim3(25, 2, NB), dim3(32, 32), 0, s2>>>(p_o, p_xT);
    gemm1v<<<dim3(2, M2 / 128), 256, GS1V, s2>>>(p_xT, p_bfq1, bfqkv_b, nullptr,
                                                 p_bfqkv, nullptr, nullptr, M2, 192, 64, 0, 0);
    bf_attn_kernel<<<NB * 8 * 49, 128, 0, s2>>>(p_bfqkv, p_idx, p_bfao);
    bf_lepe_round_kernel<<<(NB * 784 * 64 + 255) / 256, 256, 0, s2>>>(p_bfqkv, bflepe_w,
                                                                      bflepe_b, p_bfao, p_bfaoh);
    gemm1v<<<dim3(1, M2 / 128), 256, GS1V, s2>>>(p_bfaoh, p_bfo1, bfout_b, nullptr,
                                                 p_bf2, nullptr, nullptr, M2, 64, 64, 0, 0);
    transpose_kernel<<<dim3(2, 25, NB), dim3(32, 32), 0, s2>>>(p_bf2, out + OUT1, 784, 64);
    cudaEventRecord(evD, s2);

    ln_kernel<<<NROW, 256>>>(p_xr, n2g, n2b, p_h2);
    gemm1v<<<dim3(25, 64), 256, GS1V>>>(p_h2, p_fc1wp, fc1_b, nullptr, p_mid,
                                        nullptr, nullptr, NROW, HID, CDIM, 1, 1);
    gemm1v<<<dim3(7, 64), 256, GS1V>>>(p_mid, p_fc2wp, fc2_b, p_xr, out,
                                       nullptr, nullptr, NROW, CDIM, HID, 0, 0);

    cudaStreamWaitEvent(0, evD, 0);
}

// round 15
// speedup vs baseline: 1.3027x; 1.0574x over previous
#include <cuda_runtime.h>
#include <math.h>
#include <stdint.h>

#define NB    128
#define NTOKN 64
#define CDIM  784
#define NHD   8
#define HD    98
#define HID   3136
#define NROW  (NB*NTOKN)
#define M2    (NB*784)
#define OUT1  (NROW*CDIM)

// ---------------- scratch (device globals; no allocation allowed) ----------
__device__ unsigned g_h_hb  [NROW*CDIM/2];    // bf16 hi pairs (qkv A)
__device__ unsigned g_h_lb  [NROW*CDIM/2];    // bf16 lo pairs
__device__ float    g_qkv   [NROW*3*CDIM];
__device__ float    g_ao_hi [NROW*CDIM];      // aperm rounded (proj 1x)
__device__ float    g_ao_raw[NROW*CDIM];      // row-major fp32 (routing)
__device__ float    g_o     [NROW*CDIM];
__device__ float    g_xr    [NROW*CDIM];
__device__ float    g_h2    [NROW*CDIM];      // aperm
__device__ float    g_mid   [NROW*HID];       // aperm
__device__ float    g_xT    [M2*64];          // aperm rounded
__device__ float    g_bfqkv [M2*192];
__device__ float    g_bfao  [M2*64];
__device__ float    g_bfaoh [M2*64];          // aperm rounded
__device__ float    g_bf2   [M2*64];
__device__ uint4    g_qwpu  [(CDIM/16)*(3*CDIM)*4];
__device__ float4   g_pwp1  [(CDIM/16)*CDIM*4];
__device__ float4   g_bfq1  [4*192*4];
__device__ float4   g_bfo1  [4*64*4];
__device__ float4   g_fc1wp [(CDIM/16)*HID*4];
__device__ float4   g_fc2wp [(HID/16)*CDIM*4];
__device__ float    g_pwpool[CDIM*49];
__device__ float    g_pbpool[49];
__device__ float    g_pool  [NROW*49];
__device__ float    g_ar    [NB*49*49];
__device__ int      g_topk  [NB*49*4];

// ---------------- helpers ----------------------------------------------------
__device__ __forceinline__ float f2tf32f(float x) {
    unsigned r;
    asm("cvt.rna.tf32.f32 %0, %1;" : "=r"(r) : "f"(x));
    return __uint_as_float(r);
}
__device__ __forceinline__ unsigned short f2bfu(float x) {
    unsigned short u;
    asm("cvt.rn.bf16.f32 %0, %1;" : "=h"(u) : "f"(x));
    return u;
}
__device__ __forceinline__ float bfr(float x) {
    unsigned short u = f2bfu(x);
    return __uint_as_float(((unsigned)u) << 16);
}
__device__ __forceinline__ unsigned packbf(float p, float q) {
    unsigned r;
    asm("cvt.rn.bf16x2.f32 %0, %1, %2;" : "=r"(r) : "f"(q), "f"(p));
    return r;
}

// fragment-order A permutation for f32 (16row x 8k blocks of 128)
__device__ __forceinline__ size_t aperm(int row, int k, int K) {
    return ((size_t)((row >> 4) * (K >> 3) + (k >> 3)) << 7)
         + (size_t)((((row & 7) << 2) | (k & 3)) << 2)
         + (size_t)(((k & 4) >> 1) | ((row & 8) >> 3));
}
// ushort index into bf16 pair arrays (16row x 16k slabs of 128 u32)
__device__ __forceinline__ size_t bfidx(int row, int k, int K) {
    size_t u = ((size_t)((row >> 4) * (K >> 4) + (k >> 4)) << 7)
             + (size_t)(((((row & 7) << 2) | (k & 3)) << 2)
                        + (((k >> 3) & 1) << 1) + ((row >> 3) & 1));
    return u * 2 + (size_t)((k >> 2) & 1);
}

__device__ __forceinline__ void mma_tf32(float& d0, float& d1, float& d2, float& d3,
                                         unsigned a0, unsigned a1, unsigned a2, unsigned a3,
                                         unsigned b0, unsigned b1) {
    asm volatile(
        "mma.sync.aligned.m16n8k8.row.col.f32.tf32.tf32.f32 "
        "{%0,%1,%2,%3}, {%4,%5,%6,%7}, {%8,%9}, {%0,%1,%2,%3};\n"
        : "+f"(d0), "+f"(d1), "+f"(d2), "+f"(d3)
        : "r"(a0), "r"(a1), "r"(a2), "r"(a3), "r"(b0), "r"(b1));
}
__device__ __forceinline__ void mma_bf16(float& d0, float& d1, float& d2, float& d3,
                                         unsigned a0, unsigned a1, unsigned a2, unsigned a3,
                                         unsigned b0, unsigned b1) {
    asm volatile(
        "mma.sync.aligned.m16n8k16.row.col.f32.bf16.bf16.f32 "
        "{%0,%1,%2,%3}, {%4,%5,%6,%7}, {%8,%9}, {%0,%1,%2,%3};\n"
        : "+f"(d0), "+f"(d1), "+f"(d2), "+f"(d3)
        : "r"(a0), "r"(a1), "r"(a2), "r"(a3), "r"(b0), "r"(b1));
}

__device__ __forceinline__ void cp16(void* dst, const void* src, bool pred) {
    unsigned daddr = (unsigned)__cvta_generic_to_shared(dst);
    int sz = pred ? 16 : 0;
    asm volatile("cp.async.cg.shared.global [%0], [%1], 16, %2;\n"
                 :: "r"(daddr), "l"(src), "r"(sz));
}
#define CP_COMMIT() asm volatile("cp.async.commit_group;\n" ::: "memory")
#define CP_WAIT2()  asm volatile("cp.async.wait_group 2;\n" ::: "memory")

// ---------------- weight packs -----------------------------------------------
// all-bf16 3-term pack from w[K][N]: hi pairs in .x/.y, lo pairs in .z/.w
__global__ void bpack3(const float* __restrict__ w, uint4* __restrict__ ou, int K, int N) {
    int q = blockIdx.x * blockDim.x + threadIdx.x;
    int total = (K >> 4) * N * 4;
    if (q >= total) return;
    int c = q & 3, n = (q >> 2) % N, s16 = q / (4 * N);
    int k = s16 * 16 + c;
    float v0 = w[(size_t)k * N + n];
    float v1 = w[(size_t)(k + 4) * N + n];
    float v2 = w[(size_t)(k + 8) * N + n];
    float v3 = w[(size_t)(k + 12) * N + n];
    float h0 = bfr(v0), h1 = bfr(v1), h2 = bfr(v2), h3 = bfr(v3);
    ou[q] = make_uint4(packbf(h0, h1), packbf(h2, h3),
                       packbf(v0 - h0, v1 - h1), packbf(v2 - h2, v3 - h3));
}
// 1x pack from w[K][N]
__global__ void bpack1(const float* __restrict__ w, float4* __restrict__ out,
                       int K, int N) {
    int q = blockIdx.x * blockDim.x + threadIdx.x;
    int total = (K >> 4) * N * 4;
    if (q >= total) return;
    int c = q & 3, n = (q >> 2) % N, k16 = q / (4 * N);
    const float* p = w + (size_t)(k16 * 16 + c) * N + n;
    out[q] = make_float4(f2tf32f(p[0]),
                         f2tf32f(p[(size_t)4 * N]),
                         f2tf32f(p[(size_t)8 * N]),
                         f2tf32f(p[(size_t)12 * N]));
}
// 1x pack from w[N][K] (transpose during pack)
__global__ void bpack1t(const float* __restrict__ w, float4* __restrict__ out,
                        int K, int N) {
    int q = blockIdx.x * blockDim.x + threadIdx.x;
    int total = (K >> 4) * N * 4;
    if (q >= total) return;
    int c = q & 3, n = (q >> 2) % N, k16 = q / (4 * N);
    const float* p = w + (size_t)n * K + k16 * 16 + c;
    out[q] = make_float4(f2tf32f(p[0]), f2tf32f(p[4]), f2tf32f(p[8]), f2tf32f(p[12]));
}
// pooled proj weight/bias for routing sidecar
__global__ void pwp_pack(const float* __restrict__ pw, const float* __restrict__ pb,
                         float* __restrict__ pwp, float* __restrict__ pbp) {
    int e = blockIdx.x * blockDim.x + threadIdx.x;
    if (e < 784 * 49) {
        int k = e / 49, r = e % 49;
        int rh = r / 7, rw = r % 7;
        float s = 0.f;
#pragma unroll
        for (int p = 0; p < 4; p++)
#pragma unroll
            for (int q = 0; q < 4; q++)
                s += pw[(size_t)k * 784 + (rh * 4 + p) * 28 + rw * 4 + q];
        pwp[e] = s * (1.f / 16.f);
    } else if (e < 784 * 49 + 49) {
        int r = e - 784 * 49;
        int rh = r / 7, rw = r % 7;
        float s = 0.f;
#pragma unroll
        for (int p = 0; p < 4; p++)
#pragma unroll
            for (int q = 0; q < 4; q++)
                s += pb[(rh * 4 + p) * 28 + rw * 4 + q];
        pbp[r] = s * (1.f / 16.f);
    }
}

// ---------------- routing sidecar --------------------------------------------
__global__ void route_pool(const float* __restrict__ ao, const float* __restrict__ pwp,
                           const float* __restrict__ pbp, float* __restrict__ pool) {
    int row = blockIdx.x;
    __shared__ float sr[784];
    __shared__ float part[256];
    for (int i = threadIdx.x; i < 784; i += 256) sr[i] = ao[(size_t)row * 784 + i];
    __syncthreads();
    int r = threadIdx.x & 63, chunk = threadIdx.x >> 6;
    float s = 0.f;
    if (r < 49) {
        int k0 = chunk * 196;
        for (int k = k0; k < k0 + 196; k++) s = fmaf(sr[k], pwp[(size_t)k * 49 + r], s);
    }
    part[threadIdx.x] = s;
    __syncthreads();
    if (threadIdx.x < 49)
        pool[(size_t)row * 49 + threadIdx.x] =
            part[threadIdx.x] + part[64 + threadIdx.x] + part[128 + threadIdx.x]
            + part[192 + threadIdx.x] + pbp[threadIdx.x];
}

__global__ void route_score(const float* __restrict__ pool, const float* __restrict__ w,
                            const float* __restrict__ bias, float* __restrict__ ar) {
    int b = blockIdx.x;
    __shared__ float P[64][50], QR[64][50], KR[64][50];
    int tid = threadIdx.x;
    for (int e = tid; e < 64 * 49; e += 256) {
        int t = e / 49, r = e % 49;
        P[t][r] = pool[((size_t)b * 64 + t) * 49 + r];
    }
    __syncthreads();
    for (int e = tid; e < 64 * 49 * 2; e += 256) {
        int which = (e >= 64 * 49) ? 1 : 0;
        int e2 = e - which * 64 * 49;
        int oc = e2 / 49, r = e2 % 49;
        const float* wr = w + (size_t)(which * 64 + oc) * 64;
        float s = bias[which * 64 + oc];
        for (int t = 0; t < 64; t++) s = fmaf(wr[t], P[t][r], s);
        if (which) KR[oc][r] = s; else QR[oc][r] = s;
    }
    __syncthreads();
    for (int e = tid; e < 49 * 49; e += 256) {
        int r = e / 49, sc = e % 49;
        float s = 0.f;
        for (int oc = 0; oc < 64; oc++) s = fmaf(QR[oc][r], KR[oc][sc], s);
        ar[((size_t)b * 49 + r) * 49 + sc] = s;
    }
}

// ---------------- LayerNorm, aperm rounded output ----------------------------
__global__ void ln_kernel(const float* __restrict__ x, const float* __restrict__ g,
                          const float* __restrict__ b, float* __restrict__ y) {
    int row = blockIdx.x;
    const float* xr = x + (size_t)row * CDIM;
    float s = 0.f, s2 = 0.f;
    for (int i = threadIdx.x; i < CDIM; i += blockDim.x) {
        float v = xr[i]; s += v; s2 += v * v;
    }
    for (int o = 16; o; o >>= 1) {
        s  += __shfl_xor_sync(0xffffffffu, s,  o);
        s2 += __shfl_xor_sync(0xffffffffu, s2, o);
    }
    __shared__ float sh[16], sh2[16];
    int warp = threadIdx.x >> 5, lane = threadIdx.x & 31;
    if (lane == 0) { sh[warp] = s; sh2[warp] = s2; }
    __syncthreads();
    if (threadIdx.x == 0) {
        float t = 0.f, t2 = 0.f;
        int nw = blockDim.x >> 5;
        for (int i = 0; i < nw; i++) { t += sh[i]; t2 += sh2[i]; }
        sh[0] = t; sh2[0] = t2;
    }
    __syncthreads();
    float mean = sh[0] * (1.0f / CDIM);
    float var  = sh2[0] * (1.0f / CDIM) - mean * mean;
    float rinv = rsqrtf(var + 1e-5f);
    for (int i = threadIdx.x; i < CDIM; i += blockDim.x)
        y[aperm(row, i, CDIM)] = f2tf32f((xr[i] - mean) * rinv * g[i] + b[i]);
}

// ---------------- LayerNorm, native bf16 hi/lo pairs (qkv A) -----------------
__global__ void ln_split_kernel(const float* __restrict__ x, const float* __restrict__ g,
                                const float* __restrict__ b,
                                unsigned* __restrict__ hbw, unsigned* __restrict__ lbw) {
    int row = blockIdx.x;
    const float* xr = x + (size_t)row * CDIM;
    unsigned short* hb = (unsigned short*)hbw;
    unsigned short* lb = (unsigned short*)lbw;
    float s = 0.f, s2 = 0.f;
    for (int i = threadIdx.x; i < CDIM; i += blockDim.x) {
        float v = xr[i]; s += v; s2 += v * v;
    }
    for (int o = 16; o; o >>= 1) {
        s  += __shfl_xor_sync(0xffffffffu, s,  o);
        s2 += __shfl_xor_sync(0xffffffffu, s2, o);
    }
    __shared__ float sh[16], sh2[16];
    int warp = threadIdx.x >> 5, lane = threadIdx.x & 31;
    if (lane == 0) { sh[warp] = s; sh2[warp] = s2; }
    __syncthreads();
    if (threadIdx.x == 0) {
        float t = 0.f, t2 = 0.f;
        int nw = blockDim.x >> 5;
        for (int i = 0; i < nw; i++) { t += sh[i]; t2 += sh2[i]; }
        sh[0] = t; sh2[0] = t2;
    }
    __syncthreads();
    float mean = sh[0] * (1.0f / CDIM);
    float var  = sh2[0] * (1.0f / CDIM) - mean * mean;
    float rinv = rsqrtf(var + 1e-5f);
    for (int i = threadIdx.x; i < CDIM; i += blockDim.x) {
        float v = (xr[i] - mean) * rinv * g[i] + b[i];
        unsigned short hu = f2bfu(v);
        float hf = __uint_as_float(((unsigned)hu) << 16);
        size_t bi = bfidx(row, i, CDIM);
        hb[bi] = hu;
        lb[bi] = f2bfu(v - hf);
    }
}

// ---- all-bf16 3-term GEMM (qkv): ah*bh + ah*bl + al*bh, 3-stage -------------
#define S3B   4096                         // u32 per stage: HB 1024 | LB 1024 | Bu 2048
#define GS3B  (3*S3B*4)                    // 49152 bytes
__global__ void __launch_bounds__(256, 2)
gemm3b(const unsigned* __restrict__ HB, const unsigned* __restrict__ LB,
       const uint4* __restrict__ Bu, const float* __restrict__ bias,
       float* __restrict__ C, int M, int N, int K) {
    extern __shared__ unsigned smu[];
    int tid = threadIdx.x, warp = tid >> 5, lane = tid & 31;
    int wm = warp & 1, wn = warp >> 1;
    int row0 = blockIdx.y * 128, col0 = blockIdx.x * 128;
    int r = lane >> 2, c = lane & 3;
    int nk = K >> 4, K16 = K >> 4;

    float acc[4][4][4];
#pragma unroll
    for (int i = 0; i < 4; i++)
#pragma unroll
        for (int j = 0; j < 4; j++)
#pragma unroll
            for (int q = 0; q < 4; q++) acc[i][j][q] = 0.f;

#define PB(SIDX, KT) do { \
        unsigned* sa = smu + (SIDX) * S3B; \
        { \
            int b_ = tid >> 5, ln_ = tid & 31; \
            size_t g_ = ((size_t)((row0 >> 4) + b_) * K16 + (KT)) * 128 + ln_ * 4; \
            cp16(sa + b_ * 128 + ln_ * 4, HB + g_, true); \
            cp16(sa + 1024 + b_ * 128 + ln_ * 4, LB + g_, true); \
        } \
        for (int q = tid; q < 512; q += 256) { \
            int nl_ = q >> 2, cc_ = q & 3; \
            int n_ = col0 + nl_; \
            size_t g_ = ((size_t)(KT) * N + n_) * 4 + cc_; \
            cp16(sa + 2048 + q * 4, Bu + g_, n_ < N); \
        } \
    } while (0)

    PB(0, 0); CP_COMMIT();
    if (nk > 1) PB(1, 1);
    CP_COMMIT();
    if (nk > 2) PB(2, 2);
    CP_COMMIT();

    for (int kt = 0; kt < nk; kt++) {
        CP_WAIT2();
        __syncthreads();
        int s = kt % 3;
        unsigned* sa = smu + s * S3B;

        uint4 bu4[4];
#pragma unroll
        for (int nt = 0; nt < 4; nt++) {
            int nl = wn * 32 + nt * 8 + r;
            bu4[nt] = *(const uint4*)(sa + 2048 + (nl * 4 + c) * 4);
        }
#pragma unroll
        for (int mt = 0; mt < 4; mt++) {
            uint4 hb = *(const uint4*)(sa + (wm * 4 + mt) * 128 + lane * 4);
            uint4 lb = *(const uint4*)(sa + 1024 + (wm * 4 + mt) * 128 + lane * 4);
#pragma unroll
            for (int nt = 0; nt < 4; nt++) {
                mma_bf16(acc[mt][nt][0], acc[mt][nt][1], acc[mt][nt][2], acc[mt][nt][3],
                         hb.x, hb.y, hb.z, hb.w, bu4[nt].x, bu4[nt].y);
                mma_bf16(acc[mt][nt][0], acc[mt][nt][1], acc[mt][nt][2], acc[mt][nt][3],
                         hb.x, hb.y, hb.z, hb.w, bu4[nt].z, bu4[nt].w);
                mma_bf16(acc[mt][nt][0], acc[mt][nt][1], acc[mt][nt][2], acc[mt][nt][3],
                         lb.x, lb.y, lb.z, lb.w, bu4[nt].x, bu4[nt].y);
            }
        }
        __syncthreads();
        if (kt + 3 < nk) PB(s, kt + 3);
        CP_COMMIT();
    }
#undef PB

#pragma unroll
    for (int mt = 0; mt < 4; mt++) {
        int rr0 = row0 + wm * 64 + mt * 16 + r;
#pragma unroll
        for (int nt = 0; nt < 4; nt++) {
            int cb = col0 + wn * 32 + nt * 8 + 2 * c;
#pragma unroll
            for (int half = 0; half < 2; half++) {
                int rr = rr0 + half * 8;
                float v0 = acc[mt][nt][half * 2 + 0];
                float v1 = acc[mt][nt][half * 2 + 1];
                if (bias) { if (cb < N) v0 += bias[cb]; if (cb + 1 < N) v1 += bias[cb + 1]; }
                size_t base = (size_t)rr * N + cb;
                if (cb < N)     C[base]     = v0;
                if (cb + 1 < N) C[base + 1] = v1;
            }
        }
    }
}

// ---------------- 1xTF32 GEMM, fragment-permuted, 3-stage, dual-output ------
#define S1STG 4096
#define GS1V  (3*S1STG*4)
__global__ void __launch_bounds__(256, 2)
gemm1v(const float* __restrict__ A, const float4* __restrict__ Bq,
       const float* __restrict__ bias, const float* __restrict__ res,
       float* __restrict__ C, float* __restrict__ C2, const float* __restrict__ res2,
       int M, int N, int K, int act, int permC) {
    extern __shared__ float sm[];
    int tid = threadIdx.x, warp = tid >> 5, lane = tid & 31;
    int wm = warp & 1, wn = warp >> 1;
    int row0 = blockIdx.y * 128, col0 = blockIdx.x * 128;
    int r = lane >> 2, c = lane & 3;
    int nk = K >> 4, K8 = K >> 3;

    float acc[4][4][4];
#pragma unroll
    for (int i = 0; i < 4; i++)
#pragma unroll
        for (int j = 0; j < 4; j++)
#pragma unroll
            for (int q = 0; q < 4; q++) acc[i][j][q] = 0.f;

#define P1(SIDX, KT) do { \
        float* sa = sm + (SIDX) * S1STG; \
        for (int q = tid; q < 512; q += 256) { \
            int b_ = q >> 6, ks_ = (q >> 5) & 1, ln_ = q & 31; \
            size_t g_ = ((size_t)((row0 >> 4) + b_) * K8 + (KT) * 2 + ks_) * 128 + ln_ * 4; \
            cp16(sa + (b_ * 2 + ks_) * 128 + ln_ * 4, A + g_, true); \
        } \
        for (int q = tid; q < 512; q += 256) { \
            int nl_ = q >> 2, cc_ = q & 3; \
            int n_ = col0 + nl_; \
            size_t g_ = ((size_t)(KT) * N + n_) * 4 + cc_; \
            cp16(sa + 2048 + q * 4, Bq + g_, n_ < N); \
        } \
    } while (0)

    P1(0, 0); CP_COMMIT();
    if (nk > 1) P1(1, 1);
    CP_COMMIT();
    if (nk > 2) P1(2, 2);
    CP_COMMIT();

    for (int kt = 0; kt < nk; kt++) {
        CP_WAIT2();
        __syncthreads();
        int s = kt % 3;
        float* sa = sm + s * S1STG;
        float4 bq4[4];
#pragma unroll
        for (int nt = 0; nt < 4; nt++) {
            int nl = wn * 32 + nt * 8 + r;
            bq4[nt] = *(const float4*)(sa + 2048 + (nl * 4 + c) * 4);
        }
#pragma unroll
        for (int ks = 0; ks < 2; ks++) {
            float4 a4[4];
#pragma unroll
            for (int mt = 0; mt < 4; mt++) {
                int off = ((wm * 4 + mt) * 2 + ks) * 128 + lane * 4;
                a4[mt] = *(const float4*)(sa + off);
            }
#pragma unroll
            for (int mt = 0; mt < 4; mt++) {
                unsigned a0 = __float_as_uint(a4[mt].x), a1 = __float_as_uint(a4[mt].y);
                unsigned a2 = __float_as_uint(a4[mt].z), a3 = __float_as_uint(a4[mt].w);
#pragma unroll
                for (int nt = 0; nt < 4; nt++) {
                    unsigned b0 = __float_as_uint(ks == 0 ? bq4[nt].x : bq4[nt].z);
                    unsigned b1 = __float_as_uint(ks == 0 ? bq4[nt].y : bq4[nt].w);
                    mma_tf32(acc[mt][nt][0], acc[mt][nt][1], acc[mt][nt][2], acc[mt][nt][3],
                             a0, a1, a2, a3, b0, b1);
                }
            }
        }
        __syncthreads();
        if (kt + 3 < nk) P1(s, kt + 3);
        CP_COMMIT();
    }
#undef P1

#pragma unroll
    for (int mt = 0; mt < 4; mt++) {
        int rr0 = row0 + wm * 64 + mt * 16 + r;
#pragma unroll
        for (int nt = 0; nt < 4; nt++) {
            int cb = col0 + wn * 32 + nt * 8 + 2 * c;
#pragma unroll
            for (int half = 0; half < 2; half++) {
                int rr = rr0 + half * 8;
                float v0 = acc[mt][nt][half * 2 + 0];
                float v1 = acc[mt][nt][half * 2 + 1];
                if (bias) { if (cb < N) v0 += bias[cb]; if (cb + 1 < N) v1 += bias[cb + 1]; }
                if (act == 1) {
                    v0 = f2tf32f(0.5f * v0 * (1.f + erff(v0 * 0.70710678118654752f)));
                    v1 = f2tf32f(0.5f * v1 * (1.f + erff(v1 * 0.70710678118654752f)));
                }
                size_t base = (size_t)rr * N + cb;
                float w0 = v0, w1 = v1;
                if (res) { if (cb < N) w0 += res[base]; if (cb + 1 < N) w1 += res[base + 1]; }
                if (permC) {
                    if (cb < N)     C[aperm(rr, cb, N)]     = w0;
                    if (cb + 1 < N) C[aperm(rr, cb + 1, N)] = w1;
                } else {
                    if (cb < N)     C[base]     = w0;
                    if (cb + 1 < N) C[base + 1] = w1;
                }
                if (C2) {
                    float u0 = v0, u1 = v1;
                    if (res2) { if (cb < N) u0 += res2[base]; if (cb + 1 < N) u1 += res2[base + 1]; }
                    if (cb < N)     C2[base]     = u0;
                    if (cb + 1 < N) C2[base + 1] = u1;
                }
            }
        }
    }
}

// ---------------- fused main MHA: aperm rounded + raw row-major --------------
#define ATTN_SMEM ((3*64*99 + 64*64) * 4)
__global__ void attn_kernel(const float* __restrict__ qkv, float* __restrict__ oh,
                            float* __restrict__ oraw) {
    extern __shared__ float smf[];
    float* Qs = smf;
    float* Ks = Qs + 64 * 99;
    float* Vs = Ks + 64 * 99;
    float* Ss = Vs + 64 * 99;
    int b = blockIdx.x >> 3;
    int h = blockIdx.x & 7;
    const float* base = qkv + (size_t)b * 64 * (3 * CDIM) + h * HD;

    for (int e = threadIdx.x; e < 64 * HD; e += blockDim.x) {
        int r = e / HD, d = e % HD;
        const float* rp = base + (size_t)r * (3 * CDIM) + d;
        Qs[r * 99 + d] = rp[0];
        Ks[r * 99 + d] = rp[CDIM];
        Vs[r * 99 + d] = rp[2 * CDIM];
    }
    __syncthreads();

    const float scale = 1.0f / sqrtf(98.0f);
    for (int e = threadIdx.x; e < 4096; e += blockDim.x) {
        int i = e >> 6, j = e & 63;
        const float* qi = Qs + i * 99;
        const float* kj = Ks + j * 99;
        float a = 0.f;
#pragma unroll
        for (int d = 0; d < HD; d++) a = fmaf(qi[d], kj[d], a);
        Ss[e] = a * scale;
    }
    __syncthreads();

    int warp = threadIdx.x >> 5, lane = threadIdx.x & 31;
    for (int i = warp; i < 64; i += 8) {
        float v0 = Ss[i * 64 + lane], v1 = Ss[i * 64 + lane + 32];
        float mx = fmaxf(v0, v1);
        for (int o = 16; o; o >>= 1) mx = fmaxf(mx, __shfl_xor_sync(0xffffffffu, mx, o));
        float e0 = __expf(v0 - mx), e1 = __expf(v1 - mx);
        float s = e0 + e1;
        for (int o = 16; o; o >>= 1) s += __shfl_xor_sync(0xffffffffu, s, o);
        float inv = 1.f / s;
        Ss[i * 64 + lane]      = e0 * inv;
        Ss[i * 64 + lane + 32] = e1 * inv;
    }
    __syncthreads();

    for (int e = threadIdx.x; e < 64 * HD; e += blockDim.x) {
        int i = e / HD, d = e % HD;
        const float* p = Ss + i * 64;
        float a = 0.f;
#pragma unroll
        for (int j = 0; j < 64; j++) a = fmaf(p[j], Vs[j * 99 + d], a);
        int row = b * 64 + i, k = h * HD + d;
        oraw[(size_t)row * CDIM + k] = a;
        oh[aperm(row, k, CDIM)] = f2tf32f(a);
    }
}

// ---------------- transpose to aperm rounded ---------------------------------
__global__ void transpose_round_kernel(const float* __restrict__ in, float* __restrict__ oh) {
    __shared__ float tile[32][33];
    int b = blockIdx.z;
    int r0 = blockIdx.y * 32, c0 = blockIdx.x * 32;
    const float* ib = in + (size_t)b * 64 * 784;
    int r = r0 + threadIdx.y, c = c0 + threadIdx.x;
    if (r < 64 && c < 784) tile[threadIdx.y][threadIdx.x] = ib[(size_t)r * 784 + c];
    __syncthreads();
    int rr = r0 + threadIdx.x, cc = c0 + threadIdx.y;
    if (rr < 64 && cc < 784)
        oh[aperm(b * 784 + cc, rr, 64)] = f2tf32f(tile[threadIdx.x][threadIdx.y]);
}

// ---------------- plain transpose --------------------------------------------
__global__ void transpose_kernel(const float* __restrict__ in, float* __restrict__ out,
                                 int R, int Cc) {
    __shared__ float tile[32][33];
    int b = blockIdx.z;
    int r0 = blockIdx.y * 32, c0 = blockIdx.x * 32;
    const float* ib = in + (size_t)b * R * Cc;
    float* ob = out + (size_t)b * R * Cc;
    int r = r0 + threadIdx.y, c = c0 + threadIdx.x;
    if (r < R && c < Cc) tile[threadIdx.y][threadIdx.x] = ib[(size_t)r * Cc + c];
    __syncthreads();
    int rr = r0 + threadIdx.x, cc = c0 + threadIdx.y;
    if (rr < R && cc < Cc) ob[(size_t)cc * R + rr] = tile[threadIdx.x][threadIdx.y];
}

// ---------------- top-4 per (b, r) --------------------------------------------
__global__ void bf_topk_kernel(const float* __restrict__ ar, int* __restrict__ idx) {
    int t = blockIdx.x * blockDim.x + threadIdx.x;
    if (t >= NB * 49) return;
    float v[49];
    const float* row = ar + (size_t)t * 49;
#pragma unroll
    for (int s = 0; s < 49; s++) v[s] = row[s];
    for (int k = 0; k < 4; k++) {
        float best = -3.4e38f; int bi = 0;
        for (int s = 0; s < 49; s++)
            if (v[s] > best) { best = v[s]; bi = s; }
        idx[t * 4 + k] = bi;
        v[bi] = -3.4e38f;
    }
}

// ---------------- BiFormer region attention ------------------------------------
__global__ void bf_attn_kernel(const float* __restrict__ qkvt, const int* __restrict__ idx,
                               float* __restrict__ ao) {
    __shared__ float Qs[16][8], Ks[64][9], Vs[64][9], S[16][64];
    __shared__ int sreg[4];
    int r = blockIdx.x % 49;
    int m = (blockIdx.x / 49) & 7;
    int b = blockIdx.x / (49 * 8);
    int tid = threadIdx.x;
    int rh = r / 7, rw = r % 7;

    if (tid < 4) sreg[tid] = idx[((size_t)b * 49 + r) * 4 + tid];
    {
        int p = tid >> 3, d = tid & 7;
        int hw = (rh * 4 + (p >> 2)) * 28 + rw * 4 + (p & 3);
        Qs[p][d] = qkvt[((size_t)b * 784 + hw) * 192 + m * 8 + d];
    }
    __syncthreads();

    for (int e = tid; e < 512; e += 128) {
        int slot = e >> 3, d = e & 7;
        int t = slot >> 4, s = slot & 15;
        int sr = sreg[t];
        int hw = ((sr / 7) * 4 + (s >> 2)) * 28 + (sr % 7) * 4 + (s & 3);
        const float* p = qkvt + ((size_t)b * 784 + hw) * 192 + m * 8 + d;
        Ks[slot][d] = p[64];
        Vs[slot][d] = p[128];
    }
    __syncthreads();

    for (int e = tid; e < 1024; e += 128) {
        int i = e >> 6, j = e & 63;
        float a = 0.f;
#pragma unroll
        for (int d = 0; d < 8; d++) a = fmaf(Qs[i][d], Ks[j][d], a);
        S[i][j] = a * 0.125f;
    }
    __syncthreads();

    int warp = tid >> 5, lane = tid & 31;
    for (int i = warp; i < 16; i += 4) {
        float v0 = S[i][lane], v1 = S[i][lane + 32];
        float mx = fmaxf(v0, v1);
        for (int o = 16; o; o >>= 1) mx = fmaxf(mx, __shfl_xor_sync(0xffffffffu, mx, o));
        float e0 = __expf(v0 - mx), e1 = __expf(v1 - mx);
        float s = e0 + e1;
        for (int o = 16; o; o >>= 1) s += __shfl_xor_sync(0xffffffffu, s, o);
        float inv = 1.f / s;
        S[i][lane] = e0 * inv;
        S[i][lane + 32] = e1 * inv;
    }
    __syncthreads();

    {
        int i = tid >> 3, d = tid & 7;
        float a = 0.f;
#pragma unroll
        for (int j = 0; j < 64; j++) a = fmaf(S[i][j], Vs[j][d], a);
        int hw = (rh * 4 + (i >> 2)) * 28 + rw * 4 + (i & 3);
        ao[((size_t)b * 784 + hw) * 64 + m * 8 + d] = a;
    }
}

// ---------------- LePE: dw conv add, aperm rounded output --------------------
__global__ void bf_lepe_round_kernel(const float* __restrict__ qkvt,
                                     const float* __restrict__ w,
                                     const float* __restrict__ bias,
                                     const float* __restrict__ ao, float* __restrict__ aoh) {
    int e = blockIdx.x * blockDim.x + threadIdx.x;
    if (e >= NB * 784 * 64) return;
    int c  = e & 63;
    int hw = (e >> 6) % 784;
    int b  = e / (784 * 64);
    int h = hw / 28, wq = hw % 28;
    float acc = bias[c];
#pragma unroll
    for (int i = 0; i < 3; i++) {
        int hh = h + i - 1;
        if (hh < 0 || hh >= 28) continue;
#pragma unroll
        for (int j = 0; j < 3; j++) {
            int ww = wq + j - 1;
            if (ww < 0 || ww >= 28) continue;
            acc = fmaf(qkvt[((size_t)b * 784 + hh * 28 + ww) * 192 + 128 + c],
                       w[c * 9 + i * 3 + j], acc);
        }
    }
    aoh[aperm(b * 784 + hw, c, 64)] = f2tf32f(ao[e] + acc);
}

// ============================================================================
extern "C" void kernel_launch(void* const* d_in, const int* in_sizes, int n_in,
                              void* d_out, int out_size) {
    const float* x        = (const float*)d_in[0];
    const float* n1g      = (const float*)d_in[1];
    const float* n1b      = (const float*)d_in[2];
    const float* qkv_w    = (const float*)d_in[3];
    const float* proj_w   = (const float*)d_in[4];
    const float* proj_b   = (const float*)d_in[5];
    const float* n2g      = (const float*)d_in[6];
    const float* n2b      = (const float*)d_in[7];
    const float* fc1_w    = (const float*)d_in[8];
    const float* fc1_b    = (const float*)d_in[9];
    const float* fc2_w    = (const float*)d_in[10];
    const float* fc2_b    = (const float*)d_in[11];
    const float* bfqkv_w  = (const float*)d_in[12];
    const float* bfqkv_b  = (const float*)d_in[13];
    const float* bflepe_w = (const float*)d_in[14];
    const float* bflepe_b = (const float*)d_in[15];
    const float* bfout_w  = (const float*)d_in[16];
    const float* bfout_b  = (const float*)d_in[17];
    float* out = (float*)d_out;

    float *p_qkv, *p_aoh, *p_aoraw, *p_o, *p_xr, *p_h2, *p_mid;
    float *p_xT, *p_bfqkv, *p_bfao, *p_bfaoh, *p_bf2;
    unsigned *p_hhb, *p_hlb;
    float4 *p_pwp1, *p_bfq1, *p_bfo1, *p_fc1wp, *p_fc2wp;
    uint4 *p_qwpu;
    float *p_pwpool, *p_pbpool, *p_pool, *p_ar;
    int* p_idx;
    cudaGetSymbolAddress((void**)&p_hhb,    g_h_hb);
    cudaGetSymbolAddress((void**)&p_hlb,    g_h_lb);
    cudaGetSymbolAddress((void**)&p_qkv,    g_qkv);
    cudaGetSymbolAddress((void**)&p_aoh,    g_ao_hi);
    cudaGetSymbolAddress((void**)&p_aoraw,  g_ao_raw);
    cudaGetSymbolAddress((void**)&p_o,      g_o);
    cudaGetSymbolAddress((void**)&p_xr,     g_xr);
    cudaGetSymbolAddress((void**)&p_h2,     g_h2);
    cudaGetSymbolAddress((void**)&p_mid,    g_mid);
    cudaGetSymbolAddress((void**)&p_xT,     g_xT);
    cudaGetSymbolAddress((void**)&p_bfqkv,  g_bfqkv);
    cudaGetSymbolAddress((void**)&p_bfao,   g_bfao);
    cudaGetSymbolAddress((void**)&p_bfaoh,  g_bfaoh);
    cudaGetSymbolAddress((void**)&p_bf2,    g_bf2);
    cudaGetSymbolAddress((void**)&p_qwpu,   g_qwpu);
    cudaGetSymbolAddress((void**)&p_pwp1,   g_pwp1);
    cudaGetSymbolAddress((void**)&p_bfq1,   g_bfq1);
    cudaGetSymbolAddress((void**)&p_bfo1,   g_bfo1);
    cudaGetSymbolAddress((void**)&p_fc1wp,  g_fc1wp);
    cudaGetSymbolAddress((void**)&p_fc2wp,  g_fc2wp);
    cudaGetSymbolAddress((void**)&p_pwpool, g_pwpool);
    cudaGetSymbolAddress((void**)&p_pbpool, g_pbpool);
    cudaGetSymbolAddress((void**)&p_pool,   g_pool);
    cudaGetSymbolAddress((void**)&p_ar,     g_ar);
    cudaGetSymbolAddress((void**)&p_idx,    g_topk);

    cudaFuncSetAttribute(attn_kernel, cudaFuncAttributeMaxDynamicSharedMemorySize, ATTN_SMEM);
    cudaFuncSetAttribute(gemm3b, cudaFuncAttributeMaxDynamicSharedMemorySize, GS3B);
    cudaFuncSetAttribute(gemm1v, cudaFuncAttributeMaxDynamicSharedMemorySize, GS1V);

    static cudaStream_t s2 = nullptr;
    static cudaEvent_t evA = nullptr, evB = nullptr, evC = nullptr, evD = nullptr, evE = nullptr;
    if (s2 == nullptr) {
        cudaStreamCreateWithFlags(&s2, cudaStreamNonBlocking);
        cudaEventCreateWithFlags(&evA, cudaEventDisableTiming);
        cudaEventCreateWithFlags(&evB, cudaEventDisableTiming);
        cudaEventCreateWithFlags(&evC, cudaEventDisableTiming);
        cudaEventCreateWithFlags(&evD, cudaEventDisableTiming);
        cudaEventCreateWithFlags(&evE, cudaEventDisableTiming);
    }

    // ---- fork #1: weight packs + routing-weight pool on s2 ----
    cudaEventRecord(evA, 0);
    cudaStreamWaitEvent(s2, evA, 0);

    bpack3<<<(49 * 2352 * 4 + 255) / 256, 256>>>(qkv_w, p_qwpu, CDIM, 3 * CDIM);
    ln_split_kernel<<<NROW, 256>>>(x, n1g, n1b, p_hhb, p_hlb);

    pwp_pack<<<(784 * 49 + 49 + 255) / 256, 256, 0, s2>>>(proj_w, proj_b, p_pwpool, p_pbpool);
    bpack1 <<<(49 * 784 * 4 + 255) / 256, 256, 0, s2>>>(proj_w, p_pwp1, CDIM, CDIM);
    bpack1t<<<(4 * 192 * 4 + 255) / 256, 256, 0, s2>>>(bfqkv_w, p_bfq1, 64, 192);
    bpack1t<<<(4 * 64 * 4 + 255) / 256, 256, 0, s2>>>(bfout_w, p_bfo1, 64, 64);
    bpack1 <<<(49 * 3136 * 4 + 255) / 256, 256, 0, s2>>>(fc1_w, p_fc1wp, CDIM, HID);
    bpack1 <<<(196 * 784 * 4 + 255) / 256, 256, 0, s2>>>(fc2_w, p_fc2wp, HID, CDIM);
    cudaEventRecord(evB, s2);

    gemm3b<<<dim3(19, 64), 256, GS3B>>>(p_hhb, p_hlb, p_qwpu, nullptr, p_qkv,
                                        NROW, 3 * CDIM, CDIM);
    attn_kernel<<<NB * NHD, 256, ATTN_SMEM>>>(p_qkv, p_aoh, p_aoraw);
    cudaEventRecord(evE, 0);

    // routing sidecar on s2 (exact fp32 from actual attn output)
    cudaStreamWaitEvent(s2, evE, 0);
    route_pool<<<NROW, 256, 0, s2>>>(p_aoraw, p_pwpool, p_pbpool, p_pool);
    route_score<<<NB, 256, 0, s2>>>(p_pool, bfqkv_w, bfqkv_b, p_ar);
    bf_topk_kernel<<<(NB * 49 + 255) / 256, 256, 0, s2>>>(p_ar, p_idx);

    // proj (1x) on main; dual output o + xr = o + x
    cudaStreamWaitEvent(0, evB, 0);
    gemm1v<<<dim3(7, 64), 256, GS1V>>>(p_aoh, p_pwp1, proj_b, nullptr,
                                       p_o, p_xr, x, NROW, CDIM, CDIM, 0, 0);

    // ---- fork #2: BiFormer values on s2, MLP on main ----
    cudaEventRecord(evC, 0);
    cudaStreamWaitEvent(s2, evC, 0);

    transpose_round_kernel<<<dim3(25, 2, NB), dim3(32, 32), 0, s2>>>(p_o, p_xT);
    gemm1v<<<dim3(2, M2 / 128), 256, GS1V, s2>>>(p_xT, p_bfq1, bfqkv_b, nullptr,
                                                 p_bfqkv, nullptr, nullptr, M2, 192, 64, 0, 0);
    bf_attn_kernel<<<NB * 8 * 49, 128, 0, s2>>>(p_bfqkv, p_idx, p_bfao);
    bf_lepe_round_kernel<<<(NB * 784 * 64 + 255) / 256, 256, 0, s2>>>(p_bfqkv, bflepe_w,
                                                                      bflepe_b, p_bfao, p_bfaoh);
    gemm1v<<<dim3(1, M2 / 128), 256, GS1V, s2>>>(p_bfaoh, p_bfo1, bfout_b, nullptr,
                                                 p_bf2, nullptr, nullptr, M2, 64, 64, 0, 0);
    transpose_kernel<<<dim3(2, 25, NB), dim3(32, 32), 0, s2>>>(p_bf2, out + OUT1, 784, 64);
    cudaEventRecord(evD, s2);

    ln_kernel<<<NROW, 256>>>(p_xr, n2g, n2b, p_h2);
    gemm1v<<<dim3(25, 64), 256, GS1V>>>(p_h2, p_fc1wp, fc1_b, nullptr, p_mid,
                                        nullptr, nullptr, NROW, HID, CDIM, 1, 1);
    gemm1v<<<dim3(7, 64), 256, GS1V>>>(p_mid, p_fc2wp, fc2_b, p_xr, out,
                                       nullptr, nullptr, NROW, CDIM, HID, 0, 0);

    cudaStreamWaitEvent(0, evD, 0);
}

// round 16
// speedup vs baseline: 1.6591x; 1.2735x over previous
#include <cuda_runtime.h>
#include <math.h>
#include <stdint.h>

#define NB    128
#define NTOKN 64
#define CDIM  784
#define NHD   8
#define HD    98
#define HID   3136
#define NROW  (NB*NTOKN)
#define M2    (NB*784)
#define OUT1  (NROW*CDIM)

// ---------------- scratch (device globals; no allocation allowed) ----------
__device__ unsigned g_h_hb  [NROW*CDIM/2];    // bf16 hi pairs (qkv A)
__device__ unsigned g_h_lb  [NROW*CDIM/2];    // bf16 lo pairs
__device__ float    g_qkv   [NROW*3*CDIM];
__device__ unsigned g_aohh  [NROW*CDIM/2];    // fp16 pairs (proj A)
__device__ float    g_ao_raw[NROW*CDIM];      // row-major fp32 (routing)
__device__ float    g_o     [NROW*CDIM];
__device__ float    g_xr    [NROW*CDIM];
__device__ unsigned g_h2h   [NROW*CDIM/2];    // fp16 pairs (fc1 A)
__device__ unsigned g_midh  [NROW*HID/2];     // fp16 pairs (fc2 A)
__device__ unsigned g_xTh   [M2*64/2];        // fp16 pairs (bfqkv A)
__device__ float    g_bfqkv [M2*192];
__device__ float    g_bfao  [M2*64];
__device__ unsigned g_bfaohh[M2*64/2];        // fp16 pairs (bfout A)
__device__ float    g_bf2   [M2*64];
__device__ uint4    g_qwpu  [(CDIM/16)*(3*CDIM)*4];
__device__ uint4    g_pwph  [(CDIM/16)*CDIM*2];
__device__ uint4    g_bfqh  [4*192*2];
__device__ uint4    g_bfoh  [4*64*2];
__device__ uint4    g_fc1h  [(CDIM/16)*HID*2];
__device__ uint4    g_fc2h  [(HID/16)*CDIM*2];
__device__ float    g_pwpool[CDIM*49];
__device__ float    g_pbpool[49];
__device__ float    g_pool  [NROW*49];
__device__ float    g_ar    [NB*49*49];
__device__ int      g_topk  [NB*49*4];

// ---------------- helpers ----------------------------------------------------
__device__ __forceinline__ unsigned short f2bfu(float x) {
    unsigned short u;
    asm("cvt.rn.bf16.f32 %0, %1;" : "=h"(u) : "f"(x));
    return u;
}
__device__ __forceinline__ unsigned short f2hu(float x) {
    unsigned short u;
    asm("cvt.rn.f16.f32 %0, %1;" : "=h"(u) : "f"(x));
    return u;
}
__device__ __forceinline__ unsigned packbf(float p, float q) {
    unsigned r;
    asm("cvt.rn.bf16x2.f32 %0, %1, %2;" : "=r"(r) : "f"(q), "f"(p));
    return r;
}
__device__ __forceinline__ unsigned packh(float p, float q) {
    unsigned r;
    asm("cvt.rn.f16x2.f32 %0, %1, %2;" : "=r"(r) : "f"(q), "f"(p));
    return r;
}
__device__ __forceinline__ float bfr(float x) {
    return __uint_as_float(((unsigned)f2bfu(x)) << 16);
}

// ushort index into 16-bit pair arrays (16row x 16k slabs of 128 u32)
__device__ __forceinline__ size_t bfidx(int row, int k, int K) {
    size_t u = ((size_t)((row >> 4) * (K >> 4) + (k >> 4)) << 7)
             + (size_t)(((((row & 7) << 2) | (k & 3)) << 2)
                        + (((k >> 3) & 1) << 1) + ((row >> 3) & 1));
    return u * 2 + (size_t)((k >> 2) & 1);
}

__device__ __forceinline__ void mma_bf16(float& d0, float& d1, float& d2, float& d3,
                                         unsigned a0, unsigned a1, unsigned a2, unsigned a3,
                                         unsigned b0, unsigned b1) {
    asm volatile(
        "mma.sync.aligned.m16n8k16.row.col.f32.bf16.bf16.f32 "
        "{%0,%1,%2,%3}, {%4,%5,%6,%7}, {%8,%9}, {%0,%1,%2,%3};\n"
        : "+f"(d0), "+f"(d1), "+f"(d2), "+f"(d3)
        : "r"(a0), "r"(a1), "r"(a2), "r"(a3), "r"(b0), "r"(b1));
}
__device__ __forceinline__ void mma_f16(float& d0, float& d1, float& d2, float& d3,
                                        unsigned a0, unsigned a1, unsigned a2, unsigned a3,
                                        unsigned b0, unsigned b1) {
    asm volatile(
        "mma.sync.aligned.m16n8k16.row.col.f32.f16.f16.f32 "
        "{%0,%1,%2,%3}, {%4,%5,%6,%7}, {%8,%9}, {%0,%1,%2,%3};\n"
        : "+f"(d0), "+f"(d1), "+f"(d2), "+f"(d3)
        : "r"(a0), "r"(a1), "r"(a2), "r"(a3), "r"(b0), "r"(b1));
}

__device__ __forceinline__ void cp16(void* dst, const void* src, bool pred) {
    unsigned daddr = (unsigned)__cvta_generic_to_shared(dst);
    int sz = pred ? 16 : 0;
    asm volatile("cp.async.cg.shared.global [%0], [%1], 16, %2;\n"
                 :: "r"(daddr), "l"(src), "r"(sz));
}
#define CP_COMMIT() asm volatile("cp.async.commit_group;\n" ::: "memory")
#define CP_WAIT2()  asm volatile("cp.async.wait_group 2;\n" ::: "memory")

// ---------------- weight packs -----------------------------------------------
// all-bf16 3-term pack (qkv) from w[K][N]
__global__ void bpack3(const float* __restrict__ w, uint4* __restrict__ ou, int K, int N) {
    int q = blockIdx.x * blockDim.x + threadIdx.x;
    int total = (K >> 4) * N * 4;
    if (q >= total) return;
    int c = q & 3, n = (q >> 2) % N, s16 = q / (4 * N);
    int k = s16 * 16 + c;
    float v0 = w[(size_t)k * N + n];
    float v1 = w[(size_t)(k + 4) * N + n];
    float v2 = w[(size_t)(k + 8) * N + n];
    float v3 = w[(size_t)(k + 12) * N + n];
    float h0 = bfr(v0), h1 = bfr(v1), h2 = bfr(v2), h3 = bfr(v3);
    ou[q] = make_uint4(packbf(h0, h1), packbf(h2, h3),
                       packbf(v0 - h0, v1 - h1), packbf(v2 - h2, v3 - h3));
}
// fp16 1x pack from w[K][N]: per (k16, n, j) two c-columns
__global__ void bpack1h(const float* __restrict__ w, uint4* __restrict__ out,
                        int K, int N) {
    int q = blockIdx.x * blockDim.x + threadIdx.x;
    int total = (K >> 4) * N * 2;
    if (q >= total) return;
    int j = q & 1, n = (q >> 1) % N, k16 = (q >> 1) / N;
    const float* p0 = w + (size_t)(k16 * 16 + 2 * j) * N + n;
    const float* p1 = w + (size_t)(k16 * 16 + 2 * j + 1) * N + n;
    out[q] = make_uint4(packh(p0[0], p0[(size_t)4 * N]),
                        packh(p0[(size_t)8 * N], p0[(size_t)12 * N]),
                        packh(p1[0], p1[(size_t)4 * N]),
                        packh(p1[(size_t)8 * N], p1[(size_t)12 * N]));
}
// fp16 1x pack from w[N][K]
__global__ void bpack1th(const float* __restrict__ w, uint4* __restrict__ out,
                         int K, int N) {
    int q = blockIdx.x * blockDim.x + threadIdx.x;
    int total = (K >> 4) * N * 2;
    if (q >= total) return;
    int j = q & 1, n = (q >> 1) % N, k16 = (q >> 1) / N;
    const float* p0 = w + (size_t)n * K + k16 * 16 + 2 * j;
    const float* p1 = p0 + 1;
    out[q] = make_uint4(packh(p0[0], p0[4]), packh(p0[8], p0[12]),
                        packh(p1[0], p1[4]), packh(p1[8], p1[12]));
}
// pooled proj weight/bias for routing sidecar
__global__ void pwp_pack(const float* __restrict__ pw, const float* __restrict__ pb,
                         float* __restrict__ pwp, float* __restrict__ pbp) {
    int e = blockIdx.x * blockDim.x + threadIdx.x;
    if (e < 784 * 49) {
        int k = e / 49, r = e % 49;
        int rh = r / 7, rw = r % 7;
        float s = 0.f;
#pragma unroll
        for (int p = 0; p < 4; p++)
#pragma unroll
            for (int q = 0; q < 4; q++)
                s += pw[(size_t)k * 784 + (rh * 4 + p) * 28 + rw * 4 + q];
        pwp[e] = s * (1.f / 16.f);
    } else if (e < 784 * 49 + 49) {
        int r = e - 784 * 49;
        int rh = r / 7, rw = r % 7;
        float s = 0.f;
#pragma unroll
        for (int p = 0; p < 4; p++)
#pragma unroll
            for (int q = 0; q < 4; q++)
                s += pb[(rh * 4 + p) * 28 + rw * 4 + q];
        pbp[r] = s * (1.f / 16.f);
    }
}

// ---------------- routing sidecar --------------------------------------------
__global__ void route_pool(const float* __restrict__ ao, const float* __restrict__ pwp,
                           const float* __restrict__ pbp, float* __restrict__ pool) {
    int row = blockIdx.x;
    __shared__ float sr[784];
    __shared__ float part[256];
    for (int i = threadIdx.x; i < 784; i += 256) sr[i] = ao[(size_t)row * 784 + i];
    __syncthreads();
    int r = threadIdx.x & 63, chunk = threadIdx.x >> 6;
    float s = 0.f;
    if (r < 49) {
        int k0 = chunk * 196;
        for (int k = k0; k < k0 + 196; k++) s = fmaf(sr[k], pwp[(size_t)k * 49 + r], s);
    }
    part[threadIdx.x] = s;
    __syncthreads();
    if (threadIdx.x < 49)
        pool[(size_t)row * 49 + threadIdx.x] =
            part[threadIdx.x] + part[64 + threadIdx.x] + part[128 + threadIdx.x]
            + part[192 + threadIdx.x] + pbp[threadIdx.x];
}

__global__ void route_score(const float* __restrict__ pool, const float* __restrict__ w,
                            const float* __restrict__ bias, float* __restrict__ ar) {
    int b = blockIdx.x;
    __shared__ float P[64][50], QR[64][50], KR[64][50];
    int tid = threadIdx.x;
    for (int e = tid; e < 64 * 49; e += 256) {
        int t = e / 49, r = e % 49;
        P[t][r] = pool[((size_t)b * 64 + t) * 49 + r];
    }
    __syncthreads();
    for (int e = tid; e < 64 * 49 * 2; e += 256) {
        int which = (e >= 64 * 49) ? 1 : 0;
        int e2 = e - which * 64 * 49;
        int oc = e2 / 49, r = e2 % 49;
        const float* wr = w + (size_t)(which * 64 + oc) * 64;
        float s = bias[which * 64 + oc];
        for (int t = 0; t < 64; t++) s = fmaf(wr[t], P[t][r], s);
        if (which) KR[oc][r] = s; else QR[oc][r] = s;
    }
    __syncthreads();
    for (int e = tid; e < 49 * 49; e += 256) {
        int r = e / 49, sc = e % 49;
        float s = 0.f;
        for (int oc = 0; oc < 64; oc++) s = fmaf(QR[oc][r], KR[oc][sc], s);
        ar[((size_t)b * 49 + r) * 49 + sc] = s;
    }
}

// ---------------- LayerNorm, fp16 pair output --------------------------------
__global__ void ln_h_kernel(const float* __restrict__ x, const float* __restrict__ g,
                            const float* __restrict__ b, unsigned* __restrict__ yw) {
    int row = blockIdx.x;
    const float* xr = x + (size_t)row * CDIM;
    unsigned short* y = (unsigned short*)yw;
    float s = 0.f, s2 = 0.f;
    for (int i = threadIdx.x; i < CDIM; i += blockDim.x) {
        float v = xr[i]; s += v; s2 += v * v;
    }
    for (int o = 16; o; o >>= 1) {
        s  += __shfl_xor_sync(0xffffffffu, s,  o);
        s2 += __shfl_xor_sync(0xffffffffu, s2, o);
    }
    __shared__ float sh[16], sh2[16];
    int warp = threadIdx.x >> 5, lane = threadIdx.x & 31;
    if (lane == 0) { sh[warp] = s; sh2[warp] = s2; }
    __syncthreads();
    if (threadIdx.x == 0) {
        float t = 0.f, t2 = 0.f;
        int nw = blockDim.x >> 5;
        for (int i = 0; i < nw; i++) { t += sh[i]; t2 += sh2[i]; }
        sh[0] = t; sh2[0] = t2;
    }
    __syncthreads();
    float mean = sh[0] * (1.0f / CDIM);
    float var  = sh2[0] * (1.0f / CDIM) - mean * mean;
    float rinv = rsqrtf(var + 1e-5f);
    for (int i = threadIdx.x; i < CDIM; i += blockDim.x)
        y[bfidx(row, i, CDIM)] = f2hu((xr[i] - mean) * rinv * g[i] + b[i]);
}

// ---------------- LayerNorm, native bf16 hi/lo pairs (qkv A) -----------------
__global__ void ln_split_kernel(const float* __restrict__ x, const float* __restrict__ g,
                                const float* __restrict__ b,
                                unsigned* __restrict__ hbw, unsigned* __restrict__ lbw) {
    int row = blockIdx.x;
    const float* xr = x + (size_t)row * CDIM;
    unsigned short* hb = (unsigned short*)hbw;
    unsigned short* lb = (unsigned short*)lbw;
    float s = 0.f, s2 = 0.f;
    for (int i = threadIdx.x; i < CDIM; i += blockDim.x) {
        float v = xr[i]; s += v; s2 += v * v;
    }
    for (int o = 16; o; o >>= 1) {
        s  += __shfl_xor_sync(0xffffffffu, s,  o);
        s2 += __shfl_xor_sync(0xffffffffu, s2, o);
    }
    __shared__ float sh[16], sh2[16];
    int warp = threadIdx.x >> 5, lane = threadIdx.x & 31;
    if (lane == 0) { sh[warp] = s; sh2[warp] = s2; }
    __syncthreads();
    if (threadIdx.x == 0) {
        float t = 0.f, t2 = 0.f;
        int nw = blockDim.x >> 5;
        for (int i = 0; i < nw; i++) { t += sh[i]; t2 += sh2[i]; }
        sh[0] = t; sh2[0] = t2;
    }
    __syncthreads();
    float mean = sh[0] * (1.0f / CDIM);
    float var  = sh2[0] * (1.0f / CDIM) - mean * mean;
    float rinv = rsqrtf(var + 1e-5f);
    for (int i = threadIdx.x; i < CDIM; i += blockDim.x) {
        float v = (xr[i] - mean) * rinv * g[i] + b[i];
        unsigned short hu = f2bfu(v);
        float hf = __uint_as_float(((unsigned)hu) << 16);
        size_t bi = bfidx(row, i, CDIM);
        hb[bi] = hu;
        lb[bi] = f2bfu(v - hf);
    }
}

// ---- all-bf16 3-term GEMM (qkv): ah*bh + ah*bl + al*bh, 3-stage -------------
#define S3B   4096
#define GS3B  (3*S3B*4)
__global__ void __launch_bounds__(256, 2)
gemm3b(const unsigned* __restrict__ HB, const unsigned* __restrict__ LB,
       const uint4* __restrict__ Bu, const float* __restrict__ bias,
       float* __restrict__ C, int M, int N, int K) {
    extern __shared__ unsigned smu[];
    int tid = threadIdx.x, warp = tid >> 5, lane = tid & 31;
    int wm = warp & 1, wn = warp >> 1;
    int row0 = blockIdx.y * 128, col0 = blockIdx.x * 128;
    int r = lane >> 2, c = lane & 3;
    int nk = K >> 4, K16 = K >> 4;

    float acc[4][4][4];
#pragma unroll
    for (int i = 0; i < 4; i++)
#pragma unroll
        for (int j = 0; j < 4; j++)
#pragma unroll
            for (int q = 0; q < 4; q++) acc[i][j][q] = 0.f;

#define PB(SIDX, KT) do { \
        unsigned* sa = smu + (SIDX) * S3B; \
        { \
            int b_ = tid >> 5, ln_ = tid & 31; \
            size_t g_ = ((size_t)((row0 >> 4) + b_) * K16 + (KT)) * 128 + ln_ * 4; \
            cp16(sa + b_ * 128 + ln_ * 4, HB + g_, true); \
            cp16(sa + 1024 + b_ * 128 + ln_ * 4, LB + g_, true); \
        } \
        for (int q = tid; q < 512; q += 256) { \
            int nl_ = q >> 2, cc_ = q & 3; \
            int n_ = col0 + nl_; \
            size_t g_ = ((size_t)(KT) * N + n_) * 4 + cc_; \
            cp16(sa + 2048 + q * 4, Bu + g_, n_ < N); \
        } \
    } while (0)

    PB(0, 0); CP_COMMIT();
    if (nk > 1) PB(1, 1);
    CP_COMMIT();
    if (nk > 2) PB(2, 2);
    CP_COMMIT();

    for (int kt = 0; kt < nk; kt++) {
        CP_WAIT2();
        __syncthreads();
        int s = kt % 3;
        unsigned* sa = smu + s * S3B;

        uint4 bu4[4];
#pragma unroll
        for (int nt = 0; nt < 4; nt++) {
            int nl = wn * 32 + nt * 8 + r;
            bu4[nt] = *(const uint4*)(sa + 2048 + (nl * 4 + c) * 4);
        }
#pragma unroll
        for (int mt = 0; mt < 4; mt++) {
            uint4 hb = *(const uint4*)(sa + (wm * 4 + mt) * 128 + lane * 4);
            uint4 lb = *(const uint4*)(sa + 1024 + (wm * 4 + mt) * 128 + lane * 4);
#pragma unroll
            for (int nt = 0; nt < 4; nt++) {
                mma_bf16(acc[mt][nt][0], acc[mt][nt][1], acc[mt][nt][2], acc[mt][nt][3],
                         hb.x, hb.y, hb.z, hb.w, bu4[nt].x, bu4[nt].y);
                mma_bf16(acc[mt][nt][0], acc[mt][nt][1], acc[mt][nt][2], acc[mt][nt][3],
                         hb.x, hb.y, hb.z, hb.w, bu4[nt].z, bu4[nt].w);
                mma_bf16(acc[mt][nt][0], acc[mt][nt][1], acc[mt][nt][2], acc[mt][nt][3],
                         lb.x, lb.y, lb.z, lb.w, bu4[nt].x, bu4[nt].y);
            }
        }
        __syncthreads();
        if (kt + 3 < nk) PB(s, kt + 3);
        CP_COMMIT();
    }
#undef PB

#pragma unroll
    for (int mt = 0; mt < 4; mt++) {
        int rr0 = row0 + wm * 64 + mt * 16 + r;
#pragma unroll
        for (int nt = 0; nt < 4; nt++) {
            int cb = col0 + wn * 32 + nt * 8 + 2 * c;
#pragma unroll
            for (int half = 0; half < 2; half++) {
                int rr = rr0 + half * 8;
                float v0 = acc[mt][nt][half * 2 + 0];
                float v1 = acc[mt][nt][half * 2 + 1];
                if (bias) { if (cb < N) v0 += bias[cb]; if (cb + 1 < N) v1 += bias[cb + 1]; }
                size_t base = (size_t)rr * N + cb;
                if (cb < N)     C[base]     = v0;
                if (cb + 1 < N) C[base + 1] = v1;
            }
        }
    }
}

// ---- fp16 1x GEMM: A fp16 pairs (bfidx), B fp16 quads, 3-stage --------------
#define S1H   2048                      // u32/stage: A 1024 | B 1024
#define GS1H  (3*S1H*4)                 // 24576
__global__ void __launch_bounds__(256, 2)
gemm1h(const unsigned* __restrict__ AH, const uint4* __restrict__ Bq,
       const float* __restrict__ bias, const float* __restrict__ res,
       float* __restrict__ C, unsigned* __restrict__ Ch,
       float* __restrict__ C2, const float* __restrict__ res2,
       int M, int N, int K, int act) {
    extern __shared__ unsigned smu[];
    int tid = threadIdx.x, warp = tid >> 5, lane = tid & 31;
    int wm = warp & 1, wn = warp >> 1;
    int row0 = blockIdx.y * 128, col0 = blockIdx.x * 128;
    int r = lane >> 2, c = lane & 3;
    int nk = K >> 4, K16 = K >> 4;

    float acc[4][4][4];
#pragma unroll
    for (int i = 0; i < 4; i++)
#pragma unroll
        for (int j = 0; j < 4; j++)
#pragma unroll
            for (int q = 0; q < 4; q++) acc[i][j][q] = 0.f;

#define PH(SIDX, KT) do { \
        unsigned* sa = smu + (SIDX) * S1H; \
        { \
            int b_ = tid >> 5, ln_ = tid & 31; \
            size_t g_ = ((size_t)((row0 >> 4) + b_) * K16 + (KT)) * 128 + ln_ * 4; \
            cp16(sa + b_ * 128 + ln_ * 4, AH + g_, true); \
        } \
        { \
            int n_ = tid >> 1, j_ = tid & 1; \
            int ng = col0 + n_; \
            size_t g_ = ((size_t)(KT) * N + ng) * 2 + j_; \
            cp16(sa + 1024 + tid * 4, Bq + g_, ng < N); \
        } \
    } while (0)

    PH(0, 0); CP_COMMIT();
    if (nk > 1) PH(1, 1);
    CP_COMMIT();
    if (nk > 2) PH(2, 2);
    CP_COMMIT();

    for (int kt = 0; kt < nk; kt++) {
        CP_WAIT2();
        __syncthreads();
        int s = kt % 3;
        unsigned* sa = smu + s * S1H;

        uint2 b2[4];
#pragma unroll
        for (int nt = 0; nt < 4; nt++) {
            int nl = wn * 32 + nt * 8 + r;
            b2[nt] = *(const uint2*)(sa + 1024 + nl * 8 + c * 2);
        }
#pragma unroll
        for (int mt = 0; mt < 4; mt++) {
            uint4 a = *(const uint4*)(sa + (wm * 4 + mt) * 128 + lane * 4);
#pragma unroll
            for (int nt = 0; nt < 4; nt++)
                mma_f16(acc[mt][nt][0], acc[mt][nt][1], acc[mt][nt][2], acc[mt][nt][3],
                        a.x, a.y, a.z, a.w, b2[nt].x, b2[nt].y);
        }
        __syncthreads();
        if (kt + 3 < nk) PH(s, kt + 3);
        CP_COMMIT();
    }
#undef PH

    unsigned short* ch = (unsigned short*)Ch;
#pragma unroll
    for (int mt = 0; mt < 4; mt++) {
        int rr0 = row0 + wm * 64 + mt * 16 + r;
#pragma unroll
        for (int nt = 0; nt < 4; nt++) {
            int cb = col0 + wn * 32 + nt * 8 + 2 * c;
#pragma unroll
            for (int half = 0; half < 2; half++) {
                int rr = rr0 + half * 8;
                float v0 = acc[mt][nt][half * 2 + 0];
                float v1 = acc[mt][nt][half * 2 + 1];
                if (bias) { if (cb < N) v0 += bias[cb]; if (cb + 1 < N) v1 += bias[cb + 1]; }
                if (act == 1) {
                    v0 = 0.5f * v0 * (1.f + erff(v0 * 0.70710678118654752f));
                    v1 = 0.5f * v1 * (1.f + erff(v1 * 0.70710678118654752f));
                }
                size_t base = (size_t)rr * N + cb;
                if (Ch) {
                    if (cb < N)     ch[bfidx(rr, cb, N)]     = f2hu(v0);
                    if (cb + 1 < N) ch[bfidx(rr, cb + 1, N)] = f2hu(v1);
                } else {
                    float w0 = v0, w1 = v1;
                    if (res) { if (cb < N) w0 += res[base]; if (cb + 1 < N) w1 += res[base + 1]; }
                    if (cb < N)     C[base]     = w0;
                    if (cb + 1 < N) C[base + 1] = w1;
                }
                if (C2) {
                    float u0 = v0, u1 = v1;
                    if (res2) { if (cb < N) u0 += res2[base]; if (cb + 1 < N) u1 += res2[base + 1]; }
                    if (cb < N)     C2[base]     = u0;
                    if (cb + 1 < N) C2[base + 1] = u1;
                }
            }
        }
    }
}

// ---------------- fused main MHA: fp16 pairs + raw row-major -----------------
#define ATTN_SMEM ((3*64*99 + 64*64) * 4)
__global__ void attn_kernel(const float* __restrict__ qkv, unsigned* __restrict__ ohw,
                            float* __restrict__ oraw) {
    extern __shared__ float smf[];
    float* Qs = smf;
    float* Ks = Qs + 64 * 99;
    float* Vs = Ks + 64 * 99;
    float* Ss = Vs + 64 * 99;
    unsigned short* oh = (unsigned short*)ohw;
    int b = blockIdx.x >> 3;
    int h = blockIdx.x & 7;
    const float* base = qkv + (size_t)b * 64 * (3 * CDIM) + h * HD;

    for (int e = threadIdx.x; e < 64 * HD; e += blockDim.x) {
        int r = e / HD, d = e % HD;
        const float* rp = base + (size_t)r * (3 * CDIM) + d;
        Qs[r * 99 + d] = rp[0];
        Ks[r * 99 + d] = rp[CDIM];
        Vs[r * 99 + d] = rp[2 * CDIM];
    }
    __syncthreads();

    const float scale = 1.0f / sqrtf(98.0f);
    for (int e = threadIdx.x; e < 4096; e += blockDim.x) {
        int i = e >> 6, j = e & 63;
        const float* qi = Qs + i * 99;
        const float* kj = Ks + j * 99;
        float a = 0.f;
#pragma unroll
        for (int d = 0; d < HD; d++) a = fmaf(qi[d], kj[d], a);
        Ss[e] = a * scale;
    }
    __syncthreads();

    int warp = threadIdx.x >> 5, lane = threadIdx.x & 31;
    for (int i = warp; i < 64; i += 8) {
        float v0 = Ss[i * 64 + lane], v1 = Ss[i * 64 + lane + 32];
        float mx = fmaxf(v0, v1);
        for (int o = 16; o; o >>= 1) mx = fmaxf(mx, __shfl_xor_sync(0xffffffffu, mx, o));
        float e0 = __expf(v0 - mx), e1 = __expf(v1 - mx);
        float s = e0 + e1;
        for (int o = 16; o; o >>= 1) s += __shfl_xor_sync(0xffffffffu, s, o);
        float inv = 1.f / s;
        Ss[i * 64 + lane]      = e0 * inv;
        Ss[i * 64 + lane + 32] = e1 * inv;
    }
    __syncthreads();

    for (int e = threadIdx.x; e < 64 * HD; e += blockDim.x) {
        int i = e / HD, d = e % HD;
        const float* p = Ss + i * 64;
        float a = 0.f;
#pragma unroll
        for (int j = 0; j < 64; j++) a = fmaf(p[j], Vs[j * 99 + d], a);
        int row = b * 64 + i, k = h * HD + d;
        oraw[(size_t)row * CDIM + k] = a;
        oh[bfidx(row, k, CDIM)] = f2hu(a);
    }
}

// ---------------- transpose to fp16 pairs ------------------------------------
__global__ void transpose_h_kernel(const float* __restrict__ in, unsigned* __restrict__ ow) {
    __shared__ float tile[32][33];
    unsigned short* oh = (unsigned short*)ow;
    int b = blockIdx.z;
    int r0 = blockIdx.y * 32, c0 = blockIdx.x * 32;
    const float* ib = in + (size_t)b * 64 * 784;
    int r = r0 + threadIdx.y, c = c0 + threadIdx.x;
    if (r < 64 && c < 784) tile[threadIdx.y][threadIdx.x] = ib[(size_t)r * 784 + c];
    __syncthreads();
    int rr = r0 + threadIdx.x, cc = c0 + threadIdx.y;
    if (rr < 64 && cc < 784)
        oh[bfidx(b * 784 + cc, rr, 64)] = f2hu(tile[threadIdx.x][threadIdx.y]);
}

// ---------------- plain transpose --------------------------------------------
__global__ void transpose_kernel(const float* __restrict__ in, float* __restrict__ out,
                                 int R, int Cc) {
    __shared__ float tile[32][33];
    int b = blockIdx.z;
    int r0 = blockIdx.y * 32, c0 = blockIdx.x * 32;
    const float* ib = in + (size_t)b * R * Cc;
    float* ob = out + (size_t)b * R * Cc;
    int r = r0 + threadIdx.y, c = c0 + threadIdx.x;
    if (r < R && c < Cc) tile[threadIdx.y][threadIdx.x] = ib[(size_t)r * Cc + c];
    __syncthreads();
    int rr = r0 + threadIdx.x, cc = c0 + threadIdx.y;
    if (rr < R && cc < Cc) ob[(size_t)cc * R + rr] = tile[threadIdx.x][threadIdx.y];
}

// ---------------- top-4 per (b, r) --------------------------------------------
__global__ void bf_topk_kernel(const float* __restrict__ ar, int* __restrict__ idx) {
    int t = blockIdx.x * blockDim.x + threadIdx.x;
    if (t >= NB * 49) return;
    float v[49];
    const float* row = ar + (size_t)t * 49;
#pragma unroll
    for (int s = 0; s < 49; s++) v[s] = row[s];
    for (int k = 0; k < 4; k++) {
        float best = -3.4e38f; int bi = 0;
        for (int s = 0; s < 49; s++)
            if (v[s] > best) { best = v[s]; bi = s; }
        idx[t * 4 + k] = bi;
        v[bi] = -3.4e38f;
    }
}

// ---------------- BiFormer region attention ------------------------------------
__global__ void bf_attn_kernel(const float* __restrict__ qkvt, const int* __restrict__ idx,
                               float* __restrict__ ao) {
    __shared__ float Qs[16][8], Ks[64][9], Vs[64][9], S[16][64];
    __shared__ int sreg[4];
    int r = blockIdx.x % 49;
    int m = (blockIdx.x / 49) & 7;
    int b = blockIdx.x / (49 * 8);
    int tid = threadIdx.x;
    int rh = r / 7, rw = r % 7;

    if (tid < 4) sreg[tid] = idx[((size_t)b * 49 + r) * 4 + tid];
    {
        int p = tid >> 3, d = tid & 7;
        int hw = (rh * 4 + (p >> 2)) * 28 + rw * 4 + (p & 3);
        Qs[p][d] = qkvt[((size_t)b * 784 + hw) * 192 + m * 8 + d];
    }
    __syncthreads();

    for (int e = tid; e < 512; e += 128) {
        int slot = e >> 3, d = e & 7;
        int t = slot >> 4, s = slot & 15;
        int sr = sreg[t];
        int hw = ((sr / 7) * 4 + (s >> 2)) * 28 + (sr % 7) * 4 + (s & 3);
        const float* p = qkvt + ((size_t)b * 784 + hw) * 192 + m * 8 + d;
        Ks[slot][d] = p[64];
        Vs[slot][d] = p[128];
    }
    __syncthreads();

    for (int e = tid; e < 1024; e += 128) {
        int i = e >> 6, j = e & 63;
        float a = 0.f;
#pragma unroll
        for (int d = 0; d < 8; d++) a = fmaf(Qs[i][d], Ks[j][d], a);
        S[i][j] = a * 0.125f;
    }
    __syncthreads();

    int warp = tid >> 5, lane = tid & 31;
    for (int i = warp; i < 16; i += 4) {
        float v0 = S[i][lane], v1 = S[i][lane + 32];
        float mx = fmaxf(v0, v1);
        for (int o = 16; o; o >>= 1) mx = fmaxf(mx, __shfl_xor_sync(0xffffffffu, mx, o));
        float e0 = __expf(v0 - mx), e1 = __expf(v1 - mx);
        float s = e0 + e1;
        for (int o = 16; o; o >>= 1) s += __shfl_xor_sync(0xffffffffu, s, o);
        float inv = 1.f / s;
        S[i][lane] = e0 * inv;
        S[i][lane + 32] = e1 * inv;
    }
    __syncthreads();

    {
        int i = tid >> 3, d = tid & 7;
        float a = 0.f;
#pragma unroll
        for (int j = 0; j < 64; j++) a = fmaf(S[i][j], Vs[j][d], a);
        int hw = (rh * 4 + (i >> 2)) * 28 + rw * 4 + (i & 3);
        ao[((size_t)b * 784 + hw) * 64 + m * 8 + d] = a;
    }
}

// ---------------- LePE: dw conv add, fp16 pair output ------------------------
__global__ void bf_lepe_h_kernel(const float* __restrict__ qkvt,
                                 const float* __restrict__ w,
                                 const float* __restrict__ bias,
                                 const float* __restrict__ ao, unsigned* __restrict__ ow) {
    int e = blockIdx.x * blockDim.x + threadIdx.x;
    if (e >= NB * 784 * 64) return;
    unsigned short* oh = (unsigned short*)ow;
    int c  = e & 63;
    int hw = (e >> 6) % 784;
    int b  = e / (784 * 64);
    int h = hw / 28, wq = hw % 28;
    float acc = bias[c];
#pragma unroll
    for (int i = 0; i < 3; i++) {
        int hh = h + i - 1;
        if (hh < 0 || hh >= 28) continue;
#pragma unroll
        for (int j = 0; j < 3; j++) {
            int ww = wq + j - 1;
            if (ww < 0 || ww >= 28) continue;
            acc = fmaf(qkvt[((size_t)b * 784 + hh * 28 + ww) * 192 + 128 + c],
                       w[c * 9 + i * 3 + j], acc);
        }
    }
    oh[bfidx(b * 784 + hw, c, 64)] = f2hu(ao[e] + acc);
}

// ============================================================================
extern "C" void kernel_launch(void* const* d_in, const int* in_sizes, int n_in,
                              void* d_out, int out_size) {
    const float* x        = (const float*)d_in[0];
    const float* n1g      = (const float*)d_in[1];
    const float* n1b      = (const float*)d_in[2];
    const float* qkv_w    = (const float*)d_in[3];
    const float* proj_w   = (const float*)d_in[4];
    const float* proj_b   = (const float*)d_in[5];
    const float* n2g      = (const float*)d_in[6];
    const float* n2b      = (const float*)d_in[7];
    const float* fc1_w    = (const float*)d_in[8];
    const float* fc1_b    = (const float*)d_in[9];
    const float* fc2_w    = (const float*)d_in[10];
    const float* fc2_b    = (const float*)d_in[11];
    const float* bfqkv_w  = (const float*)d_in[12];
    const float* bfqkv_b  = (const float*)d_in[13];
    const float* bflepe_w = (const float*)d_in[14];
    const float* bflepe_b = (const float*)d_in[15];
    const float* bfout_w  = (const float*)d_in[16];
    const float* bfout_b  = (const float*)d_in[17];
    float* out = (float*)d_out;

    float *p_qkv, *p_aoraw, *p_o, *p_xr, *p_bfqkv, *p_bfao, *p_bf2;
    unsigned *p_hhb, *p_hlb, *p_aohh, *p_h2h, *p_midh, *p_xTh, *p_bfaohh;
    uint4 *p_qwpu, *p_pwph, *p_bfqh, *p_bfoh, *p_fc1h, *p_fc2h;
    float *p_pwpool, *p_pbpool, *p_pool, *p_ar;
    int* p_idx;
    cudaGetSymbolAddress((void**)&p_hhb,    g_h_hb);
    cudaGetSymbolAddress((void**)&p_hlb,    g_h_lb);
    cudaGetSymbolAddress((void**)&p_qkv,    g_qkv);
    cudaGetSymbolAddress((void**)&p_aohh,   g_aohh);
    cudaGetSymbolAddress((void**)&p_aoraw,  g_ao_raw);
    cudaGetSymbolAddress((void**)&p_o,      g_o);
    cudaGetSymbolAddress((void**)&p_xr,     g_xr);
    cudaGetSymbolAddress((void**)&p_h2h,    g_h2h);
    cudaGetSymbolAddress((void**)&p_midh,   g_midh);
    cudaGetSymbolAddress((void**)&p_xTh,    g_xTh);
    cudaGetSymbolAddress((void**)&p_bfqkv,  g_bfqkv);
    cudaGetSymbolAddress((void**)&p_bfao,   g_bfao);
    cudaGetSymbolAddress((void**)&p_bfaohh, g_bfaohh);
    cudaGetSymbolAddress((void**)&p_bf2,    g_bf2);
    cudaGetSymbolAddress((void**)&p_qwpu,   g_qwpu);
    cudaGetSymbolAddress((void**)&p_pwph,   g_pwph);
    cudaGetSymbolAddress((void**)&p_bfqh,   g_bfqh);
    cudaGetSymbolAddress((void**)&p_bfoh,   g_bfoh);
    cudaGetSymbolAddress((void**)&p_fc1h,   g_fc1h);
    cudaGetSymbolAddress((void**)&p_fc2h,   g_fc2h);
    cudaGetSymbolAddress((void**)&p_pwpool, g_pwpool);
    cudaGetSymbolAddress((void**)&p_pbpool, g_pbpool);
    cudaGetSymbolAddress((void**)&p_pool,   g_pool);
    cudaGetSymbolAddress((void**)&p_ar,     g_ar);
    cudaGetSymbolAddress((void**)&p_idx,    g_topk);

    cudaFuncSetAttribute(attn_kernel, cudaFuncAttributeMaxDynamicSharedMemorySize, ATTN_SMEM);
    cudaFuncSetAttribute(gemm3b, cudaFuncAttributeMaxDynamicSharedMemorySize, GS3B);
    cudaFuncSetAttribute(gemm1h, cudaFuncAttributeMaxDynamicSharedMemorySize, GS1H);

    static cudaStream_t s2 = nullptr;
    static cudaEvent_t evA = nullptr, evB = nullptr, evC = nullptr, evD = nullptr, evE = nullptr;
    if (s2 == nullptr) {
        cudaStreamCreateWithFlags(&s2, cudaStreamNonBlocking);
        cudaEventCreateWithFlags(&evA, cudaEventDisableTiming);
        cudaEventCreateWithFlags(&evB, cudaEventDisableTiming);
        cudaEventCreateWithFlags(&evC, cudaEventDisableTiming);
        cudaEventCreateWithFlags(&evD, cudaEventDisableTiming);
        cudaEventCreateWithFlags(&evE, cudaEventDisableTiming);
    }

    // ---- fork #1: weight packs + routing-weight pool on s2 ----
    cudaEventRecord(evA, 0);
    cudaStreamWaitEvent(s2, evA, 0);

    bpack3<<<(49 * 2352 * 4 + 255) / 256, 256>>>(qkv_w, p_qwpu, CDIM, 3 * CDIM);
    ln_split_kernel<<<NROW, 256>>>(x, n1g, n1b, p_hhb, p_hlb);

    pwp_pack<<<(784 * 49 + 49 + 255) / 256, 256, 0, s2>>>(proj_w, proj_b, p_pwpool, p_pbpool);
    bpack1h <<<(49 * 784 * 2 + 255) / 256, 256, 0, s2>>>(proj_w, p_pwph, CDIM, CDIM);
    bpack1th<<<(4 * 192 * 2 + 255) / 256, 256, 0, s2>>>(bfqkv_w, p_bfqh, 64, 192);
    bpack1th<<<(4 * 64 * 2 + 255) / 256, 256, 0, s2>>>(bfout_w, p_bfoh, 64, 64);
    bpack1h <<<(49 * 3136 * 2 + 255) / 256, 256, 0, s2>>>(fc1_w, p_fc1h, CDIM, HID);
    bpack1h <<<(196 * 784 * 2 + 255) / 256, 256, 0, s2>>>(fc2_w, p_fc2h, HID, CDIM);
    cudaEventRecord(evB, s2);

    gemm3b<<<dim3(19, 64), 256, GS3B>>>(p_hhb, p_hlb, p_qwpu, nullptr, p_qkv,
                                        NROW, 3 * CDIM, CDIM);
    attn_kernel<<<NB * NHD, 256, ATTN_SMEM>>>(p_qkv, p_aohh, p_aoraw);
    cudaEventRecord(evE, 0);

    // routing sidecar on s2 (exact fp32)
    cudaStreamWaitEvent(s2, evE, 0);
    route_pool<<<NROW, 256, 0, s2>>>(p_aoraw, p_pwpool, p_pbpool, p_pool);
    route_score<<<NB, 256, 0, s2>>>(p_pool, bfqkv_w, bfqkv_b, p_ar);
    bf_topk_kernel<<<(NB * 49 + 255) / 256, 256, 0, s2>>>(p_ar, p_idx);

    // proj (fp16) on main; dual output o + xr = o + x
    cudaStreamWaitEvent(0, evB, 0);
    gemm1h<<<dim3(7, 64), 256, GS1H>>>(p_aohh, p_pwph, proj_b, nullptr,
                                       p_o, nullptr, p_xr, x, NROW, CDIM, CDIM, 0);

    // ---- fork #2: BiFormer values on s2, MLP on main ----
    cudaEventRecord(evC, 0);
    cudaStreamWaitEvent(s2, evC, 0);

    transpose_h_kernel<<<dim3(25, 2, NB), dim3(32, 32), 0, s2>>>(p_o, p_xTh);
    gemm1h<<<dim3(2, M2 / 128), 256, GS1H, s2>>>(p_xTh, p_bfqh, bfqkv_b, nullptr,
                                                 p_bfqkv, nullptr, nullptr, nullptr,
                                                 M2, 192, 64, 0);
    bf_attn_kernel<<<NB * 8 * 49, 128, 0, s2>>>(p_bfqkv, p_idx, p_bfao);
    bf_lepe_h_kernel<<<(NB * 784 * 64 + 255) / 256, 256, 0, s2>>>(p_bfqkv, bflepe_w,
                                                                  bflepe_b, p_bfao, p_bfaohh);
    gemm1h<<<dim3(1, M2 / 128), 256, GS1H, s2>>>(p_bfaohh, p_bfoh, bfout_b, nullptr,
                                                 p_bf2, nullptr, nullptr, nullptr,
                                                 M2, 64, 64, 0);
    transpose_kernel<<<dim3(2, 25, NB), dim3(32, 32), 0, s2>>>(p_bf2, out + OUT1, 784, 64);
    cudaEventRecord(evD, s2);

    ln_h_kernel<<<NROW, 256>>>(p_xr, n2g, n2b, p_h2h);
    gemm1h<<<dim3(25, 64), 256, GS1H>>>(p_h2h, p_fc1h, fc1_b, nullptr,
                                        nullptr, p_midh, nullptr, nullptr,
                                        NROW, HID, CDIM, 1);
    gemm1h<<<dim3(7, 64), 256, GS1H>>>(p_midh, p_fc2h, fc2_b, p_xr,
                                       out, nullptr, nullptr, nullptr,
                                       NROW, CDIM, HID, 0);

    cudaStreamWaitEvent(0, evD, 0);
}